// round 1
// baseline (speedup 1.0000x reference)
#include <cuda_runtime.h>
#include <math.h>

#define B_ 4
#define C_ 256
#define N_ 4096
#define D_ 32

// Scratch (static __device__ — no allocation at runtime, per harness rules)
__device__ float g_q [B_*D_*N_];   // [b][d][n]
__device__ float g_k [B_*D_*N_];   // [b][d][n]
__device__ float g_v [B_*N_*C_];   // [b][n][c]  (token-major for coalesced PV reads)
__device__ float g_ao[B_*N_*C_];   // [b][n][c]  attention output

// ---------------------------------------------------------------------------
// Projection GEMM: out[o][n] = sum_c W[o][c] * X[b][c][n] + bias[o]
//   !TRANS: store [B][O][N]   (used for q, k)
//    TRANS: store [B][N][C]   (used for v; transposed via smem for coalescing)
// Tile: 32 o x 128 n, K-tiles of 64. 256 threads, micro-tile 2x8.
// ---------------------------------------------------------------------------
template<bool TRANS>
__global__ __launch_bounds__(256)
void proj_kernel(const float* __restrict__ X,
                 const float* __restrict__ W,
                 const float* __restrict__ bias,
                 float* __restrict__ out,
                 int O)
{
    __shared__ float W_s[32][68];
    __shared__ float X_s[64][132];
    const int b  = blockIdx.z;
    const int o0 = blockIdx.y * 32;
    const int n0 = blockIdx.x * 128;
    const int t  = threadIdx.x;
    const int to = t >> 4, tn = t & 15;
    const float* Xb = X + b * (C_ * N_);

    float acc[2][8];
#pragma unroll
    for (int i = 0; i < 2; i++)
#pragma unroll
        for (int j = 0; j < 8; j++) acc[i][j] = 0.f;

    for (int kt = 0; kt < C_; kt += 64) {
        __syncthreads();
#pragma unroll
        for (int it = 0; it < 2; it++) {           // 512 float4 = 32x64 W tile
            int idx4 = t + it * 256;
            int o = idx4 >> 4, c4 = idx4 & 15;
            *(float4*)&W_s[o][c4 * 4] =
                *(const float4*)&W[(o0 + o) * C_ + kt + c4 * 4];
        }
#pragma unroll
        for (int it = 0; it < 8; it++) {           // 2048 float4 = 64x128 X tile
            int idx4 = t + it * 256;
            int kc = idx4 >> 5, n4 = idx4 & 31;
            *(float4*)&X_s[kc][n4 * 4] =
                *(const float4*)&Xb[(kt + kc) * N_ + n0 + n4 * 4];
        }
        __syncthreads();
#pragma unroll 4
        for (int kc = 0; kc < 64; kc++) {
            float xr[8];
            *(float4*)&xr[0] = *(const float4*)&X_s[kc][tn * 8];
            *(float4*)&xr[4] = *(const float4*)&X_s[kc][tn * 8 + 4];
            float w0 = W_s[to * 2 + 0][kc];
            float w1 = W_s[to * 2 + 1][kc];
#pragma unroll
            for (int j = 0; j < 8; j++) {
                acc[0][j] += w0 * xr[j];
                acc[1][j] += w1 * xr[j];
            }
        }
    }

    if (!TRANS) {
#pragma unroll
        for (int i = 0; i < 2; i++) {
            int o = o0 + to * 2 + i;
            float bv = bias[o];
            float* p = out + (b * O + o) * N_ + n0 + tn * 8;
            *(float4*)&p[0] = make_float4(acc[i][0]+bv, acc[i][1]+bv, acc[i][2]+bv, acc[i][3]+bv);
            *(float4*)&p[4] = make_float4(acc[i][4]+bv, acc[i][5]+bv, acc[i][6]+bv, acc[i][7]+bv);
        }
    } else {
        // stage result tile in smem, emit transposed [n][c] with coalesced float4 stores
        __syncthreads();
#pragma unroll
        for (int i = 0; i < 2; i++) {
            float bv = bias[o0 + to * 2 + i];
#pragma unroll
            for (int j = 0; j < 8; j++)
                X_s[to * 2 + i][tn * 8 + j] = acc[i][j] + bv;
        }
        __syncthreads();
#pragma unroll
        for (int it = 0; it < 4; it++) {           // 1024 float4 stores
            int idx = t + it * 256;
            int nl = idx >> 3, o4 = idx & 7;
            float4 r;
            r.x = X_s[o4 * 4 + 0][nl];
            r.y = X_s[o4 * 4 + 1][nl];
            r.z = X_s[o4 * 4 + 2][nl];
            r.w = X_s[o4 * 4 + 3][nl];
            *(float4*)&out[(b * N_ + n0 + nl) * C_ + o0 + o4 * 4] = r;
        }
    }
}

// ---------------------------------------------------------------------------
// Flash attention (fp32, online softmax), no softmax scale (matches reference).
//   Q,K: [B][D][N]; V,AO: [B][N][C]. Block = 64 queries, full sweep over 4096 keys
//   in tiles of 64. 256 threads. Accumulator: 8 rows x 8 cols per thread.
// ---------------------------------------------------------------------------
__global__ __launch_bounds__(256, 2)
void attn_kernel(const float* __restrict__ q,
                 const float* __restrict__ k,
                 const float* __restrict__ v,
                 float* __restrict__ ao)
{
    __shared__ float q_s[D_][68];
    __shared__ float k_s[D_][68];
    __shared__ float s_s[64][68];
    __shared__ float m_sm[64], l_sm[64], c_sm[64];

    const int b  = blockIdx.y;
    const int m0 = blockIdx.x * 64;
    const int t  = threadIdx.x;
    const float* qb = q + b * (D_ * N_);
    const float* kb = k + b * (D_ * N_);
    const float* vb = v + (size_t)b * (N_ * C_);

    // Load Q tile [32 d][64 m] directly (coalesced along n; no transpose needed)
#pragma unroll
    for (int it = 0; it < 2; it++) {
        int idx4 = t + it * 256;
        int dd = idx4 >> 4, m4 = idx4 & 15;
        *(float4*)&q_s[dd][m4 * 4] = *(const float4*)&qb[dd * N_ + m0 + m4 * 4];
    }
    if (t < 64) { m_sm[t] = -INFINITY; l_sm[t] = 0.f; }

    float acc[8][8];
#pragma unroll
    for (int i = 0; i < 8; i++)
#pragma unroll
        for (int j = 0; j < 8; j++) acc[i][j] = 0.f;

    const int tq   = t >> 4, tn16 = t & 15;   // S-phase map: 4x4 of 64x64
    const int row4 = t >> 2, seg  = t & 3;    // softmax map: 4 threads / row
    const int tr   = t >> 5, tc   = t & 31;   // PV map: 8 rows x 8 cols

    for (int nt = 0; nt < N_ / 64; nt++) {
        const int n0 = nt * 64;
        __syncthreads();                      // prev-iter PV done before reuse
        // Load K tile [32 d][64 n]
#pragma unroll
        for (int it = 0; it < 2; it++) {
            int idx4 = t + it * 256;
            int dd = idx4 >> 4, m4 = idx4 & 15;
            *(float4*)&k_s[dd][m4 * 4] = *(const float4*)&kb[dd * N_ + n0 + m4 * 4];
        }
        __syncthreads();

        // ---- S = Q K^T (64x64 tile) ----
        float sa[4][4];
#pragma unroll
        for (int i = 0; i < 4; i++)
#pragma unroll
            for (int j = 0; j < 4; j++) sa[i][j] = 0.f;
#pragma unroll 8
        for (int kk = 0; kk < D_; kk++) {
            float qr[4], kr[4];
            *(float4*)qr = *(const float4*)&q_s[kk][tq * 4];
            *(float4*)kr = *(const float4*)&k_s[kk][tn16 * 4];
#pragma unroll
            for (int i = 0; i < 4; i++)
#pragma unroll
                for (int j = 0; j < 4; j++) sa[i][j] += qr[i] * kr[j];
        }
#pragma unroll
        for (int i = 0; i < 4; i++)
            *(float4*)&s_s[tq * 4 + i][tn16 * 4] =
                make_float4(sa[i][0], sa[i][1], sa[i][2], sa[i][3]);
        __syncthreads();

        // ---- row max (strided scan -> conflict-free) ----
        float mx = -INFINITY;
#pragma unroll
        for (int u = 0; u < 16; u++) mx = fmaxf(mx, s_s[row4][u * 4 + seg]);
        mx = fmaxf(mx, __shfl_xor_sync(0xffffffffu, mx, 1));
        mx = fmaxf(mx, __shfl_xor_sync(0xffffffffu, mx, 2));
        if (seg == 0) {
            float mo = m_sm[row4];
            float mn = fmaxf(mo, mx);
            m_sm[row4] = mn;
            c_sm[row4] = __expf(mo - mn);   // first tile: exp(-inf)=0
        }
        __syncthreads();

        // ---- exp + row sum ----
        float mn = m_sm[row4];
        float sm = 0.f;
#pragma unroll
        for (int u = 0; u < 16; u++) {
            float p = __expf(s_s[row4][u * 4 + seg] - mn);
            s_s[row4][u * 4 + seg] = p;
            sm += p;
        }
        sm += __shfl_xor_sync(0xffffffffu, sm, 1);
        sm += __shfl_xor_sync(0xffffffffu, sm, 2);
        if (seg == 0) l_sm[row4] = l_sm[row4] * c_sm[row4] + sm;
        __syncthreads();

        // ---- rescale accumulator ----
#pragma unroll
        for (int i = 0; i < 8; i++) {
            float cf = c_sm[tr * 8 + i];
#pragma unroll
            for (int j = 0; j < 8; j++) acc[i][j] *= cf;
        }

        // ---- O += P V : V read coalesced from [n][c], L1-resident tile ----
        const float* vt = vb + (size_t)n0 * C_ + tc * 8;
#pragma unroll 4
        for (int n = 0; n < 64; n++) {
            float vr[8];
            *(float4*)&vr[0] = *(const float4*)&vt[n * C_];
            *(float4*)&vr[4] = *(const float4*)&vt[n * C_ + 4];
#pragma unroll
            for (int i = 0; i < 8; i++) {
                float p = s_s[tr * 8 + i][n];   // broadcast within warp
#pragma unroll
                for (int j = 0; j < 8; j++) acc[i][j] += p * vr[j];
            }
        }
    }

    // ---- normalize + store AO [m][c] (coalesced) ----
#pragma unroll
    for (int i = 0; i < 8; i++) {
        float inv = 1.f / l_sm[tr * 8 + i];
        float* p = ao + (size_t)(b * N_ + m0 + tr * 8 + i) * C_ + tc * 8;
        *(float4*)&p[0] = make_float4(acc[i][0]*inv, acc[i][1]*inv, acc[i][2]*inv, acc[i][3]*inv);
        *(float4*)&p[4] = make_float4(acc[i][4]*inv, acc[i][5]*inv, acc[i][6]*inv, acc[i][7]*inv);
    }
}

// ---------------------------------------------------------------------------
// Output projection + bias + residual:
//   out[b][o][m] = sum_c wo[o][c] * AO[b][m][c] + bo[o] + x[b][o][m]
// Same tiling as proj_kernel; AO tile transposed into smem on load.
// ---------------------------------------------------------------------------
__global__ __launch_bounds__(256)
void oproj_kernel(const float* __restrict__ AO,
                  const float* __restrict__ W,
                  const float* __restrict__ bias,
                  const float* __restrict__ x,
                  float* __restrict__ out)
{
    __shared__ float W_s[32][68];
    __shared__ float A_s[64][132];
    const int b  = blockIdx.z;
    const int o0 = blockIdx.y * 32;
    const int m0 = blockIdx.x * 128;
    const int t  = threadIdx.x;
    const int to = t >> 4, tn = t & 15;

    float acc[2][8];
#pragma unroll
    for (int i = 0; i < 2; i++)
#pragma unroll
        for (int j = 0; j < 8; j++) acc[i][j] = 0.f;

    for (int kt = 0; kt < C_; kt += 64) {
        __syncthreads();
#pragma unroll
        for (int it = 0; it < 2; it++) {
            int idx4 = t + it * 256;
            int o = idx4 >> 4, c4 = idx4 & 15;
            *(float4*)&W_s[o][c4 * 4] =
                *(const float4*)&W[(o0 + o) * C_ + kt + c4 * 4];
        }
#pragma unroll
        for (int it = 0; it < 8; it++) {          // AO[m][c] -> A_s[c][m]
            int idx4 = t + it * 256;
            int m = idx4 >> 4, c4 = idx4 & 15;
            float4 a4 = *(const float4*)&AO[(size_t)(b * N_ + m0 + m) * C_ + kt + c4 * 4];
            A_s[c4 * 4 + 0][m] = a4.x;
            A_s[c4 * 4 + 1][m] = a4.y;
            A_s[c4 * 4 + 2][m] = a4.z;
            A_s[c4 * 4 + 3][m] = a4.w;
        }
        __syncthreads();
#pragma unroll 4
        for (int kc = 0; kc < 64; kc++) {
            float ar[8];
            *(float4*)&ar[0] = *(const float4*)&A_s[kc][tn * 8];
            *(float4*)&ar[4] = *(const float4*)&A_s[kc][tn * 8 + 4];
            float w0 = W_s[to * 2 + 0][kc];
            float w1 = W_s[to * 2 + 1][kc];
#pragma unroll
            for (int j = 0; j < 8; j++) {
                acc[0][j] += w0 * ar[j];
                acc[1][j] += w1 * ar[j];
            }
        }
    }

#pragma unroll
    for (int i = 0; i < 2; i++) {
        int o = o0 + to * 2 + i;
        float bv = bias[o];
        size_t base = (size_t)(b * C_ + o) * N_ + m0 + tn * 8;
        float4 x0 = *(const float4*)&x[base];
        float4 x1 = *(const float4*)&x[base + 4];
        *(float4*)&out[base] =
            make_float4(acc[i][0]+bv+x0.x, acc[i][1]+bv+x0.y, acc[i][2]+bv+x0.z, acc[i][3]+bv+x0.w);
        *(float4*)&out[base + 4] =
            make_float4(acc[i][4]+bv+x1.x, acc[i][5]+bv+x1.y, acc[i][6]+bv+x1.z, acc[i][7]+bv+x1.w);
    }
}

// ---------------------------------------------------------------------------
extern "C" void kernel_launch(void* const* d_in, const int* in_sizes, int n_in,
                              void* d_out, int out_size)
{
    const float* x  = (const float*)d_in[0];
    const float* wq = (const float*)d_in[1];
    const float* bq = (const float*)d_in[2];
    const float* wk = (const float*)d_in[3];
    const float* bk = (const float*)d_in[4];
    const float* wv = (const float*)d_in[5];
    const float* bv = (const float*)d_in[6];
    const float* wo = (const float*)d_in[7];
    const float* bo = (const float*)d_in[8];
    float* out = (float*)d_out;

    float *gq, *gk, *gv, *gao;
    cudaGetSymbolAddress((void**)&gq,  g_q);
    cudaGetSymbolAddress((void**)&gk,  g_k);
    cudaGetSymbolAddress((void**)&gv,  g_v);
    cudaGetSymbolAddress((void**)&gao, g_ao);

    dim3 blk(256);
    proj_kernel<false><<<dim3(N_ / 128, 1,       B_), blk>>>(x, wq, bq, gq, D_);
    proj_kernel<false><<<dim3(N_ / 128, 1,       B_), blk>>>(x, wk, bk, gk, D_);
    proj_kernel<true ><<<dim3(N_ / 128, C_ / 32, B_), blk>>>(x, wv, bv, gv, C_);
    attn_kernel       <<<dim3(N_ / 64,  B_),          blk>>>(gq, gk, gv, gao);
    oproj_kernel      <<<dim3(N_ / 128, C_ / 32, B_), blk>>>(gao, wo, bo, x, out);
}

// round 2
// speedup vs baseline: 1.0065x; 1.0065x over previous
#include <cuda_runtime.h>
#include <math.h>

#define B_ 4
#define C_ 256
#define N_ 4096
#define D_ 32

// Scratch (static __device__ — no allocation at runtime, per harness rules)
__device__ float g_q [B_*D_*N_];   // [b][d][n]
__device__ float g_k [B_*D_*N_];   // [b][d][n]
__device__ float g_v [B_*N_*C_];   // [b][n][c]  (token-major for coalesced PV reads)
__device__ float g_ao[B_*N_*C_];   // [b][n][c]  attention output

// ---------------------------------------------------------------------------
// Projection GEMM: out[o][n] = sum_c W[o][c] * X[b][c][n] + bias[o]
//   !TRANS: store [B][O][N]   (used for q, k)
//    TRANS: store [B][N][C]   (used for v; transposed via smem for coalescing)
// Tile: 32 o x 128 n, K-tiles of 64. 256 threads, micro-tile 2x8.
// ---------------------------------------------------------------------------
template<bool TRANS>
__global__ __launch_bounds__(256)
void proj_kernel(const float* __restrict__ X,
                 const float* __restrict__ W,
                 const float* __restrict__ bias,
                 float* __restrict__ out,
                 int O)
{
    __shared__ float W_s[32][68];
    __shared__ float X_s[64][132];
    const int b  = blockIdx.z;
    const int o0 = blockIdx.y * 32;
    const int n0 = blockIdx.x * 128;
    const int t  = threadIdx.x;
    const int to = t >> 4, tn = t & 15;
    const float* Xb = X + b * (C_ * N_);

    float acc[2][8];
#pragma unroll
    for (int i = 0; i < 2; i++)
#pragma unroll
        for (int j = 0; j < 8; j++) acc[i][j] = 0.f;

    for (int kt = 0; kt < C_; kt += 64) {
        __syncthreads();
#pragma unroll
        for (int it = 0; it < 2; it++) {           // 512 float4 = 32x64 W tile
            int idx4 = t + it * 256;
            int o = idx4 >> 4, c4 = idx4 & 15;
            *(float4*)&W_s[o][c4 * 4] =
                *(const float4*)&W[(o0 + o) * C_ + kt + c4 * 4];
        }
#pragma unroll
        for (int it = 0; it < 8; it++) {           // 2048 float4 = 64x128 X tile
            int idx4 = t + it * 256;
            int kc = idx4 >> 5, n4 = idx4 & 31;
            *(float4*)&X_s[kc][n4 * 4] =
                *(const float4*)&Xb[(kt + kc) * N_ + n0 + n4 * 4];
        }
        __syncthreads();
#pragma unroll 4
        for (int kc = 0; kc < 64; kc++) {
            float xr[8];
            *(float4*)&xr[0] = *(const float4*)&X_s[kc][tn * 8];
            *(float4*)&xr[4] = *(const float4*)&X_s[kc][tn * 8 + 4];
            float w0 = W_s[to * 2 + 0][kc];
            float w1 = W_s[to * 2 + 1][kc];
#pragma unroll
            for (int j = 0; j < 8; j++) {
                acc[0][j] += w0 * xr[j];
                acc[1][j] += w1 * xr[j];
            }
        }
    }

    if (!TRANS) {
#pragma unroll
        for (int i = 0; i < 2; i++) {
            int o = o0 + to * 2 + i;
            float bv = bias[o];
            float* p = out + (b * O + o) * N_ + n0 + tn * 8;
            *(float4*)&p[0] = make_float4(acc[i][0]+bv, acc[i][1]+bv, acc[i][2]+bv, acc[i][3]+bv);
            *(float4*)&p[4] = make_float4(acc[i][4]+bv, acc[i][5]+bv, acc[i][6]+bv, acc[i][7]+bv);
        }
    } else {
        // stage result tile in smem, emit transposed [n][c] with coalesced float4 stores
        __syncthreads();
#pragma unroll
        for (int i = 0; i < 2; i++) {
            float bv = bias[o0 + to * 2 + i];
#pragma unroll
            for (int j = 0; j < 8; j++)
                X_s[to * 2 + i][tn * 8 + j] = acc[i][j] + bv;
        }
        __syncthreads();
#pragma unroll
        for (int it = 0; it < 4; it++) {           // 1024 float4 stores
            int idx = t + it * 256;
            int nl = idx >> 3, o4 = idx & 7;
            float4 r;
            r.x = X_s[o4 * 4 + 0][nl];
            r.y = X_s[o4 * 4 + 1][nl];
            r.z = X_s[o4 * 4 + 2][nl];
            r.w = X_s[o4 * 4 + 3][nl];
            *(float4*)&out[(b * N_ + n0 + nl) * C_ + o0 + o4 * 4] = r;
        }
    }
}

// ---------------------------------------------------------------------------
// Flash attention (fp32, online softmax), no softmax scale (matches reference).
//   Q,K: [B][D][N]; V,AO: [B][N][C]. Block = 64 queries, full sweep over 4096 keys
//   in tiles of 64. 256 threads. Accumulator: 8 rows x 8 cols per thread.
// ---------------------------------------------------------------------------
__global__ __launch_bounds__(256, 2)
void attn_kernel(const float* __restrict__ q,
                 const float* __restrict__ k,
                 const float* __restrict__ v,
                 float* __restrict__ ao)
{
    __shared__ float q_s[D_][68];
    __shared__ float k_s[D_][68];
    __shared__ float s_s[64][68];
    __shared__ float m_sm[64], l_sm[64], c_sm[64];

    const int b  = blockIdx.y;
    const int m0 = blockIdx.x * 64;
    const int t  = threadIdx.x;
    const float* qb = q + b * (D_ * N_);
    const float* kb = k + b * (D_ * N_);
    const float* vb = v + (size_t)b * (N_ * C_);

    // Load Q tile [32 d][64 m] directly (coalesced along n; no transpose needed)
#pragma unroll
    for (int it = 0; it < 2; it++) {
        int idx4 = t + it * 256;
        int dd = idx4 >> 4, m4 = idx4 & 15;
        *(float4*)&q_s[dd][m4 * 4] = *(const float4*)&qb[dd * N_ + m0 + m4 * 4];
    }
    if (t < 64) { m_sm[t] = -INFINITY; l_sm[t] = 0.f; }

    float acc[8][8];
#pragma unroll
    for (int i = 0; i < 8; i++)
#pragma unroll
        for (int j = 0; j < 8; j++) acc[i][j] = 0.f;

    const int tq   = t >> 4, tn16 = t & 15;   // S-phase map: 4x4 of 64x64
    const int row4 = t >> 2, seg  = t & 3;    // softmax map: 4 threads / row
    const int tr   = t >> 5, tc   = t & 31;   // PV map: 8 rows x 8 cols

    for (int nt = 0; nt < N_ / 64; nt++) {
        const int n0 = nt * 64;
        __syncthreads();                      // prev-iter PV done before reuse
        // Load K tile [32 d][64 n]
#pragma unroll
        for (int it = 0; it < 2; it++) {
            int idx4 = t + it * 256;
            int dd = idx4 >> 4, m4 = idx4 & 15;
            *(float4*)&k_s[dd][m4 * 4] = *(const float4*)&kb[dd * N_ + n0 + m4 * 4];
        }
        __syncthreads();

        // ---- S = Q K^T (64x64 tile) ----
        float sa[4][4];
#pragma unroll
        for (int i = 0; i < 4; i++)
#pragma unroll
            for (int j = 0; j < 4; j++) sa[i][j] = 0.f;
#pragma unroll 8
        for (int kk = 0; kk < D_; kk++) {
            float qr[4], kr[4];
            *(float4*)qr = *(const float4*)&q_s[kk][tq * 4];
            *(float4*)kr = *(const float4*)&k_s[kk][tn16 * 4];
#pragma unroll
            for (int i = 0; i < 4; i++)
#pragma unroll
                for (int j = 0; j < 4; j++) sa[i][j] += qr[i] * kr[j];
        }
#pragma unroll
        for (int i = 0; i < 4; i++)
            *(float4*)&s_s[tq * 4 + i][tn16 * 4] =
                make_float4(sa[i][0], sa[i][1], sa[i][2], sa[i][3]);
        __syncthreads();

        // ---- row max (strided scan -> conflict-free) ----
        float mx = -INFINITY;
#pragma unroll
        for (int u = 0; u < 16; u++) mx = fmaxf(mx, s_s[row4][u * 4 + seg]);
        mx = fmaxf(mx, __shfl_xor_sync(0xffffffffu, mx, 1));
        mx = fmaxf(mx, __shfl_xor_sync(0xffffffffu, mx, 2));
        if (seg == 0) {
            float mo = m_sm[row4];
            float mn = fmaxf(mo, mx);
            m_sm[row4] = mn;
            c_sm[row4] = __expf(mo - mn);   // first tile: exp(-inf)=0
        }
        __syncthreads();

        // ---- exp + row sum ----
        float mn = m_sm[row4];
        float sm = 0.f;
#pragma unroll
        for (int u = 0; u < 16; u++) {
            float p = __expf(s_s[row4][u * 4 + seg] - mn);
            s_s[row4][u * 4 + seg] = p;
            sm += p;
        }
        sm += __shfl_xor_sync(0xffffffffu, sm, 1);
        sm += __shfl_xor_sync(0xffffffffu, sm, 2);
        if (seg == 0) l_sm[row4] = l_sm[row4] * c_sm[row4] + sm;
        __syncthreads();

        // ---- rescale accumulator ----
#pragma unroll
        for (int i = 0; i < 8; i++) {
            float cf = c_sm[tr * 8 + i];
#pragma unroll
            for (int j = 0; j < 8; j++) acc[i][j] *= cf;
        }

        // ---- O += P V : V read coalesced from [n][c], L1-resident tile ----
        const float* vt = vb + (size_t)n0 * C_ + tc * 8;
#pragma unroll 4
        for (int n = 0; n < 64; n++) {
            float vr[8];
            *(float4*)&vr[0] = *(const float4*)&vt[n * C_];
            *(float4*)&vr[4] = *(const float4*)&vt[n * C_ + 4];
#pragma unroll
            for (int i = 0; i < 8; i++) {
                float p = s_s[tr * 8 + i][n];   // broadcast within warp
#pragma unroll
                for (int j = 0; j < 8; j++) acc[i][j] += p * vr[j];
            }
        }
    }

    // ---- normalize + store AO [m][c] (coalesced) ----
#pragma unroll
    for (int i = 0; i < 8; i++) {
        float inv = 1.f / l_sm[tr * 8 + i];
        float* p = ao + (size_t)(b * N_ + m0 + tr * 8 + i) * C_ + tc * 8;
        *(float4*)&p[0] = make_float4(acc[i][0]*inv, acc[i][1]*inv, acc[i][2]*inv, acc[i][3]*inv);
        *(float4*)&p[4] = make_float4(acc[i][4]*inv, acc[i][5]*inv, acc[i][6]*inv, acc[i][7]*inv);
    }
}

// ---------------------------------------------------------------------------
// Output projection + bias + residual:
//   out[b][o][m] = sum_c wo[o][c] * AO[b][m][c] + bo[o] + x[b][o][m]
// Same tiling as proj_kernel; AO tile transposed into smem on load.
// ---------------------------------------------------------------------------
__global__ __launch_bounds__(256)
void oproj_kernel(const float* __restrict__ AO,
                  const float* __restrict__ W,
                  const float* __restrict__ bias,
                  const float* __restrict__ x,
                  float* __restrict__ out)
{
    __shared__ float W_s[32][68];
    __shared__ float A_s[64][132];
    const int b  = blockIdx.z;
    const int o0 = blockIdx.y * 32;
    const int m0 = blockIdx.x * 128;
    const int t  = threadIdx.x;
    const int to = t >> 4, tn = t & 15;

    float acc[2][8];
#pragma unroll
    for (int i = 0; i < 2; i++)
#pragma unroll
        for (int j = 0; j < 8; j++) acc[i][j] = 0.f;

    for (int kt = 0; kt < C_; kt += 64) {
        __syncthreads();
#pragma unroll
        for (int it = 0; it < 2; it++) {
            int idx4 = t + it * 256;
            int o = idx4 >> 4, c4 = idx4 & 15;
            *(float4*)&W_s[o][c4 * 4] =
                *(const float4*)&W[(o0 + o) * C_ + kt + c4 * 4];
        }
#pragma unroll
        for (int it = 0; it < 8; it++) {          // AO[m][c] -> A_s[c][m]
            int idx4 = t + it * 256;
            int m = idx4 >> 4, c4 = idx4 & 15;
            float4 a4 = *(const float4*)&AO[(size_t)(b * N_ + m0 + m) * C_ + kt + c4 * 4];
            A_s[c4 * 4 + 0][m] = a4.x;
            A_s[c4 * 4 + 1][m] = a4.y;
            A_s[c4 * 4 + 2][m] = a4.z;
            A_s[c4 * 4 + 3][m] = a4.w;
        }
        __syncthreads();
#pragma unroll 4
        for (int kc = 0; kc < 64; kc++) {
            float ar[8];
            *(float4*)&ar[0] = *(const float4*)&A_s[kc][tn * 8];
            *(float4*)&ar[4] = *(const float4*)&A_s[kc][tn * 8 + 4];
            float w0 = W_s[to * 2 + 0][kc];
            float w1 = W_s[to * 2 + 1][kc];
#pragma unroll
            for (int j = 0; j < 8; j++) {
                acc[0][j] += w0 * ar[j];
                acc[1][j] += w1 * ar[j];
            }
        }
    }

#pragma unroll
    for (int i = 0; i < 2; i++) {
        int o = o0 + to * 2 + i;
        float bv = bias[o];
        size_t base = (size_t)(b * C_ + o) * N_ + m0 + tn * 8;
        float4 x0 = *(const float4*)&x[base];
        float4 x1 = *(const float4*)&x[base + 4];
        *(float4*)&out[base] =
            make_float4(acc[i][0]+bv+x0.x, acc[i][1]+bv+x0.y, acc[i][2]+bv+x0.z, acc[i][3]+bv+x0.w);
        *(float4*)&out[base + 4] =
            make_float4(acc[i][4]+bv+x1.x, acc[i][5]+bv+x1.y, acc[i][6]+bv+x1.z, acc[i][7]+bv+x1.w);
    }
}

// ---------------------------------------------------------------------------
extern "C" void kernel_launch(void* const* d_in, const int* in_sizes, int n_in,
                              void* d_out, int out_size)
{
    const float* x  = (const float*)d_in[0];
    const float* wq = (const float*)d_in[1];
    const float* bq = (const float*)d_in[2];
    const float* wk = (const float*)d_in[3];
    const float* bk = (const float*)d_in[4];
    const float* wv = (const float*)d_in[5];
    const float* bv = (const float*)d_in[6];
    const float* wo = (const float*)d_in[7];
    const float* bo = (const float*)d_in[8];
    float* out = (float*)d_out;

    float *gq, *gk, *gv, *gao;
    cudaGetSymbolAddress((void**)&gq,  g_q);
    cudaGetSymbolAddress((void**)&gk,  g_k);
    cudaGetSymbolAddress((void**)&gv,  g_v);
    cudaGetSymbolAddress((void**)&gao, g_ao);

    dim3 blk(256);
    proj_kernel<false><<<dim3(N_ / 128, 1,       B_), blk>>>(x, wq, bq, gq, D_);
    proj_kernel<false><<<dim3(N_ / 128, 1,       B_), blk>>>(x, wk, bk, gk, D_);
    proj_kernel<true ><<<dim3(N_ / 128, C_ / 32, B_), blk>>>(x, wv, bv, gv, C_);
    attn_kernel       <<<dim3(N_ / 64,  B_),          blk>>>(gq, gk, gv, gao);
    oproj_kernel      <<<dim3(N_ / 128, C_ / 32, B_), blk>>>(gao, wo, bo, x, out);
}

// round 4
// speedup vs baseline: 1.8954x; 1.8832x over previous
#include <cuda_runtime.h>
#include <cuda_bf16.h>
#include <math.h>
#include <stdint.h>

#define B_ 4
#define C_ 256
#define N_ 4096
#define D_ 32

// ---------------------------------------------------------------------------
// PTX helpers (base sm_100-safe ONLY: mma.sync, cp.async, cp.async.bulk,
// mbarrier+expect_tx. NO tcgen05/TMEM/'a'-variant features.)
// ---------------------------------------------------------------------------
__device__ __forceinline__ uint32_t smem_u32(const void* p) {
    uint32_t a;
    asm("{ .reg .u64 t; cvta.to.shared.u64 t, %1; cvt.u32.u64 %0, t; }" : "=r"(a) : "l"(p));
    return a;
}
#define MBARRIER_INIT(a, c) \
    asm volatile("mbarrier.init.shared.b64 [%0], %1;" :: "r"((uint32_t)(a)), "r"((uint32_t)(c)) : "memory")
#define MBARRIER_EXPECT_TX(a, n) \
    asm volatile("mbarrier.arrive.expect_tx.shared.b64 _, [%0], %1;" :: "r"((uint32_t)(a)), "r"((uint32_t)(n)) : "memory")
#define MBARRIER_WAIT_PARITY(a, ph) do { \
    uint32_t _m = (uint32_t)(a); uint32_t _p = (uint32_t)(ph); uint32_t _d; \
    asm volatile("{\n\t.reg .pred p;\n\tmbarrier.try_wait.parity.shared.b64 p, [%1], %2;\n\tselp.b32 %0,1,0,p;\n\t}" \
        : "=r"(_d) : "r"(_m), "r"(_p) : "memory"); \
    if (!_d) { \
        asm volatile("{\n\t.reg .pred P1;\n\tWL_%=:\n\tmbarrier.try_wait.parity.shared.b64 P1, [%0], %1;\n\t@P1 bra.uni WD_%=;\n\tbra.uni WL_%=;\n\tWD_%=:\n\t}" \
            :: "r"(_m), "r"(_p) : "memory"); \
    } } while (0)

__device__ __forceinline__ void cpasync16(uint32_t dst, const void* src) {
    asm volatile("cp.async.cg.shared.global [%0], [%1], 16;" :: "r"(dst), "l"(src) : "memory");
}
#define CP_COMMIT() asm volatile("cp.async.commit_group;" ::: "memory")
#define CP_WAIT0()  asm volatile("cp.async.wait_group 0;" ::: "memory")

__device__ __forceinline__ void bulk128(uint32_t dst, const void* src, uint32_t mbar) {
    asm volatile("cp.async.bulk.shared::cta.global.mbarrier::complete_tx::bytes [%0], [%1], 128, [%2];"
                 :: "r"(dst), "l"(src), "r"(mbar) : "memory");
}

__device__ __forceinline__ void mma16816(float* d, const uint32_t* a, const uint32_t* b) {
    asm volatile("mma.sync.aligned.m16n8k16.row.col.f32.bf16.bf16.f32 "
                 "{%0,%1,%2,%3}, {%4,%5,%6,%7}, {%8,%9}, {%0,%1,%2,%3};"
                 : "+f"(d[0]), "+f"(d[1]), "+f"(d[2]), "+f"(d[3])
                 : "r"(a[0]), "r"(a[1]), "r"(a[2]), "r"(a[3]), "r"(b[0]), "r"(b[1]));
}

__device__ __forceinline__ uint32_t pack_bf16x2(float x, float y) {
    __nv_bfloat162 h = __floats2bfloat162_rn(x, y);
    return *(uint32_t*)&h;
}

// ---------------------------------------------------------------------------
// Scratch
// ---------------------------------------------------------------------------
__device__ __nv_bfloat16 g_qp [B_*N_*64];   // [b][n][qh(32)|ql(32)]
__device__ __nv_bfloat16 g_kp [B_*N_*64];
__device__ __nv_bfloat16 g_vhi[B_*C_*N_];   // [b][c][n]
__device__ __nv_bfloat16 g_vlo[B_*C_*N_];
__device__ float         g_ao [B_*N_*C_];   // [b][n][c]

// ---------------------------------------------------------------------------
// QK projection -> packed hi|lo bf16 rows (O=32)
// ---------------------------------------------------------------------------
__global__ __launch_bounds__(256)
void qk_pack_kernel(const float* __restrict__ X, const float* __restrict__ W,
                    const float* __restrict__ bias, __nv_bfloat16* __restrict__ outp)
{
    __shared__ float W_s[32][68];
    __shared__ float X_s[64][132];
    const int b  = blockIdx.z;
    const int n0 = blockIdx.x * 128;
    const int t  = threadIdx.x;
    const int to = t >> 4, tn = t & 15;
    const float* Xb = X + b * (C_ * N_);

    float acc[2][8];
#pragma unroll
    for (int i = 0; i < 2; i++)
#pragma unroll
        for (int j = 0; j < 8; j++) acc[i][j] = 0.f;

    for (int kt = 0; kt < C_; kt += 64) {
        __syncthreads();
#pragma unroll
        for (int it = 0; it < 2; it++) {
            int idx4 = t + it * 256;
            int o = idx4 >> 4, c4 = idx4 & 15;
            *(float4*)&W_s[o][c4 * 4] = *(const float4*)&W[o * C_ + kt + c4 * 4];
        }
#pragma unroll
        for (int it = 0; it < 8; it++) {
            int idx4 = t + it * 256;
            int kc = idx4 >> 5, n4 = idx4 & 31;
            *(float4*)&X_s[kc][n4 * 4] = *(const float4*)&Xb[(kt + kc) * N_ + n0 + n4 * 4];
        }
        __syncthreads();
#pragma unroll 4
        for (int kc = 0; kc < 64; kc++) {
            float xr[8];
            *(float4*)&xr[0] = *(const float4*)&X_s[kc][tn * 8];
            *(float4*)&xr[4] = *(const float4*)&X_s[kc][tn * 8 + 4];
            float w0 = W_s[to * 2 + 0][kc];
            float w1 = W_s[to * 2 + 1][kc];
#pragma unroll
            for (int j = 0; j < 8; j++) { acc[0][j] += w0 * xr[j]; acc[1][j] += w1 * xr[j]; }
        }
    }
    __syncthreads();
#pragma unroll
    for (int i = 0; i < 2; i++) {
        float bv = bias[to * 2 + i];
#pragma unroll
        for (int j = 0; j < 8; j++) X_s[to * 2 + i][tn * 8 + j] = acc[i][j] + bv;
    }
    __syncthreads();
#pragma unroll
    for (int it = 0; it < 8; it++) {             // 128 n x 16 granules(4 bf16)
        int idx = t + it * 256;
        int n = idx >> 4, g = idx & 15;
        unsigned short us[4];
#pragma unroll
        for (int e = 0; e < 4; e++) {
            int col = g * 4 + e;
            if (col < 32) {
                us[e] = __bfloat16_as_ushort(__float2bfloat16(X_s[col][n]));
            } else {
                float f = X_s[col - 32][n];
                __nv_bfloat16 h = __float2bfloat16(f);
                us[e] = __bfloat16_as_ushort(__float2bfloat16(f - __bfloat162float(h)));
            }
        }
        *(uint2*)&outp[(size_t)(b * N_ + n0 + n) * 64 + g * 4] = *(uint2*)us;
    }
}

// ---------------------------------------------------------------------------
// V projection -> v_hi / v_lo bf16 [b][c][n]
// ---------------------------------------------------------------------------
__global__ __launch_bounds__(256)
void v_split_kernel(const float* __restrict__ X, const float* __restrict__ W,
                    const float* __restrict__ bias,
                    __nv_bfloat16* __restrict__ vhi, __nv_bfloat16* __restrict__ vlo)
{
    __shared__ float W_s[32][68];
    __shared__ float X_s[64][132];
    const int b  = blockIdx.z;
    const int o0 = blockIdx.y * 32;
    const int n0 = blockIdx.x * 128;
    const int t  = threadIdx.x;
    const int to = t >> 4, tn = t & 15;
    const float* Xb = X + b * (C_ * N_);

    float acc[2][8];
#pragma unroll
    for (int i = 0; i < 2; i++)
#pragma unroll
        for (int j = 0; j < 8; j++) acc[i][j] = 0.f;

    for (int kt = 0; kt < C_; kt += 64) {
        __syncthreads();
#pragma unroll
        for (int it = 0; it < 2; it++) {
            int idx4 = t + it * 256;
            int o = idx4 >> 4, c4 = idx4 & 15;
            *(float4*)&W_s[o][c4 * 4] = *(const float4*)&W[(o0 + o) * C_ + kt + c4 * 4];
        }
#pragma unroll
        for (int it = 0; it < 8; it++) {
            int idx4 = t + it * 256;
            int kc = idx4 >> 5, n4 = idx4 & 31;
            *(float4*)&X_s[kc][n4 * 4] = *(const float4*)&Xb[(kt + kc) * N_ + n0 + n4 * 4];
        }
        __syncthreads();
#pragma unroll 4
        for (int kc = 0; kc < 64; kc++) {
            float xr[8];
            *(float4*)&xr[0] = *(const float4*)&X_s[kc][tn * 8];
            *(float4*)&xr[4] = *(const float4*)&X_s[kc][tn * 8 + 4];
            float w0 = W_s[to * 2 + 0][kc];
            float w1 = W_s[to * 2 + 1][kc];
#pragma unroll
            for (int j = 0; j < 8; j++) { acc[0][j] += w0 * xr[j]; acc[1][j] += w1 * xr[j]; }
        }
    }
#pragma unroll
    for (int i = 0; i < 2; i++) {
        int o = o0 + to * 2 + i;
        float bv = bias[o];
        unsigned short hs[8], ls[8];
#pragma unroll
        for (int j = 0; j < 8; j++) {
            float f = acc[i][j] + bv;
            __nv_bfloat16 h = __float2bfloat16(f);
            hs[j] = __bfloat16_as_ushort(h);
            ls[j] = __bfloat16_as_ushort(__float2bfloat16(f - __bfloat162float(h)));
        }
        size_t base = (size_t)(b * C_ + o) * N_ + n0 + tn * 8;
        *(uint4*)&vhi[base] = *(uint4*)hs;
        *(uint4*)&vlo[base] = *(uint4*)ls;
    }
}

// ---------------------------------------------------------------------------
// mma.sync flash attention. 512 threads, M=128 q/CTA, 64-key tiles.
// All smem tiles use 144B row stride (16B aligned, bank-conflict-free:
// bank = (4g + tg) mod 32, distinct across the warp for every frag pattern).
// ---------------------------------------------------------------------------
#define RS 144
#define OFF_MBAR 0
#define OFF_LSUM 16
#define OFF_Q    1024
#define OFF_K0   19456
#define OFF_K1   28672
#define OFF_PH   37888
#define OFF_PL   56320
#define OFF_VH0  74752
#define OFF_VL0  111616
#define OFF_VH1  148480
#define OFF_VL1  185344
#define ATTN_SMEM 222208
#define TILE_TX  73728   // (64 + 256 + 256) rows * 128 B

__device__ __forceinline__ void ldA(uint32_t* a, const char* base, int R, int col, int goff) {
    // goff = g*RS + tg*4 (bytes); col in bf16 elements
    a[0] = *(const uint32_t*)(base + R * RS + goff + col * 2);
    a[1] = *(const uint32_t*)(base + (R + 8) * RS + goff + col * 2);
    a[2] = *(const uint32_t*)(base + R * RS + goff + (col + 8) * 2);
    a[3] = *(const uint32_t*)(base + (R + 8) * RS + goff + (col + 8) * 2);
}
__device__ __forceinline__ void ldB(uint32_t* bfr, const char* base, int Rn, int col, int goff) {
    bfr[0] = *(const uint32_t*)(base + Rn * RS + goff + col * 2);
    bfr[1] = *(const uint32_t*)(base + Rn * RS + goff + (col + 8) * 2);
}

__global__ __launch_bounds__(512, 1)
void attn_mma_kernel(const __nv_bfloat16* __restrict__ qp,
                     const __nv_bfloat16* __restrict__ kp,
                     const __nv_bfloat16* __restrict__ vhi,
                     const __nv_bfloat16* __restrict__ vlo,
                     float* __restrict__ ao)
{
    extern __shared__ char sm[];
    const uint32_t sb = smem_u32(sm);
    const int t = threadIdx.x;
    const int wid = t >> 5, lane = t & 31;
    const int g = lane >> 2, tg = lane & 3;
    const int goff = g * RS + tg * 4;
    const int wm = wid >> 2, wn = wid & 3;       // 4x4 warp grid
    const int b = blockIdx.y, m0 = blockIdx.x * 128;

    const __nv_bfloat16* qp_b = qp + (size_t)b * N_ * 64;
    const __nv_bfloat16* kp_b = kp + (size_t)b * N_ * 64;
    const __nv_bfloat16* vh_b = vhi + (size_t)b * C_ * N_;
    const __nv_bfloat16* vl_b = vlo + (size_t)b * C_ * N_;

    float* lsum_s = (float*)(sm + OFF_LSUM);
    if (t == 0) { MBARRIER_INIT(sb + OFF_MBAR, 1); MBARRIER_INIT(sb + OFF_MBAR + 8, 1); }
    if (t < 128) lsum_s[t] = 0.f;

    // Q load (once): 128 rows x 128B, 16B chunks
#pragma unroll
    for (int i = 0; i < 2; i++) {
        int idx = t + i * 512;
        int r = idx >> 3, ch = idx & 7;
        cpasync16(sb + OFF_Q + r * RS + ch * 16, qp_b + (size_t)(m0 + r) * 64 + ch * 8);
    }
    CP_COMMIT();
    __syncthreads();   // mbarrier init + lsum visible before first expect_tx

    // issue tile 0 into buffer 0
    {
        if (t == 0) MBARRIER_EXPECT_TX(sb + OFF_MBAR, TILE_TX);
        if (t < 256) {
            bulk128(sb + OFF_VH0 + t * RS, vh_b + (size_t)t * N_, sb + OFF_MBAR);
            if (t < 64) bulk128(sb + OFF_K0 + t * RS, kp_b + (size_t)t * 64, sb + OFF_MBAR);
        } else {
            int c = t - 256;
            bulk128(sb + OFF_VL0 + c * RS, vl_b + (size_t)c * N_, sb + OFF_MBAR);
        }
    }
    CP_WAIT0();        // Q resident

    float oacc[2][8][4];
#pragma unroll
    for (int i = 0; i < 2; i++)
#pragma unroll
        for (int j = 0; j < 8; j++)
#pragma unroll
            for (int c = 0; c < 4; c++) oacc[i][j][c] = 0.f;
    float lpart[2][2] = {{0.f, 0.f}, {0.f, 0.f}};

    // (A-col, B-col) pairs for the 3 split-precision terms x 2 k16 steps
    const int acol[6] = {0, 16, 32, 48, 0, 16};
    const int bcol[6] = {0, 16, 0, 16, 32, 48};

    for (int nt = 0; nt < 64; nt++) {
        const int cur = nt & 1;
        if (nt + 1 < 64) {                       // prefetch next tile
            const int nb = (nt + 1) & 1;
            const int nn = (nt + 1) * 64;
            const uint32_t kd  = sb + (nb ? OFF_K1 : OFF_K0);
            const uint32_t vhd = sb + (nb ? OFF_VH1 : OFF_VH0);
            const uint32_t vld = sb + (nb ? OFF_VL1 : OFF_VL0);
            const uint32_t mb  = sb + OFF_MBAR + nb * 8;
            if (t == 0) MBARRIER_EXPECT_TX(mb, TILE_TX);
            if (t < 256) {
                bulk128(vhd + t * RS, vh_b + (size_t)t * N_ + nn, mb);
                if (t < 64) bulk128(kd + t * RS, kp_b + (size_t)(nn + t) * 64, mb);
            } else {
                int c = t - 256;
                bulk128(vld + c * RS, vl_b + (size_t)c * N_ + nn, mb);
            }
        }
        MBARRIER_WAIT_PARITY(sb + OFF_MBAR + cur * 8, (nt >> 1) & 1);
        __syncthreads();

        const char* Kp  = sm + (cur ? OFF_K1 : OFF_K0);
        const char* Vhp = sm + (cur ? OFF_VH1 : OFF_VH0);
        const char* Vlp = sm + (cur ? OFF_VL1 : OFF_VL0);

        // ---- S = Q K^T : warp tile M32 x N16 (rows wm*32, keys wn*16) ----
        float sacc[2][2][4];
#pragma unroll
        for (int i = 0; i < 2; i++)
#pragma unroll
            for (int j = 0; j < 2; j++)
#pragma unroll
                for (int c = 0; c < 4; c++) sacc[i][j][c] = 0.f;

#pragma unroll
        for (int s = 0; s < 6; s++) {
            uint32_t af[2][4], bf[2][2];
#pragma unroll
            for (int mf = 0; mf < 2; mf++)
                ldA(af[mf], sm + OFF_Q, wm * 32 + mf * 16, acol[s], goff);
#pragma unroll
            for (int nf = 0; nf < 2; nf++)
                ldB(bf[nf], Kp, wn * 16 + nf * 8, bcol[s], goff);
#pragma unroll
            for (int mf = 0; mf < 2; mf++)
#pragma unroll
                for (int nf = 0; nf < 2; nf++)
                    mma16816(sacc[mf][nf], af[mf], bf[nf]);
        }

        // ---- softmax on fragments -> P hi/lo smem ----
#pragma unroll
        for (int mf = 0; mf < 2; mf++) {
            const int r0 = wm * 32 + mf * 16 + g;
#pragma unroll
            for (int nf = 0; nf < 2; nf++) {
                const int cb = wn * 16 + nf * 8 + 2 * tg;
                float p0 = __expf(fminf(sacc[mf][nf][0], 60.f));
                float p1 = __expf(fminf(sacc[mf][nf][1], 60.f));
                float p2 = __expf(fminf(sacc[mf][nf][2], 60.f));
                float p3 = __expf(fminf(sacc[mf][nf][3], 60.f));
                lpart[mf][0] += p0 + p1;
                lpart[mf][1] += p2 + p3;
                __nv_bfloat16 h0 = __float2bfloat16(p0), h1 = __float2bfloat16(p1);
                __nv_bfloat16 h2 = __float2bfloat16(p2), h3 = __float2bfloat16(p3);
                float l0 = p0 - __bfloat162float(h0), l1 = p1 - __bfloat162float(h1);
                float l2 = p2 - __bfloat162float(h2), l3 = p3 - __bfloat162float(h3);
                *(uint32_t*)(sm + OFF_PH + r0 * RS + cb * 2) =
                    (uint32_t)__bfloat16_as_ushort(h0) | ((uint32_t)__bfloat16_as_ushort(h1) << 16);
                *(uint32_t*)(sm + OFF_PH + (r0 + 8) * RS + cb * 2) =
                    (uint32_t)__bfloat16_as_ushort(h2) | ((uint32_t)__bfloat16_as_ushort(h3) << 16);
                *(uint32_t*)(sm + OFF_PL + r0 * RS + cb * 2) = pack_bf16x2(l0, l1);
                *(uint32_t*)(sm + OFF_PL + (r0 + 8) * RS + cb * 2) = pack_bf16x2(l2, l3);
            }
        }
        __syncthreads();

        // ---- O += P V : warp tile M32 x N64 channels (rows wm*32, ch wn*64) ----
#pragma unroll
        for (int kk = 0; kk < 4; kk++) {
            uint32_t aH[2][4], aL[2][4];
#pragma unroll
            for (int mf = 0; mf < 2; mf++) {
                ldA(aH[mf], sm + OFF_PH, wm * 32 + mf * 16, kk * 16, goff);
                ldA(aL[mf], sm + OFF_PL, wm * 32 + mf * 16, kk * 16, goff);
            }
#pragma unroll
            for (int nf = 0; nf < 8; nf++) {
                uint32_t bh[2], bl[2];
                ldB(bh, Vhp, wn * 64 + nf * 8, kk * 16, goff);
                ldB(bl, Vlp, wn * 64 + nf * 8, kk * 16, goff);
#pragma unroll
                for (int mf = 0; mf < 2; mf++) {
                    mma16816(oacc[mf][nf], aH[mf], bh);
                    mma16816(oacc[mf][nf], aL[mf], bh);
                    mma16816(oacc[mf][nf], aH[mf], bl);
                }
            }
        }
        __syncthreads();   // P + V buffers free for next tile
    }

    // ---- lsum reduction ----
#pragma unroll
    for (int mf = 0; mf < 2; mf++) {
        atomicAdd(&lsum_s[wm * 32 + mf * 16 + g],     lpart[mf][0]);
        atomicAdd(&lsum_s[wm * 32 + mf * 16 + 8 + g], lpart[mf][1]);
    }
    __syncthreads();

    // ---- epilogue: O / lsum -> g_ao [b][m][c] ----
#pragma unroll
    for (int mf = 0; mf < 2; mf++) {
        const int rA = wm * 32 + mf * 16 + g;
        const int rB = rA + 8;
        const float invA = 1.f / lsum_s[rA];
        const float invB = 1.f / lsum_s[rB];
        float* baseA = ao + (size_t)(b * N_ + m0 + rA) * C_;
        float* baseB = ao + (size_t)(b * N_ + m0 + rB) * C_;
#pragma unroll
        for (int nf = 0; nf < 8; nf++) {
            const int cb = wn * 64 + nf * 8 + 2 * tg;
            *(float2*)(baseA + cb) = make_float2(oacc[mf][nf][0] * invA, oacc[mf][nf][1] * invA);
            *(float2*)(baseB + cb) = make_float2(oacc[mf][nf][2] * invB, oacc[mf][nf][3] * invB);
        }
    }
}

// ---------------------------------------------------------------------------
// Output projection + bias + residual (fp32)
// ---------------------------------------------------------------------------
__global__ __launch_bounds__(256)
void oproj_kernel(const float* __restrict__ AO,
                  const float* __restrict__ W,
                  const float* __restrict__ bias,
                  const float* __restrict__ x,
                  float* __restrict__ out)
{
    __shared__ float W_s[32][68];
    __shared__ float A_s[64][132];
    const int b  = blockIdx.z;
    const int o0 = blockIdx.y * 32;
    const int m0 = blockIdx.x * 128;
    const int t  = threadIdx.x;
    const int to = t >> 4, tn = t & 15;

    float acc[2][8];
#pragma unroll
    for (int i = 0; i < 2; i++)
#pragma unroll
        for (int j = 0; j < 8; j++) acc[i][j] = 0.f;

    for (int kt = 0; kt < C_; kt += 64) {
        __syncthreads();
#pragma unroll
        for (int it = 0; it < 2; it++) {
            int idx4 = t + it * 256;
            int o = idx4 >> 4, c4 = idx4 & 15;
            *(float4*)&W_s[o][c4 * 4] = *(const float4*)&W[(o0 + o) * C_ + kt + c4 * 4];
        }
#pragma unroll
        for (int it = 0; it < 8; it++) {
            int idx4 = t + it * 256;
            int m = idx4 >> 4, c4 = idx4 & 15;
            float4 a4 = *(const float4*)&AO[(size_t)(b * N_ + m0 + m) * C_ + kt + c4 * 4];
            A_s[c4 * 4 + 0][m] = a4.x;
            A_s[c4 * 4 + 1][m] = a4.y;
            A_s[c4 * 4 + 2][m] = a4.z;
            A_s[c4 * 4 + 3][m] = a4.w;
        }
        __syncthreads();
#pragma unroll 4
        for (int kc = 0; kc < 64; kc++) {
            float ar[8];
            *(float4*)&ar[0] = *(const float4*)&A_s[kc][tn * 8];
            *(float4*)&ar[4] = *(const float4*)&A_s[kc][tn * 8 + 4];
            float w0 = W_s[to * 2 + 0][kc];
            float w1 = W_s[to * 2 + 1][kc];
#pragma unroll
            for (int j = 0; j < 8; j++) { acc[0][j] += w0 * ar[j]; acc[1][j] += w1 * ar[j]; }
        }
    }

#pragma unroll
    for (int i = 0; i < 2; i++) {
        int o = o0 + to * 2 + i;
        float bv = bias[o];
        size_t base = (size_t)(b * C_ + o) * N_ + m0 + tn * 8;
        float4 x0 = *(const float4*)&x[base];
        float4 x1 = *(const float4*)&x[base + 4];
        *(float4*)&out[base] =
            make_float4(acc[i][0]+bv+x0.x, acc[i][1]+bv+x0.y, acc[i][2]+bv+x0.z, acc[i][3]+bv+x0.w);
        *(float4*)&out[base + 4] =
            make_float4(acc[i][4]+bv+x1.x, acc[i][5]+bv+x1.y, acc[i][6]+bv+x1.z, acc[i][7]+bv+x1.w);
    }
}

// ---------------------------------------------------------------------------
extern "C" void kernel_launch(void* const* d_in, const int* in_sizes, int n_in,
                              void* d_out, int out_size)
{
    const float* x  = (const float*)d_in[0];
    const float* wq = (const float*)d_in[1];
    const float* bq = (const float*)d_in[2];
    const float* wk = (const float*)d_in[3];
    const float* bk = (const float*)d_in[4];
    const float* wv = (const float*)d_in[5];
    const float* bv = (const float*)d_in[6];
    const float* wo = (const float*)d_in[7];
    const float* bo = (const float*)d_in[8];
    float* out = (float*)d_out;

    __nv_bfloat16 *gqp, *gkp, *gvh, *gvl;
    float *gao;
    cudaGetSymbolAddress((void**)&gqp, g_qp);
    cudaGetSymbolAddress((void**)&gkp, g_kp);
    cudaGetSymbolAddress((void**)&gvh, g_vhi);
    cudaGetSymbolAddress((void**)&gvl, g_vlo);
    cudaGetSymbolAddress((void**)&gao, g_ao);

    cudaFuncSetAttribute(attn_mma_kernel, cudaFuncAttributeMaxDynamicSharedMemorySize, ATTN_SMEM);

    dim3 blk(256);
    qk_pack_kernel<<<dim3(N_ / 128, 1, B_), blk>>>(x, wq, bq, gqp);
    qk_pack_kernel<<<dim3(N_ / 128, 1, B_), blk>>>(x, wk, bk, gkp);
    v_split_kernel<<<dim3(N_ / 128, C_ / 32, B_), blk>>>(x, wv, bv, gvh, gvl);
    attn_mma_kernel<<<dim3(N_ / 128, B_), 512, ATTN_SMEM>>>(gqp, gkp, gvh, gvl, gao);
    oproj_kernel  <<<dim3(N_ / 128, C_ / 32, B_), blk>>>(gao, wo, bo, x, out);
}

// round 5
// speedup vs baseline: 2.1678x; 1.1437x over previous
#include <cuda_runtime.h>
#include <cuda_bf16.h>
#include <math.h>
#include <stdint.h>

#define B_ 4
#define C_ 256
#define N_ 4096
#define D_ 32

// ---------------------------------------------------------------------------
// PTX helpers (base sm_100-safe: mma.sync, cp.async, cp.async.bulk, mbarrier)
// ---------------------------------------------------------------------------
__device__ __forceinline__ uint32_t smem_u32(const void* p) {
    uint32_t a;
    asm("{ .reg .u64 t; cvta.to.shared.u64 t, %1; cvt.u32.u64 %0, t; }" : "=r"(a) : "l"(p));
    return a;
}
#define MBARRIER_INIT(a, c) \
    asm volatile("mbarrier.init.shared.b64 [%0], %1;" :: "r"((uint32_t)(a)), "r"((uint32_t)(c)) : "memory")
#define MBARRIER_EXPECT_TX(a, n) \
    asm volatile("mbarrier.arrive.expect_tx.shared.b64 _, [%0], %1;" :: "r"((uint32_t)(a)), "r"((uint32_t)(n)) : "memory")
#define MBARRIER_WAIT_PARITY(a, ph) do { \
    uint32_t _m = (uint32_t)(a); uint32_t _p = (uint32_t)(ph); uint32_t _d; \
    asm volatile("{\n\t.reg .pred p;\n\tmbarrier.try_wait.parity.shared.b64 p, [%1], %2;\n\tselp.b32 %0,1,0,p;\n\t}" \
        : "=r"(_d) : "r"(_m), "r"(_p) : "memory"); \
    if (!_d) { \
        asm volatile("{\n\t.reg .pred P1;\n\tWL_%=:\n\tmbarrier.try_wait.parity.shared.b64 P1, [%0], %1;\n\t@P1 bra.uni WD_%=;\n\tbra.uni WL_%=;\n\tWD_%=:\n\t}" \
            :: "r"(_m), "r"(_p) : "memory"); \
    } } while (0)

__device__ __forceinline__ void cpasync16(uint32_t dst, const void* src) {
    asm volatile("cp.async.cg.shared.global [%0], [%1], 16;" :: "r"(dst), "l"(src) : "memory");
}
#define CP_COMMIT() asm volatile("cp.async.commit_group;" ::: "memory")
#define CP_WAIT0()  asm volatile("cp.async.wait_group 0;" ::: "memory")

__device__ __forceinline__ void bulk128(uint32_t dst, const void* src, uint32_t mbar) {
    asm volatile("cp.async.bulk.shared::cta.global.mbarrier::complete_tx::bytes [%0], [%1], 128, [%2];"
                 :: "r"(dst), "l"(src), "r"(mbar) : "memory");
}

__device__ __forceinline__ void mma16816(float* d, const uint32_t* a, const uint32_t* b) {
    asm volatile("mma.sync.aligned.m16n8k16.row.col.f32.bf16.bf16.f32 "
                 "{%0,%1,%2,%3}, {%4,%5,%6,%7}, {%8,%9}, {%0,%1,%2,%3};"
                 : "+f"(d[0]), "+f"(d[1]), "+f"(d[2]), "+f"(d[3])
                 : "r"(a[0]), "r"(a[1]), "r"(a[2]), "r"(a[3]), "r"(b[0]), "r"(b[1]));
}
__device__ __forceinline__ uint32_t pack_bf16x2(float x, float y) {
    __nv_bfloat162 h = __floats2bfloat162_rn(x, y);
    return *(uint32_t*)&h;
}

// ---------------------------------------------------------------------------
// Scratch
// ---------------------------------------------------------------------------
__device__ __nv_bfloat16 g_qp [B_*N_*64];   // [b][n][qh(32)|ql(32)]
__device__ __nv_bfloat16 g_kp [B_*N_*64];
__device__ __nv_bfloat16 g_vhi[B_*C_*N_];   // [b][c][n]
__device__ float         g_ao [B_*N_*C_];   // [b][n][c]

// ---------------------------------------------------------------------------
// QK projection -> packed hi|lo bf16 rows (O=32)
// ---------------------------------------------------------------------------
__global__ __launch_bounds__(256)
void qk_pack_kernel(const float* __restrict__ X, const float* __restrict__ W,
                    const float* __restrict__ bias, __nv_bfloat16* __restrict__ outp)
{
    __shared__ float W_s[32][68];
    __shared__ float X_s[64][132];
    const int b  = blockIdx.z;
    const int n0 = blockIdx.x * 128;
    const int t  = threadIdx.x;
    const int to = t >> 4, tn = t & 15;
    const float* Xb = X + b * (C_ * N_);

    float acc[2][8];
#pragma unroll
    for (int i = 0; i < 2; i++)
#pragma unroll
        for (int j = 0; j < 8; j++) acc[i][j] = 0.f;

    for (int kt = 0; kt < C_; kt += 64) {
        __syncthreads();
#pragma unroll
        for (int it = 0; it < 2; it++) {
            int idx4 = t + it * 256;
            int o = idx4 >> 4, c4 = idx4 & 15;
            *(float4*)&W_s[o][c4 * 4] = *(const float4*)&W[o * C_ + kt + c4 * 4];
        }
#pragma unroll
        for (int it = 0; it < 8; it++) {
            int idx4 = t + it * 256;
            int kc = idx4 >> 5, n4 = idx4 & 31;
            *(float4*)&X_s[kc][n4 * 4] = *(const float4*)&Xb[(kt + kc) * N_ + n0 + n4 * 4];
        }
        __syncthreads();
#pragma unroll 4
        for (int kc = 0; kc < 64; kc++) {
            float xr[8];
            *(float4*)&xr[0] = *(const float4*)&X_s[kc][tn * 8];
            *(float4*)&xr[4] = *(const float4*)&X_s[kc][tn * 8 + 4];
            float w0 = W_s[to * 2 + 0][kc];
            float w1 = W_s[to * 2 + 1][kc];
#pragma unroll
            for (int j = 0; j < 8; j++) { acc[0][j] += w0 * xr[j]; acc[1][j] += w1 * xr[j]; }
        }
    }
    __syncthreads();
#pragma unroll
    for (int i = 0; i < 2; i++) {
        float bv = bias[to * 2 + i];
#pragma unroll
        for (int j = 0; j < 8; j++) X_s[to * 2 + i][tn * 8 + j] = acc[i][j] + bv;
    }
    __syncthreads();
#pragma unroll
    for (int it = 0; it < 8; it++) {             // 128 n x 16 granules(4 bf16)
        int idx = t + it * 256;
        int n = idx >> 4, g = idx & 15;
        unsigned short us[4];
#pragma unroll
        for (int e = 0; e < 4; e++) {
            int col = g * 4 + e;
            if (col < 32) {
                us[e] = __bfloat16_as_ushort(__float2bfloat16(X_s[col][n]));
            } else {
                float f = X_s[col - 32][n];
                __nv_bfloat16 h = __float2bfloat16(f);
                us[e] = __bfloat16_as_ushort(__float2bfloat16(f - __bfloat162float(h)));
            }
        }
        *(uint2*)&outp[(size_t)(b * N_ + n0 + n) * 64 + g * 4] = *(uint2*)us;
    }
}

// ---------------------------------------------------------------------------
// V projection -> v_hi bf16 [b][c][n]  (no lo term needed anymore)
// ---------------------------------------------------------------------------
__global__ __launch_bounds__(256)
void v_proj_kernel(const float* __restrict__ X, const float* __restrict__ W,
                   const float* __restrict__ bias, __nv_bfloat16* __restrict__ vhi)
{
    __shared__ float W_s[32][68];
    __shared__ float X_s[64][132];
    const int b  = blockIdx.z;
    const int o0 = blockIdx.y * 32;
    const int n0 = blockIdx.x * 128;
    const int t  = threadIdx.x;
    const int to = t >> 4, tn = t & 15;
    const float* Xb = X + b * (C_ * N_);

    float acc[2][8];
#pragma unroll
    for (int i = 0; i < 2; i++)
#pragma unroll
        for (int j = 0; j < 8; j++) acc[i][j] = 0.f;

    for (int kt = 0; kt < C_; kt += 64) {
        __syncthreads();
#pragma unroll
        for (int it = 0; it < 2; it++) {
            int idx4 = t + it * 256;
            int o = idx4 >> 4, c4 = idx4 & 15;
            *(float4*)&W_s[o][c4 * 4] = *(const float4*)&W[(o0 + o) * C_ + kt + c4 * 4];
        }
#pragma unroll
        for (int it = 0; it < 8; it++) {
            int idx4 = t + it * 256;
            int kc = idx4 >> 5, n4 = idx4 & 31;
            *(float4*)&X_s[kc][n4 * 4] = *(const float4*)&Xb[(kt + kc) * N_ + n0 + n4 * 4];
        }
        __syncthreads();
#pragma unroll 4
        for (int kc = 0; kc < 64; kc++) {
            float xr[8];
            *(float4*)&xr[0] = *(const float4*)&X_s[kc][tn * 8];
            *(float4*)&xr[4] = *(const float4*)&X_s[kc][tn * 8 + 4];
            float w0 = W_s[to * 2 + 0][kc];
            float w1 = W_s[to * 2 + 1][kc];
#pragma unroll
            for (int j = 0; j < 8; j++) { acc[0][j] += w0 * xr[j]; acc[1][j] += w1 * xr[j]; }
        }
    }
#pragma unroll
    for (int i = 0; i < 2; i++) {
        int o = o0 + to * 2 + i;
        float bv = bias[o];
        unsigned short hs[8];
#pragma unroll
        for (int j = 0; j < 8; j++)
            hs[j] = __bfloat16_as_ushort(__float2bfloat16(acc[i][j] + bv));
        *(uint4*)&vhi[(size_t)(b * C_ + o) * N_ + n0 + tn * 8] = *(uint4*)hs;
    }
}

// ---------------------------------------------------------------------------
// Pipelined mma.sync flash attention. 512 threads, M=128 q/CTA, 64-key tiles.
// Per iter i: softmax(S_i)->P ; sync ; [PV_i + S_{i+1} one MMA block] ; sync.
// K prefetch distance 2, V distance 1, per-slot mbarriers.
// 144B row stride => conflict-free for all fragment patterns.
// ---------------------------------------------------------------------------
#define RS 144
#define OFF_MBAR 0      // mbK0@0 mbK1@8 mbV0@16 mbV1@24
#define OFF_LSUM 32
#define OFF_Q    1024
#define OFF_K0   19456
#define OFF_K1   28672
#define OFF_PH   37888
#define OFF_PL   56320
#define OFF_VH0  74752
#define OFF_VH1  111616
#define ATTN_SMEM 148480
#define K_TX 8192
#define V_TX 32768

__device__ __forceinline__ void ldA(uint32_t* a, const char* base, int R, int col, int goff) {
    a[0] = *(const uint32_t*)(base + R * RS + goff + col * 2);
    a[1] = *(const uint32_t*)(base + (R + 8) * RS + goff + col * 2);
    a[2] = *(const uint32_t*)(base + R * RS + goff + (col + 8) * 2);
    a[3] = *(const uint32_t*)(base + (R + 8) * RS + goff + (col + 8) * 2);
}
__device__ __forceinline__ void ldB(uint32_t* bfr, const char* base, int Rn, int col, int goff) {
    bfr[0] = *(const uint32_t*)(base + Rn * RS + goff + col * 2);
    bfr[1] = *(const uint32_t*)(base + Rn * RS + goff + (col + 8) * 2);
}

// S = Q K^T, 6 split-precision MMA steps -> sacc[2][2][4]
__device__ __forceinline__ void s_mma(float sacc[2][2][4], const char* sm_,
                                      const char* Kp, int wm, int wn, int goff)
{
#pragma unroll
    for (int i = 0; i < 2; i++)
#pragma unroll
        for (int j = 0; j < 2; j++)
#pragma unroll
            for (int c = 0; c < 4; c++) sacc[i][j][c] = 0.f;
    const int acol[6] = {0, 16, 32, 48, 0, 16};
    const int bcol[6] = {0, 16, 0, 16, 32, 48};
#pragma unroll
    for (int s = 0; s < 6; s++) {
        uint32_t af[2][4], bf[2][2];
#pragma unroll
        for (int mf = 0; mf < 2; mf++)
            ldA(af[mf], sm_ + OFF_Q, wm * 32 + mf * 16, acol[s], goff);
#pragma unroll
        for (int nf = 0; nf < 2; nf++)
            ldB(bf[nf], Kp, wn * 16 + nf * 8, bcol[s], goff);
#pragma unroll
        for (int mf = 0; mf < 2; mf++)
#pragma unroll
            for (int nf = 0; nf < 2; nf++)
                mma16816(sacc[mf][nf], af[mf], bf[nf]);
    }
}

__global__ __launch_bounds__(512, 1)
void attn_mma_kernel(const __nv_bfloat16* __restrict__ qp,
                     const __nv_bfloat16* __restrict__ kp,
                     const __nv_bfloat16* __restrict__ vhi,
                     float* __restrict__ ao)
{
    extern __shared__ char sm[];
    const uint32_t sb = smem_u32(sm);
    const int t = threadIdx.x;
    const int wid = t >> 5, lane = t & 31;
    const int g = lane >> 2, tg = lane & 3;
    const int goff = g * RS + tg * 4;
    const int wm = wid >> 2, wn = wid & 3;       // 4x4 warp grid
    const int b = blockIdx.y, m0 = blockIdx.x * 128;

    const __nv_bfloat16* qp_b = qp + (size_t)b * N_ * 64;
    const __nv_bfloat16* kp_b = kp + (size_t)b * N_ * 64;
    const __nv_bfloat16* vh_b = vhi + (size_t)b * C_ * N_;

    float* lsum_s = (float*)(sm + OFF_LSUM);
    if (t == 0) {
        MBARRIER_INIT(sb + 0, 1);  MBARRIER_INIT(sb + 8, 1);
        MBARRIER_INIT(sb + 16, 1); MBARRIER_INIT(sb + 24, 1);
    }
    if (t < 128) lsum_s[t] = 0.f;

    // Q (128x8 chunks) + K_0 (64x8 chunks) via cp.async
#pragma unroll
    for (int i = 0; i < 2; i++) {
        int idx = t + i * 512;
        int r = idx >> 3, ch = idx & 7;
        cpasync16(sb + OFF_Q + r * RS + ch * 16, qp_b + (size_t)(m0 + r) * 64 + ch * 8);
    }
    {
        int r = t >> 3, ch = t & 7;
        cpasync16(sb + OFF_K0 + r * RS + ch * 16, kp_b + (size_t)r * 64 + ch * 8);
    }
    CP_COMMIT();
    __syncthreads();   // mbarrier init + lsum visible

    // bulk: V_0 -> slot0 (mbV0), K_1 -> slot1 (mbK1)
    if (t == 0) { MBARRIER_EXPECT_TX(sb + 16, V_TX); MBARRIER_EXPECT_TX(sb + 8, K_TX); }
    if (t < 256) bulk128(sb + OFF_VH0 + t * RS, vh_b + (size_t)t * N_, sb + 16);
    if (t < 64)  bulk128(sb + OFF_K1 + t * RS, kp_b + (size_t)(64 + t) * 64, sb + 8);

    CP_WAIT0();
    __syncthreads();   // Q, K_0 resident for all warps

    float sacc[2][2][4];
    s_mma(sacc, sm, sm + OFF_K0, wm, wn, goff);  // S_0

    float oacc[2][8][4];
#pragma unroll
    for (int i = 0; i < 2; i++)
#pragma unroll
        for (int j = 0; j < 8; j++)
#pragma unroll
            for (int c = 0; c < 4; c++) oacc[i][j][c] = 0.f;
    float lpart[2][2] = {{0.f, 0.f}, {0.f, 0.f}};
    int vcnt0 = 0, vcnt1 = 0, kcnt0 = 0, kcnt1 = 0;

    __syncthreads();   // all warps done reading K_0 before iter-0 prefetch reuses slot0

    for (int i = 0; i < 64; i++) {
        const int cur = i & 1;
        // ---- a: prefetch V_{i+1} (slot (i+1)&1), K_{i+2} (slot i&1) ----
        if (i + 1 < 64) {
            const int s = (i + 1) & 1, nn = (i + 1) * 64;
            const uint32_t vdst = sb + (s ? OFF_VH1 : OFF_VH0);
            if (t == 0) MBARRIER_EXPECT_TX(sb + 16 + s * 8, V_TX);
            if (t < 256) bulk128(vdst + t * RS, vh_b + (size_t)t * N_ + nn, sb + 16 + s * 8);
        }
        if (i + 2 < 64) {
            const int s = i & 1, nn2 = (i + 2) * 64;
            const uint32_t kdst = sb + (s ? OFF_K1 : OFF_K0);
            if (t == 0) MBARRIER_EXPECT_TX(sb + s * 8, K_TX);
            if (t < 64) bulk128(kdst + t * RS, kp_b + (size_t)(nn2 + t) * 64, sb + s * 8);
        }

        // ---- b: softmax on sacc (S_i) -> PH/PL ----
#pragma unroll
        for (int mf = 0; mf < 2; mf++) {
            const int r0 = wm * 32 + mf * 16 + g;
#pragma unroll
            for (int nf = 0; nf < 2; nf++) {
                const int cb = wn * 16 + nf * 8 + 2 * tg;
                float p0 = __expf(fminf(sacc[mf][nf][0], 60.f));
                float p1 = __expf(fminf(sacc[mf][nf][1], 60.f));
                float p2 = __expf(fminf(sacc[mf][nf][2], 60.f));
                float p3 = __expf(fminf(sacc[mf][nf][3], 60.f));
                lpart[mf][0] += p0 + p1;
                lpart[mf][1] += p2 + p3;
                __nv_bfloat16 h0 = __float2bfloat16(p0), h1 = __float2bfloat16(p1);
                __nv_bfloat16 h2 = __float2bfloat16(p2), h3 = __float2bfloat16(p3);
                float l0 = p0 - __bfloat162float(h0), l1 = p1 - __bfloat162float(h1);
                float l2 = p2 - __bfloat162float(h2), l3 = p3 - __bfloat162float(h3);
                *(uint32_t*)(sm + OFF_PH + r0 * RS + cb * 2) =
                    (uint32_t)__bfloat16_as_ushort(h0) | ((uint32_t)__bfloat16_as_ushort(h1) << 16);
                *(uint32_t*)(sm + OFF_PH + (r0 + 8) * RS + cb * 2) =
                    (uint32_t)__bfloat16_as_ushort(h2) | ((uint32_t)__bfloat16_as_ushort(h3) << 16);
                *(uint32_t*)(sm + OFF_PL + r0 * RS + cb * 2) = pack_bf16x2(l0, l1);
                *(uint32_t*)(sm + OFF_PL + (r0 + 8) * RS + cb * 2) = pack_bf16x2(l2, l3);
            }
        }
        __syncthreads();     // c: P visible

        // ---- d: wait V_i, K_{i+1} ----
        if (cur == 0) { MBARRIER_WAIT_PARITY(sb + 16, vcnt0 & 1); vcnt0++; }
        else          { MBARRIER_WAIT_PARITY(sb + 24, vcnt1 & 1); vcnt1++; }
        if (i + 1 < 64) {
            if (((i + 1) & 1) == 0) { MBARRIER_WAIT_PARITY(sb + 0, kcnt0 & 1); kcnt0++; }
            else                    { MBARRIER_WAIT_PARITY(sb + 8, kcnt1 & 1); kcnt1++; }
        }

        const char* Vhp = sm + (cur ? OFF_VH1 : OFF_VH0);

        // ---- e: one MMA block: S_{i+1} then PV_i (2-term) ----
        if (i + 1 < 64)
            s_mma(sacc, sm, sm + (((i + 1) & 1) ? OFF_K1 : OFF_K0), wm, wn, goff);

#pragma unroll
        for (int kk = 0; kk < 4; kk++) {
            uint32_t aH[2][4], aL[2][4];
#pragma unroll
            for (int mf = 0; mf < 2; mf++) {
                ldA(aH[mf], sm + OFF_PH, wm * 32 + mf * 16, kk * 16, goff);
                ldA(aL[mf], sm + OFF_PL, wm * 32 + mf * 16, kk * 16, goff);
            }
#pragma unroll
            for (int nf = 0; nf < 8; nf++) {
                uint32_t bh[2];
                ldB(bh, Vhp, wn * 64 + nf * 8, kk * 16, goff);
#pragma unroll
                for (int mf = 0; mf < 2; mf++) {
                    mma16816(oacc[mf][nf], aH[mf], bh);
                    mma16816(oacc[mf][nf], aL[mf], bh);
                }
            }
        }
        __syncthreads();     // f: P/V/K slots free for next iteration
    }

    // ---- lsum reduction (exact fp32 denominators) ----
#pragma unroll
    for (int mf = 0; mf < 2; mf++) {
        atomicAdd(&lsum_s[wm * 32 + mf * 16 + g],     lpart[mf][0]);
        atomicAdd(&lsum_s[wm * 32 + mf * 16 + 8 + g], lpart[mf][1]);
    }
    __syncthreads();

    // ---- epilogue: O / lsum -> ao [b][m][c] ----
#pragma unroll
    for (int mf = 0; mf < 2; mf++) {
        const int rA = wm * 32 + mf * 16 + g;
        const int rB = rA + 8;
        const float invA = 1.f / lsum_s[rA];
        const float invB = 1.f / lsum_s[rB];
        float* baseA = ao + (size_t)(b * N_ + m0 + rA) * C_;
        float* baseB = ao + (size_t)(b * N_ + m0 + rB) * C_;
#pragma unroll
        for (int nf = 0; nf < 8; nf++) {
            const int cb = wn * 64 + nf * 8 + 2 * tg;
            *(float2*)(baseA + cb) = make_float2(oacc[mf][nf][0] * invA, oacc[mf][nf][1] * invA);
            *(float2*)(baseB + cb) = make_float2(oacc[mf][nf][2] * invB, oacc[mf][nf][3] * invB);
        }
    }
}

// ---------------------------------------------------------------------------
// Output projection + bias + residual (fp32)
// ---------------------------------------------------------------------------
__global__ __launch_bounds__(256)
void oproj_kernel(const float* __restrict__ AO,
                  const float* __restrict__ W,
                  const float* __restrict__ bias,
                  const float* __restrict__ x,
                  float* __restrict__ out)
{
    __shared__ float W_s[32][68];
    __shared__ float A_s[64][132];
    const int b  = blockIdx.z;
    const int o0 = blockIdx.y * 32;
    const int m0 = blockIdx.x * 128;
    const int t  = threadIdx.x;
    const int to = t >> 4, tn = t & 15;

    float acc[2][8];
#pragma unroll
    for (int i = 0; i < 2; i++)
#pragma unroll
        for (int j = 0; j < 8; j++) acc[i][j] = 0.f;

    for (int kt = 0; kt < C_; kt += 64) {
        __syncthreads();
#pragma unroll
        for (int it = 0; it < 2; it++) {
            int idx4 = t + it * 256;
            int o = idx4 >> 4, c4 = idx4 & 15;
            *(float4*)&W_s[o][c4 * 4] = *(const float4*)&W[(o0 + o) * C_ + kt + c4 * 4];
        }
#pragma unroll
        for (int it = 0; it < 8; it++) {
            int idx4 = t + it * 256;
            int m = idx4 >> 4, c4 = idx4 & 15;
            float4 a4 = *(const float4*)&AO[(size_t)(b * N_ + m0 + m) * C_ + kt + c4 * 4];
            A_s[c4 * 4 + 0][m] = a4.x;
            A_s[c4 * 4 + 1][m] = a4.y;
            A_s[c4 * 4 + 2][m] = a4.z;
            A_s[c4 * 4 + 3][m] = a4.w;
        }
        __syncthreads();
#pragma unroll 4
        for (int kc = 0; kc < 64; kc++) {
            float ar[8];
            *(float4*)&ar[0] = *(const float4*)&A_s[kc][tn * 8];
            *(float4*)&ar[4] = *(const float4*)&A_s[kc][tn * 8 + 4];
            float w0 = W_s[to * 2 + 0][kc];
            float w1 = W_s[to * 2 + 1][kc];
#pragma unroll
            for (int j = 0; j < 8; j++) { acc[0][j] += w0 * ar[j]; acc[1][j] += w1 * ar[j]; }
        }
    }

#pragma unroll
    for (int i = 0; i < 2; i++) {
        int o = o0 + to * 2 + i;
        float bv = bias[o];
        size_t base = (size_t)(b * C_ + o) * N_ + m0 + tn * 8;
        float4 x0 = *(const float4*)&x[base];
        float4 x1 = *(const float4*)&x[base + 4];
        *(float4*)&out[base] =
            make_float4(acc[i][0]+bv+x0.x, acc[i][1]+bv+x0.y, acc[i][2]+bv+x0.z, acc[i][3]+bv+x0.w);
        *(float4*)&out[base + 4] =
            make_float4(acc[i][4]+bv+x1.x, acc[i][5]+bv+x1.y, acc[i][6]+bv+x1.z, acc[i][7]+bv+x1.w);
    }
}

// ---------------------------------------------------------------------------
extern "C" void kernel_launch(void* const* d_in, const int* in_sizes, int n_in,
                              void* d_out, int out_size)
{
    const float* x  = (const float*)d_in[0];
    const float* wq = (const float*)d_in[1];
    const float* bq = (const float*)d_in[2];
    const float* wk = (const float*)d_in[3];
    const float* bk = (const float*)d_in[4];
    const float* wv = (const float*)d_in[5];
    const float* bv = (const float*)d_in[6];
    const float* wo = (const float*)d_in[7];
    const float* bo = (const float*)d_in[8];
    float* out = (float*)d_out;

    __nv_bfloat16 *gqp, *gkp, *gvh;
    float *gao;
    cudaGetSymbolAddress((void**)&gqp, g_qp);
    cudaGetSymbolAddress((void**)&gkp, g_kp);
    cudaGetSymbolAddress((void**)&gvh, g_vhi);
    cudaGetSymbolAddress((void**)&gao, g_ao);

    cudaFuncSetAttribute(attn_mma_kernel, cudaFuncAttributeMaxDynamicSharedMemorySize, ATTN_SMEM);

    dim3 blk(256);
    qk_pack_kernel<<<dim3(N_ / 128, 1, B_), blk>>>(x, wq, bq, gqp);
    qk_pack_kernel<<<dim3(N_ / 128, 1, B_), blk>>>(x, wk, bk, gkp);
    v_proj_kernel <<<dim3(N_ / 128, C_ / 32, B_), blk>>>(x, wv, bv, gvh);
    attn_mma_kernel<<<dim3(N_ / 128, B_), 512, ATTN_SMEM>>>(gqp, gkp, gvh, gao);
    oproj_kernel  <<<dim3(N_ / 128, C_ / 32, B_), blk>>>(gao, wo, bo, x, out);
}

// round 6
// speedup vs baseline: 2.7073x; 1.2489x over previous
#include <cuda_runtime.h>
#include <cuda_bf16.h>
#include <math.h>
#include <stdint.h>

#define B_ 4
#define C_ 256
#define N_ 4096
#define D_ 32

// ---------------------------------------------------------------------------
// PTX helpers (base sm_100-safe: mma.sync, ldmatrix, cp.async[.bulk], mbarrier)
// ---------------------------------------------------------------------------
__device__ __forceinline__ uint32_t smem_u32(const void* p) {
    uint32_t a;
    asm("{ .reg .u64 t; cvta.to.shared.u64 t, %1; cvt.u32.u64 %0, t; }" : "=r"(a) : "l"(p));
    return a;
}
#define MBARRIER_INIT(a, c) \
    asm volatile("mbarrier.init.shared.b64 [%0], %1;" :: "r"((uint32_t)(a)), "r"((uint32_t)(c)) : "memory")
#define MBARRIER_EXPECT_TX(a, n) \
    asm volatile("mbarrier.arrive.expect_tx.shared.b64 _, [%0], %1;" :: "r"((uint32_t)(a)), "r"((uint32_t)(n)) : "memory")
#define MBARRIER_WAIT_PARITY(a, ph) do { \
    uint32_t _m = (uint32_t)(a); uint32_t _p = (uint32_t)(ph); uint32_t _d; \
    asm volatile("{\n\t.reg .pred p;\n\tmbarrier.try_wait.parity.shared.b64 p, [%1], %2;\n\tselp.b32 %0,1,0,p;\n\t}" \
        : "=r"(_d) : "r"(_m), "r"(_p) : "memory"); \
    if (!_d) { \
        asm volatile("{\n\t.reg .pred P1;\n\tWL_%=:\n\tmbarrier.try_wait.parity.shared.b64 P1, [%0], %1;\n\t@P1 bra.uni WD_%=;\n\tbra.uni WL_%=;\n\tWD_%=:\n\t}" \
            :: "r"(_m), "r"(_p) : "memory"); \
    } } while (0)

__device__ __forceinline__ void cpasync16(uint32_t dst, const void* src) {
    asm volatile("cp.async.cg.shared.global [%0], [%1], 16;" :: "r"(dst), "l"(src) : "memory");
}
#define CP_COMMIT() asm volatile("cp.async.commit_group;" ::: "memory")
#define CP_WAIT(n)  asm volatile("cp.async.wait_group %0;" :: "n"(n) : "memory")

__device__ __forceinline__ void bulk128(uint32_t dst, const void* src, uint32_t mbar) {
    asm volatile("cp.async.bulk.shared::cta.global.mbarrier::complete_tx::bytes [%0], [%1], 128, [%2];"
                 :: "r"(dst), "l"(src), "r"(mbar) : "memory");
}

__device__ __forceinline__ void mma16816(float* d, const uint32_t* a, const uint32_t* b) {
    asm volatile("mma.sync.aligned.m16n8k16.row.col.f32.bf16.bf16.f32 "
                 "{%0,%1,%2,%3}, {%4,%5,%6,%7}, {%8,%9}, {%0,%1,%2,%3};"
                 : "+f"(d[0]), "+f"(d[1]), "+f"(d[2]), "+f"(d[3])
                 : "r"(a[0]), "r"(a[1]), "r"(a[2]), "r"(a[3]), "r"(b[0]), "r"(b[1]));
}
__device__ __forceinline__ void ldsm4(uint32_t* r, uint32_t addr) {
    asm volatile("ldmatrix.sync.aligned.m8n8.x4.shared.b16 {%0,%1,%2,%3}, [%4];"
                 : "=r"(r[0]), "=r"(r[1]), "=r"(r[2]), "=r"(r[3]) : "r"(addr));
}
__device__ __forceinline__ uint32_t pack_bf16x2(float x, float y) {
    __nv_bfloat162 h = __floats2bfloat162_rn(x, y);
    return *(uint32_t*)&h;
}

#define RS 144
// per-lane ldmatrix address offsets (bytes) for the 144B-stride layout
// A-frag (m16k16): tiles rows R..R+15, col c / c+8
// B-frag (2x n8k16): tiles (Rn,c),(Rn,c+8),(Rn+8,c),(Rn+8,c+8)
__device__ __forceinline__ int aoffA(int lane) { return (lane & 15) * RS + (lane >> 4) * 16; }
__device__ __forceinline__ int aoffB(int lane) { return ((lane & 7) + ((lane >> 4) << 3)) * RS + (lane & 8) * 2; }

// ---------------------------------------------------------------------------
// Scratch
// ---------------------------------------------------------------------------
__device__ __nv_bfloat16 g_qp  [B_*N_*64];   // [b][n][qh(32)|ql(32)]
__device__ __nv_bfloat16 g_kp  [B_*N_*64];
__device__ __nv_bfloat16 g_vhi [B_*C_*N_];   // [b][c][n]
__device__ __nv_bfloat16 g_aohi[B_*N_*C_];   // [b][n][c]
__device__ __nv_bfloat16 g_aolo[B_*N_*C_];
__device__ __nv_bfloat16 g_wohi[C_*C_];
__device__ __nv_bfloat16 g_wolo[C_*C_];

// ---------------------------------------------------------------------------
// wo -> hi/lo bf16
// ---------------------------------------------------------------------------
__global__ void wprep_kernel(const float* __restrict__ wo,
                             __nv_bfloat16* __restrict__ whi, __nv_bfloat16* __restrict__ wlo)
{
    int i = blockIdx.x * 256 + threadIdx.x;
    float f = wo[i];
    __nv_bfloat16 h = __float2bfloat16(f);
    whi[i] = h;
    wlo[i] = __float2bfloat16(f - __bfloat162float(h));
}

// ---------------------------------------------------------------------------
// fused Q+K projection -> packed hi|lo bf16 rows (O=32); blockIdx.y: 0=q 1=k
// ---------------------------------------------------------------------------
__global__ __launch_bounds__(256)
void qk2_pack_kernel(const float* __restrict__ X,
                     const float* __restrict__ Wq, const float* __restrict__ Bq,
                     const float* __restrict__ Wk, const float* __restrict__ Bk,
                     __nv_bfloat16* __restrict__ outq, __nv_bfloat16* __restrict__ outk)
{
    __shared__ float W_s[32][68];
    __shared__ float X_s[64][132];
    const int b  = blockIdx.z;
    const int n0 = blockIdx.x * 128;
    const float* W = blockIdx.y ? Wk : Wq;
    const float* bias = blockIdx.y ? Bk : Bq;
    __nv_bfloat16* outp = blockIdx.y ? outk : outq;
    const int t  = threadIdx.x;
    const int to = t >> 4, tn = t & 15;
    const float* Xb = X + b * (C_ * N_);

    float acc[2][8];
#pragma unroll
    for (int i = 0; i < 2; i++)
#pragma unroll
        for (int j = 0; j < 8; j++) acc[i][j] = 0.f;

    for (int kt = 0; kt < C_; kt += 64) {
        __syncthreads();
#pragma unroll
        for (int it = 0; it < 2; it++) {
            int idx4 = t + it * 256;
            int o = idx4 >> 4, c4 = idx4 & 15;
            *(float4*)&W_s[o][c4 * 4] = *(const float4*)&W[o * C_ + kt + c4 * 4];
        }
#pragma unroll
        for (int it = 0; it < 8; it++) {
            int idx4 = t + it * 256;
            int kc = idx4 >> 5, n4 = idx4 & 31;
            *(float4*)&X_s[kc][n4 * 4] = *(const float4*)&Xb[(kt + kc) * N_ + n0 + n4 * 4];
        }
        __syncthreads();
#pragma unroll 4
        for (int kc = 0; kc < 64; kc++) {
            float xr[8];
            *(float4*)&xr[0] = *(const float4*)&X_s[kc][tn * 8];
            *(float4*)&xr[4] = *(const float4*)&X_s[kc][tn * 8 + 4];
            float w0 = W_s[to * 2 + 0][kc];
            float w1 = W_s[to * 2 + 1][kc];
#pragma unroll
            for (int j = 0; j < 8; j++) { acc[0][j] += w0 * xr[j]; acc[1][j] += w1 * xr[j]; }
        }
    }
    __syncthreads();
#pragma unroll
    for (int i = 0; i < 2; i++) {
        float bv = bias[to * 2 + i];
#pragma unroll
        for (int j = 0; j < 8; j++) X_s[to * 2 + i][tn * 8 + j] = acc[i][j] + bv;
    }
    __syncthreads();
#pragma unroll
    for (int it = 0; it < 8; it++) {
        int idx = t + it * 256;
        int n = idx >> 4, g = idx & 15;
        unsigned short us[4];
#pragma unroll
        for (int e = 0; e < 4; e++) {
            int col = g * 4 + e;
            if (col < 32) {
                us[e] = __bfloat16_as_ushort(__float2bfloat16(X_s[col][n]));
            } else {
                float f = X_s[col - 32][n];
                __nv_bfloat16 h = __float2bfloat16(f);
                us[e] = __bfloat16_as_ushort(__float2bfloat16(f - __bfloat162float(h)));
            }
        }
        *(uint2*)&outp[(size_t)(b * N_ + n0 + n) * 64 + g * 4] = *(uint2*)us;
    }
}

// ---------------------------------------------------------------------------
// V projection -> v_hi bf16 [b][c][n]
// ---------------------------------------------------------------------------
__global__ __launch_bounds__(256)
void v_proj_kernel(const float* __restrict__ X, const float* __restrict__ W,
                   const float* __restrict__ bias, __nv_bfloat16* __restrict__ vhi)
{
    __shared__ float W_s[32][68];
    __shared__ float X_s[64][132];
    const int b  = blockIdx.z;
    const int o0 = blockIdx.y * 32;
    const int n0 = blockIdx.x * 128;
    const int t  = threadIdx.x;
    const int to = t >> 4, tn = t & 15;
    const float* Xb = X + b * (C_ * N_);

    float acc[2][8];
#pragma unroll
    for (int i = 0; i < 2; i++)
#pragma unroll
        for (int j = 0; j < 8; j++) acc[i][j] = 0.f;

    for (int kt = 0; kt < C_; kt += 64) {
        __syncthreads();
#pragma unroll
        for (int it = 0; it < 2; it++) {
            int idx4 = t + it * 256;
            int o = idx4 >> 4, c4 = idx4 & 15;
            *(float4*)&W_s[o][c4 * 4] = *(const float4*)&W[(o0 + o) * C_ + kt + c4 * 4];
        }
#pragma unroll
        for (int it = 0; it < 8; it++) {
            int idx4 = t + it * 256;
            int kc = idx4 >> 5, n4 = idx4 & 31;
            *(float4*)&X_s[kc][n4 * 4] = *(const float4*)&Xb[(kt + kc) * N_ + n0 + n4 * 4];
        }
        __syncthreads();
#pragma unroll 4
        for (int kc = 0; kc < 64; kc++) {
            float xr[8];
            *(float4*)&xr[0] = *(const float4*)&X_s[kc][tn * 8];
            *(float4*)&xr[4] = *(const float4*)&X_s[kc][tn * 8 + 4];
            float w0 = W_s[to * 2 + 0][kc];
            float w1 = W_s[to * 2 + 1][kc];
#pragma unroll
            for (int j = 0; j < 8; j++) { acc[0][j] += w0 * xr[j]; acc[1][j] += w1 * xr[j]; }
        }
    }
#pragma unroll
    for (int i = 0; i < 2; i++) {
        int o = o0 + to * 2 + i;
        float bv = bias[o];
        unsigned short hs[8];
#pragma unroll
        for (int j = 0; j < 8; j++)
            hs[j] = __bfloat16_as_ushort(__float2bfloat16(acc[i][j] + bv));
        *(uint4*)&vhi[(size_t)(b * C_ + o) * N_ + n0 + tn * 8] = *(uint4*)hs;
    }
}

// ---------------------------------------------------------------------------
// Pipelined mma.sync flash attention (ldmatrix edition).
// 512 threads, M=128 q/CTA, 64-key tiles, Q-hi frags resident in registers.
// ---------------------------------------------------------------------------
#define OFF_LSUM 32
#define OFF_Q    1024
#define OFF_K0   19456
#define OFF_K1   28672
#define OFF_PH   37888
#define OFF_PL   56320
#define OFF_VH0  74752
#define OFF_VH1  111616
#define ATTN_SMEM 148480
#define K_TX 8192
#define V_TX 32768

__global__ __launch_bounds__(512, 1)
void attn_mma_kernel(const __nv_bfloat16* __restrict__ qp,
                     const __nv_bfloat16* __restrict__ kp,
                     const __nv_bfloat16* __restrict__ vhi,
                     __nv_bfloat16* __restrict__ aohi,
                     __nv_bfloat16* __restrict__ aolo)
{
    extern __shared__ char sm[];
    const uint32_t sb = smem_u32(sm);
    const int t = threadIdx.x;
    const int wid = t >> 5, lane = t & 31;
    const int g = lane >> 2, tg = lane & 3;
    const int oA = aoffA(lane), oB = aoffB(lane);
    const int wm = wid >> 2, wn = wid & 3;
    const int b = blockIdx.y, m0 = blockIdx.x * 128;

    const __nv_bfloat16* qp_b = qp + (size_t)b * N_ * 64;
    const __nv_bfloat16* kp_b = kp + (size_t)b * N_ * 64;
    const __nv_bfloat16* vh_b = vhi + (size_t)b * C_ * N_;

    float* lsum_s = (float*)(sm + OFF_LSUM);
    if (t == 0) {
        MBARRIER_INIT(sb + 0, 1);  MBARRIER_INIT(sb + 8, 1);
        MBARRIER_INIT(sb + 16, 1); MBARRIER_INIT(sb + 24, 1);
    }
    if (t < 128) lsum_s[t] = 0.f;

#pragma unroll
    for (int i = 0; i < 2; i++) {
        int idx = t + i * 512;
        int r = idx >> 3, ch = idx & 7;
        cpasync16(sb + OFF_Q + r * RS + ch * 16, qp_b + (size_t)(m0 + r) * 64 + ch * 8);
    }
    {
        int r = t >> 3, ch = t & 7;
        cpasync16(sb + OFF_K0 + r * RS + ch * 16, kp_b + (size_t)r * 64 + ch * 8);
    }
    CP_COMMIT();
    __syncthreads();

    if (t == 0) { MBARRIER_EXPECT_TX(sb + 16, V_TX); MBARRIER_EXPECT_TX(sb + 8, K_TX); }
    if (t < 256) bulk128(sb + OFF_VH0 + t * RS, vh_b + (size_t)t * N_, sb + 16);
    if (t < 64)  bulk128(sb + OFF_K1 + t * RS, kp_b + (size_t)(64 + t) * 64, sb + 8);

    CP_WAIT(0);
    __syncthreads();

    // Q-hi fragments (cols 0,16) resident forever
    uint32_t qfh[2][2][4];
#pragma unroll
    for (int mf = 0; mf < 2; mf++)
#pragma unroll
        for (int c = 0; c < 2; c++)
            ldsm4(qfh[mf][c], sb + OFF_Q + (wm * 32 + mf * 16) * RS + c * 32 + oA);

    const uint32_t sbPH = sb + OFF_PH, sbPL = sb + OFF_PL, sbQ = sb + OFF_Q;
    const int rowA = wm * 32;   // warp's A-row base
    const int rowB = wn * 16;   // warp's K-row base (S phase)

    // S_0
    float sacc[2][2][4];
    {
#pragma unroll
        for (int i = 0; i < 2; i++)
#pragma unroll
            for (int j = 0; j < 2; j++)
#pragma unroll
                for (int c = 0; c < 4; c++) sacc[i][j][c] = 0.f;
        const uint32_t Kb = sb + OFF_K0 + rowB * RS + oB;
        uint32_t bK[4];
        ldsm4(bK, Kb + 0);                               // k-col 0
#pragma unroll
        for (int mf = 0; mf < 2; mf++) { mma16816(sacc[mf][0], qfh[mf][0], &bK[0]); mma16816(sacc[mf][1], qfh[mf][0], &bK[2]); }
        {
            uint32_t ql[4];
#pragma unroll
            for (int mf = 0; mf < 2; mf++) {
                ldsm4(ql, sbQ + (rowA + mf * 16) * RS + 64 + oA);   // q-lo col 32
                mma16816(sacc[mf][0], ql, &bK[0]); mma16816(sacc[mf][1], ql, &bK[2]);
            }
        }
        ldsm4(bK, Kb + 32);                              // k-col 16
#pragma unroll
        for (int mf = 0; mf < 2; mf++) { mma16816(sacc[mf][0], qfh[mf][1], &bK[0]); mma16816(sacc[mf][1], qfh[mf][1], &bK[2]); }
        {
            uint32_t ql[4];
#pragma unroll
            for (int mf = 0; mf < 2; mf++) {
                ldsm4(ql, sbQ + (rowA + mf * 16) * RS + 96 + oA);   // q-lo col 48
                mma16816(sacc[mf][0], ql, &bK[0]); mma16816(sacc[mf][1], ql, &bK[2]);
            }
        }
        ldsm4(bK, Kb + 64);                              // k-lo col 32
#pragma unroll
        for (int mf = 0; mf < 2; mf++) { mma16816(sacc[mf][0], qfh[mf][0], &bK[0]); mma16816(sacc[mf][1], qfh[mf][0], &bK[2]); }
        ldsm4(bK, Kb + 96);                              // k-lo col 48
#pragma unroll
        for (int mf = 0; mf < 2; mf++) { mma16816(sacc[mf][0], qfh[mf][1], &bK[0]); mma16816(sacc[mf][1], qfh[mf][1], &bK[2]); }
    }

    float oacc[2][8][4];
#pragma unroll
    for (int i = 0; i < 2; i++)
#pragma unroll
        for (int j = 0; j < 8; j++)
#pragma unroll
            for (int c = 0; c < 4; c++) oacc[i][j][c] = 0.f;
    float lpart[2][2] = {{0.f, 0.f}, {0.f, 0.f}};
    int vcnt0 = 0, vcnt1 = 0, kcnt0 = 0, kcnt1 = 0;

    __syncthreads();

    for (int i = 0; i < 64; i++) {
        const int cur = i & 1;
        if (i + 1 < 64) {
            const int s = (i + 1) & 1, nn = (i + 1) * 64;
            const uint32_t vdst = sb + (s ? OFF_VH1 : OFF_VH0);
            if (t == 0) MBARRIER_EXPECT_TX(sb + 16 + s * 8, V_TX);
            if (t < 256) bulk128(vdst + t * RS, vh_b + (size_t)t * N_ + nn, sb + 16 + s * 8);
        }
        if (i + 2 < 64) {
            const int s = i & 1, nn2 = (i + 2) * 64;
            const uint32_t kdst = sb + (s ? OFF_K1 : OFF_K0);
            if (t == 0) MBARRIER_EXPECT_TX(sb + s * 8, K_TX);
            if (t < 64) bulk128(kdst + t * RS, kp_b + (size_t)(nn2 + t) * 64, sb + s * 8);
        }

        // softmax(S_i) -> PH/PL
#pragma unroll
        for (int mf = 0; mf < 2; mf++) {
            const int r0 = rowA + mf * 16 + g;
#pragma unroll
            for (int nf = 0; nf < 2; nf++) {
                const int cb = rowB + nf * 8 + 2 * tg;
                float p0 = __expf(fminf(sacc[mf][nf][0], 60.f));
                float p1 = __expf(fminf(sacc[mf][nf][1], 60.f));
                float p2 = __expf(fminf(sacc[mf][nf][2], 60.f));
                float p3 = __expf(fminf(sacc[mf][nf][3], 60.f));
                lpart[mf][0] += p0 + p1;
                lpart[mf][1] += p2 + p3;
                uint32_t hA = pack_bf16x2(p0, p1);
                uint32_t hB = pack_bf16x2(p2, p3);
                __nv_bfloat162 hv0 = *(__nv_bfloat162*)&hA;
                __nv_bfloat162 hv1 = *(__nv_bfloat162*)&hB;
                *(uint32_t*)(sm + OFF_PH + r0 * RS + cb * 2) = hA;
                *(uint32_t*)(sm + OFF_PH + (r0 + 8) * RS + cb * 2) = hB;
                *(uint32_t*)(sm + OFF_PL + r0 * RS + cb * 2) =
                    pack_bf16x2(p0 - __bfloat162float(hv0.x), p1 - __bfloat162float(hv0.y));
                *(uint32_t*)(sm + OFF_PL + (r0 + 8) * RS + cb * 2) =
                    pack_bf16x2(p2 - __bfloat162float(hv1.x), p3 - __bfloat162float(hv1.y));
            }
        }
        __syncthreads();

        if (cur == 0) { MBARRIER_WAIT_PARITY(sb + 16, vcnt0 & 1); vcnt0++; }
        else          { MBARRIER_WAIT_PARITY(sb + 24, vcnt1 & 1); vcnt1++; }
        if (i + 1 < 64) {
            if (((i + 1) & 1) == 0) { MBARRIER_WAIT_PARITY(sb + 0, kcnt0 & 1); kcnt0++; }
            else                    { MBARRIER_WAIT_PARITY(sb + 8, kcnt1 & 1); kcnt1++; }
        }

        const uint32_t Vb = sb + (cur ? OFF_VH1 : OFF_VH0);

        // S_{i+1}
        if (i + 1 < 64) {
            const uint32_t Kb = sb + (((i + 1) & 1) ? OFF_K1 : OFF_K0) + rowB * RS + oB;
#pragma unroll
            for (int a = 0; a < 2; a++)
#pragma unroll
                for (int j2 = 0; j2 < 2; j2++)
#pragma unroll
                    for (int c = 0; c < 4; c++) sacc[a][j2][c] = 0.f;
            uint32_t bK[4];
            ldsm4(bK, Kb + 0);
#pragma unroll
            for (int mf = 0; mf < 2; mf++) { mma16816(sacc[mf][0], qfh[mf][0], &bK[0]); mma16816(sacc[mf][1], qfh[mf][0], &bK[2]); }
            {
                uint32_t ql[4];
#pragma unroll
                for (int mf = 0; mf < 2; mf++) {
                    ldsm4(ql, sbQ + (rowA + mf * 16) * RS + 64 + oA);
                    mma16816(sacc[mf][0], ql, &bK[0]); mma16816(sacc[mf][1], ql, &bK[2]);
                }
            }
            ldsm4(bK, Kb + 32);
#pragma unroll
            for (int mf = 0; mf < 2; mf++) { mma16816(sacc[mf][0], qfh[mf][1], &bK[0]); mma16816(sacc[mf][1], qfh[mf][1], &bK[2]); }
            {
                uint32_t ql[4];
#pragma unroll
                for (int mf = 0; mf < 2; mf++) {
                    ldsm4(ql, sbQ + (rowA + mf * 16) * RS + 96 + oA);
                    mma16816(sacc[mf][0], ql, &bK[0]); mma16816(sacc[mf][1], ql, &bK[2]);
                }
            }
            ldsm4(bK, Kb + 64);
#pragma unroll
            for (int mf = 0; mf < 2; mf++) { mma16816(sacc[mf][0], qfh[mf][0], &bK[0]); mma16816(sacc[mf][1], qfh[mf][0], &bK[2]); }
            ldsm4(bK, Kb + 96);
#pragma unroll
            for (int mf = 0; mf < 2; mf++) { mma16816(sacc[mf][0], qfh[mf][1], &bK[0]); mma16816(sacc[mf][1], qfh[mf][1], &bK[2]); }
        }

        // PV_i (2-term)
#pragma unroll
        for (int kk = 0; kk < 4; kk++) {
            uint32_t aH[2][4], aL[2][4];
#pragma unroll
            for (int mf = 0; mf < 2; mf++) {
                ldsm4(aH[mf], sbPH + (rowA + mf * 16) * RS + kk * 32 + oA);
                ldsm4(aL[mf], sbPL + (rowA + mf * 16) * RS + kk * 32 + oA);
            }
#pragma unroll
            for (int j = 0; j < 4; j++) {
                uint32_t bV[4];
                ldsm4(bV, Vb + (wn * 64 + j * 16) * RS + kk * 32 + oB);
#pragma unroll
                for (int mf = 0; mf < 2; mf++) {
                    mma16816(oacc[mf][2 * j],     aH[mf], &bV[0]);
                    mma16816(oacc[mf][2 * j],     aL[mf], &bV[0]);
                    mma16816(oacc[mf][2 * j + 1], aH[mf], &bV[2]);
                    mma16816(oacc[mf][2 * j + 1], aL[mf], &bV[2]);
                }
            }
        }
        __syncthreads();
    }

#pragma unroll
    for (int mf = 0; mf < 2; mf++) {
        atomicAdd(&lsum_s[rowA + mf * 16 + g],     lpart[mf][0]);
        atomicAdd(&lsum_s[rowA + mf * 16 + 8 + g], lpart[mf][1]);
    }
    __syncthreads();

    // epilogue: O/lsum -> bf16 hi/lo AO
#pragma unroll
    for (int mf = 0; mf < 2; mf++) {
        const int rA = rowA + mf * 16 + g;
        const int rB = rA + 8;
        const float invA = 1.f / lsum_s[rA];
        const float invB = 1.f / lsum_s[rB];
        __nv_bfloat16* hA = aohi + (size_t)(b * N_ + m0 + rA) * C_;
        __nv_bfloat16* hB = aohi + (size_t)(b * N_ + m0 + rB) * C_;
        __nv_bfloat16* lA = aolo + (size_t)(b * N_ + m0 + rA) * C_;
        __nv_bfloat16* lB = aolo + (size_t)(b * N_ + m0 + rB) * C_;
#pragma unroll
        for (int nf = 0; nf < 8; nf++) {
            const int cb = wn * 64 + nf * 8 + 2 * tg;
            float a0 = oacc[mf][nf][0] * invA, a1 = oacc[mf][nf][1] * invA;
            float b0v = oacc[mf][nf][2] * invB, b1v = oacc[mf][nf][3] * invB;
            uint32_t ha = pack_bf16x2(a0, a1);
            uint32_t hb = pack_bf16x2(b0v, b1v);
            __nv_bfloat162 va = *(__nv_bfloat162*)&ha;
            __nv_bfloat162 vb = *(__nv_bfloat162*)&hb;
            *(uint32_t*)(hA + cb) = ha;
            *(uint32_t*)(hB + cb) = hb;
            *(uint32_t*)(lA + cb) = pack_bf16x2(a0 - __bfloat162float(va.x), a1 - __bfloat162float(va.y));
            *(uint32_t*)(lB + cb) = pack_bf16x2(b0v - __bfloat162float(vb.x), b1v - __bfloat162float(vb.y));
        }
    }
}

// ---------------------------------------------------------------------------
// Output projection via split-bf16 mma.sync: out = wo*AO + bo + x
// CTA: 128 o x 128 m, K=256 in 4 stages of 64, double-buffered cp.async.
// ---------------------------------------------------------------------------
#define OP_WH 0
#define OP_WL 18432
#define OP_AH 36864
#define OP_AL 55296
#define OP_BUF 73728
#define OPROJ_SMEM 147456

__global__ __launch_bounds__(512, 1)
void oproj_mma_kernel(const __nv_bfloat16* __restrict__ aohi,
                      const __nv_bfloat16* __restrict__ aolo,
                      const __nv_bfloat16* __restrict__ whi,
                      const __nv_bfloat16* __restrict__ wlo,
                      const float* __restrict__ bo,
                      const float* __restrict__ x,
                      float* __restrict__ out)
{
    extern __shared__ char sm[];
    const uint32_t sb = smem_u32(sm);
    const int t = threadIdx.x;
    const int wid = t >> 5, lane = t & 31;
    const int g = lane >> 2, tg = lane & 3;
    const int oA = aoffA(lane), oB = aoffB(lane);
    const int wm = wid >> 2, wn = wid & 3;
    const int b = blockIdx.z, o0 = blockIdx.y * 128, m0 = blockIdx.x * 128;

    const int r = (t >> 3) & 127;          // row within tile for loads
    const int ch = t & 7;                  // 16B chunk
    const int arr_hi = t >> 10;            // unused; loads below use explicit loop

    float oac[2][4][4];
#pragma unroll
    for (int i = 0; i < 2; i++)
#pragma unroll
        for (int j = 0; j < 4; j++)
#pragma unroll
            for (int c = 0; c < 4; c++) oac[i][j][c] = 0.f;

    // stage loader: 4096 16B chunks (4 arrays x 128 rows x 8)
    auto load_stage = [&](int kt, int buf) {
        const uint32_t base = sb + buf * OP_BUF;
#pragma unroll
        for (int it = 0; it < 8; it++) {
            int idx = t + it * 512;
            int arr = idx >> 10, rr = (idx >> 3) & 127, cc = idx & 7;
            uint32_t dst = base + arr * 18432 + rr * RS + cc * 16;
            const __nv_bfloat16* src;
            if (arr == 0)      src = whi + (size_t)(o0 + rr) * C_ + kt + cc * 8;
            else if (arr == 1) src = wlo + (size_t)(o0 + rr) * C_ + kt + cc * 8;
            else if (arr == 2) src = aohi + (size_t)(b * N_ + m0 + rr) * C_ + kt + cc * 8;
            else               src = aolo + (size_t)(b * N_ + m0 + rr) * C_ + kt + cc * 8;
            cpasync16(dst, src);
        }
        CP_COMMIT();
    };

    load_stage(0, 0);
    for (int s = 0; s < 4; s++) {
        if (s + 1 < 4) { load_stage((s + 1) * 64, (s + 1) & 1); CP_WAIT(1); }
        else CP_WAIT(0);
        __syncthreads();
        const uint32_t base = sb + (s & 1) * OP_BUF;
        const uint32_t Wh = base + OP_WH + (wm * 32) * RS + oA;
        const uint32_t Wl = base + OP_WL + (wm * 32) * RS + oA;
        const uint32_t Ah = base + OP_AH + (wn * 32) * RS + oB;
        const uint32_t Al = base + OP_AL + (wn * 32) * RS + oB;
#pragma unroll
        for (int ks = 0; ks < 4; ks++) {
            uint32_t awh[2][4], awl[2][4];
#pragma unroll
            for (int mf = 0; mf < 2; mf++) {
                ldsm4(awh[mf], Wh + mf * 16 * RS + ks * 32);
                ldsm4(awl[mf], Wl + mf * 16 * RS + ks * 32);
            }
#pragma unroll
            for (int j = 0; j < 2; j++) {
                uint32_t bh[4], bl[4];
                ldsm4(bh, Ah + j * 16 * RS + ks * 32);
                ldsm4(bl, Al + j * 16 * RS + ks * 32);
#pragma unroll
                for (int h = 0; h < 2; h++) {
                    const int nf = 2 * j + h;
#pragma unroll
                    for (int mf = 0; mf < 2; mf++) {
                        mma16816(oac[mf][nf], awh[mf], &bh[2 * h]);
                        mma16816(oac[mf][nf], awl[mf], &bh[2 * h]);
                        mma16816(oac[mf][nf], awh[mf], &bl[2 * h]);
                    }
                }
            }
        }
        __syncthreads();
    }

    // epilogue: + bo + x -> out [b][o][m]
#pragma unroll
    for (int mf = 0; mf < 2; mf++) {
        const int rA = o0 + wm * 32 + mf * 16 + g;
        const int rB = rA + 8;
        const float bvA = bo[rA], bvB = bo[rB];
#pragma unroll
        for (int nf = 0; nf < 4; nf++) {
            const int m = m0 + wn * 32 + nf * 8 + 2 * tg;
            size_t iA = (size_t)(b * C_ + rA) * N_ + m;
            size_t iB = (size_t)(b * C_ + rB) * N_ + m;
            float2 xA = *(const float2*)&x[iA];
            float2 xB = *(const float2*)&x[iB];
            *(float2*)&out[iA] = make_float2(oac[mf][nf][0] + bvA + xA.x, oac[mf][nf][1] + bvA + xA.y);
            *(float2*)&out[iB] = make_float2(oac[mf][nf][2] + bvB + xB.x, oac[mf][nf][3] + bvB + xB.y);
        }
    }
}

// ---------------------------------------------------------------------------
extern "C" void kernel_launch(void* const* d_in, const int* in_sizes, int n_in,
                              void* d_out, int out_size)
{
    const float* x  = (const float*)d_in[0];
    const float* wq = (const float*)d_in[1];
    const float* bq = (const float*)d_in[2];
    const float* wk = (const float*)d_in[3];
    const float* bk = (const float*)d_in[4];
    const float* wv = (const float*)d_in[5];
    const float* bv = (const float*)d_in[6];
    const float* wo = (const float*)d_in[7];
    const float* bo = (const float*)d_in[8];
    float* out = (float*)d_out;

    __nv_bfloat16 *gqp, *gkp, *gvh, *gaoh, *gaol, *gwh, *gwl;
    cudaGetSymbolAddress((void**)&gqp,  g_qp);
    cudaGetSymbolAddress((void**)&gkp,  g_kp);
    cudaGetSymbolAddress((void**)&gvh,  g_vhi);
    cudaGetSymbolAddress((void**)&gaoh, g_aohi);
    cudaGetSymbolAddress((void**)&gaol, g_aolo);
    cudaGetSymbolAddress((void**)&gwh,  g_wohi);
    cudaGetSymbolAddress((void**)&gwl,  g_wolo);

    cudaFuncSetAttribute(attn_mma_kernel, cudaFuncAttributeMaxDynamicSharedMemorySize, ATTN_SMEM);
    cudaFuncSetAttribute(oproj_mma_kernel, cudaFuncAttributeMaxDynamicSharedMemorySize, OPROJ_SMEM);

    dim3 blk(256);
    wprep_kernel   <<<C_, C_>>>(wo, gwh, gwl);
    qk2_pack_kernel<<<dim3(N_ / 128, 2, B_), blk>>>(x, wq, bq, wk, bk, gqp, gkp);
    v_proj_kernel  <<<dim3(N_ / 128, C_ / 32, B_), blk>>>(x, wv, bv, gvh);
    attn_mma_kernel<<<dim3(N_ / 128, B_), 512, ATTN_SMEM>>>(gqp, gkp, gvh, gaoh, gaol);
    oproj_mma_kernel<<<dim3(N_ / 128, C_ / 128, B_), 512, OPROJ_SMEM>>>(gaoh, gaol, gwh, gwl, bo, x, out);
}

// round 7
// speedup vs baseline: 2.7947x; 1.0323x over previous
#include <cuda_runtime.h>
#include <cuda_bf16.h>
#include <math.h>
#include <stdint.h>

#define B_ 4
#define C_ 256
#define N_ 4096
#define D_ 32

// ---------------------------------------------------------------------------
// PTX helpers (base sm_100-safe: mma.sync, ldmatrix, cp.async[.bulk], mbarrier)
// ---------------------------------------------------------------------------
__device__ __forceinline__ uint32_t smem_u32(const void* p) {
    uint32_t a;
    asm("{ .reg .u64 t; cvta.to.shared.u64 t, %1; cvt.u32.u64 %0, t; }" : "=r"(a) : "l"(p));
    return a;
}
#define MBARRIER_INIT(a, c) \
    asm volatile("mbarrier.init.shared.b64 [%0], %1;" :: "r"((uint32_t)(a)), "r"((uint32_t)(c)) : "memory")
#define MBARRIER_EXPECT_TX(a, n) \
    asm volatile("mbarrier.arrive.expect_tx.shared.b64 _, [%0], %1;" :: "r"((uint32_t)(a)), "r"((uint32_t)(n)) : "memory")
#define MBARRIER_ARRIVE(a) \
    asm volatile("mbarrier.arrive.shared.b64 _, [%0];" :: "r"((uint32_t)(a)) : "memory")
#define MBARRIER_WAIT_PARITY(a, ph) do { \
    uint32_t _m = (uint32_t)(a); uint32_t _p = (uint32_t)(ph); uint32_t _d; \
    asm volatile("{\n\t.reg .pred p;\n\tmbarrier.try_wait.parity.shared.b64 p, [%1], %2;\n\tselp.b32 %0,1,0,p;\n\t}" \
        : "=r"(_d) : "r"(_m), "r"(_p) : "memory"); \
    if (!_d) { \
        asm volatile("{\n\t.reg .pred P1;\n\tWL_%=:\n\tmbarrier.try_wait.parity.shared.b64 P1, [%0], %1;\n\t@P1 bra.uni WD_%=;\n\tbra.uni WL_%=;\n\tWD_%=:\n\t}" \
            :: "r"(_m), "r"(_p) : "memory"); \
    } } while (0)
#define NBAR(id) asm volatile("bar.sync %0, 256;" :: "r"(id) : "memory")

__device__ __forceinline__ void cpasync16(uint32_t dst, const void* src) {
    asm volatile("cp.async.cg.shared.global [%0], [%1], 16;" :: "r"(dst), "l"(src) : "memory");
}
#define CP_COMMIT() asm volatile("cp.async.commit_group;" ::: "memory")
#define CP_WAIT(n)  asm volatile("cp.async.wait_group %0;" :: "n"(n) : "memory")

__device__ __forceinline__ void bulk128(uint32_t dst, const void* src, uint32_t mbar) {
    asm volatile("cp.async.bulk.shared::cta.global.mbarrier::complete_tx::bytes [%0], [%1], 128, [%2];"
                 :: "r"(dst), "l"(src), "r"(mbar) : "memory");
}

__device__ __forceinline__ void mma16816(float* d, const uint32_t* a, const uint32_t* b) {
    asm volatile("mma.sync.aligned.m16n8k16.row.col.f32.bf16.bf16.f32 "
                 "{%0,%1,%2,%3}, {%4,%5,%6,%7}, {%8,%9}, {%0,%1,%2,%3};"
                 : "+f"(d[0]), "+f"(d[1]), "+f"(d[2]), "+f"(d[3])
                 : "r"(a[0]), "r"(a[1]), "r"(a[2]), "r"(a[3]), "r"(b[0]), "r"(b[1]));
}
__device__ __forceinline__ void ldsm4(uint32_t* r, uint32_t addr) {
    asm volatile("ldmatrix.sync.aligned.m8n8.x4.shared.b16 {%0,%1,%2,%3}, [%4];"
                 : "=r"(r[0]), "=r"(r[1]), "=r"(r[2]), "=r"(r[3]) : "r"(addr));
}
__device__ __forceinline__ uint32_t pack_bf16x2(float x, float y) {
    __nv_bfloat162 h = __floats2bfloat162_rn(x, y);
    return *(uint32_t*)&h;
}

#define RS 144
__device__ __forceinline__ int aoffA(int lane) { return (lane & 15) * RS + (lane >> 4) * 16; }
__device__ __forceinline__ int aoffB(int lane) { return ((lane & 7) + ((lane >> 4) << 3)) * RS + (lane & 8) * 2; }

// ---------------------------------------------------------------------------
// Scratch
// ---------------------------------------------------------------------------
__device__ __nv_bfloat16 g_qp  [B_*N_*64];   // [b][n][qh(32)|ql(32)]
__device__ __nv_bfloat16 g_kp  [B_*N_*64];
__device__ __nv_bfloat16 g_vhi [B_*C_*N_];   // [b][c][n]
__device__ __nv_bfloat16 g_aohi[B_*N_*C_];   // [b][n][c]
__device__ __nv_bfloat16 g_aolo[B_*N_*C_];
__device__ __nv_bfloat16 g_wohi[C_*C_];
__device__ __nv_bfloat16 g_wolo[C_*C_];

// ---------------------------------------------------------------------------
__global__ void wprep_kernel(const float* __restrict__ wo,
                             __nv_bfloat16* __restrict__ whi, __nv_bfloat16* __restrict__ wlo)
{
    int i = blockIdx.x * 256 + threadIdx.x;
    float f = wo[i];
    __nv_bfloat16 h = __float2bfloat16(f);
    whi[i] = h;
    wlo[i] = __float2bfloat16(f - __bfloat162float(h));
}

// ---------------------------------------------------------------------------
// fused Q+K projection -> packed hi|lo bf16 rows (O=32); blockIdx.y: 0=q 1=k
// ---------------------------------------------------------------------------
__global__ __launch_bounds__(256)
void qk2_pack_kernel(const float* __restrict__ X,
                     const float* __restrict__ Wq, const float* __restrict__ Bq,
                     const float* __restrict__ Wk, const float* __restrict__ Bk,
                     __nv_bfloat16* __restrict__ outq, __nv_bfloat16* __restrict__ outk)
{
    __shared__ float W_s[32][68];
    __shared__ float X_s[64][132];
    const int b  = blockIdx.z;
    const int n0 = blockIdx.x * 128;
    const float* W = blockIdx.y ? Wk : Wq;
    const float* bias = blockIdx.y ? Bk : Bq;
    __nv_bfloat16* outp = blockIdx.y ? outk : outq;
    const int t  = threadIdx.x;
    const int to = t >> 4, tn = t & 15;
    const float* Xb = X + b * (C_ * N_);

    float acc[2][8];
#pragma unroll
    for (int i = 0; i < 2; i++)
#pragma unroll
        for (int j = 0; j < 8; j++) acc[i][j] = 0.f;

    for (int kt = 0; kt < C_; kt += 64) {
        __syncthreads();
#pragma unroll
        for (int it = 0; it < 2; it++) {
            int idx4 = t + it * 256;
            int o = idx4 >> 4, c4 = idx4 & 15;
            *(float4*)&W_s[o][c4 * 4] = *(const float4*)&W[o * C_ + kt + c4 * 4];
        }
#pragma unroll
        for (int it = 0; it < 8; it++) {
            int idx4 = t + it * 256;
            int kc = idx4 >> 5, n4 = idx4 & 31;
            *(float4*)&X_s[kc][n4 * 4] = *(const float4*)&Xb[(kt + kc) * N_ + n0 + n4 * 4];
        }
        __syncthreads();
#pragma unroll 4
        for (int kc = 0; kc < 64; kc++) {
            float xr[8];
            *(float4*)&xr[0] = *(const float4*)&X_s[kc][tn * 8];
            *(float4*)&xr[4] = *(const float4*)&X_s[kc][tn * 8 + 4];
            float w0 = W_s[to * 2 + 0][kc];
            float w1 = W_s[to * 2 + 1][kc];
#pragma unroll
            for (int j = 0; j < 8; j++) { acc[0][j] += w0 * xr[j]; acc[1][j] += w1 * xr[j]; }
        }
    }
    __syncthreads();
#pragma unroll
    for (int i = 0; i < 2; i++) {
        float bv = bias[to * 2 + i];
#pragma unroll
        for (int j = 0; j < 8; j++) X_s[to * 2 + i][tn * 8 + j] = acc[i][j] + bv;
    }
    __syncthreads();
#pragma unroll
    for (int it = 0; it < 8; it++) {
        int idx = t + it * 256;
        int n = idx >> 4, g = idx & 15;
        unsigned short us[4];
#pragma unroll
        for (int e = 0; e < 4; e++) {
            int col = g * 4 + e;
            if (col < 32) {
                us[e] = __bfloat16_as_ushort(__float2bfloat16(X_s[col][n]));
            } else {
                float f = X_s[col - 32][n];
                __nv_bfloat16 h = __float2bfloat16(f);
                us[e] = __bfloat16_as_ushort(__float2bfloat16(f - __bfloat162float(h)));
            }
        }
        *(uint2*)&outp[(size_t)(b * N_ + n0 + n) * 64 + g * 4] = *(uint2*)us;
    }
}

// ---------------------------------------------------------------------------
// V projection -> v_hi bf16 [b][c][n]
// ---------------------------------------------------------------------------
__global__ __launch_bounds__(256)
void v_proj_kernel(const float* __restrict__ X, const float* __restrict__ W,
                   const float* __restrict__ bias, __nv_bfloat16* __restrict__ vhi)
{
    __shared__ float W_s[32][68];
    __shared__ float X_s[64][132];
    const int b  = blockIdx.z;
    const int o0 = blockIdx.y * 32;
    const int n0 = blockIdx.x * 128;
    const int t  = threadIdx.x;
    const int to = t >> 4, tn = t & 15;
    const float* Xb = X + b * (C_ * N_);

    float acc[2][8];
#pragma unroll
    for (int i = 0; i < 2; i++)
#pragma unroll
        for (int j = 0; j < 8; j++) acc[i][j] = 0.f;

    for (int kt = 0; kt < C_; kt += 64) {
        __syncthreads();
#pragma unroll
        for (int it = 0; it < 2; it++) {
            int idx4 = t + it * 256;
            int o = idx4 >> 4, c4 = idx4 & 15;
            *(float4*)&W_s[o][c4 * 4] = *(const float4*)&W[(o0 + o) * C_ + kt + c4 * 4];
        }
#pragma unroll
        for (int it = 0; it < 8; it++) {
            int idx4 = t + it * 256;
            int kc = idx4 >> 5, n4 = idx4 & 31;
            *(float4*)&X_s[kc][n4 * 4] = *(const float4*)&Xb[(kt + kc) * N_ + n0 + n4 * 4];
        }
        __syncthreads();
#pragma unroll 4
        for (int kc = 0; kc < 64; kc++) {
            float xr[8];
            *(float4*)&xr[0] = *(const float4*)&X_s[kc][tn * 8];
            *(float4*)&xr[4] = *(const float4*)&X_s[kc][tn * 8 + 4];
            float w0 = W_s[to * 2 + 0][kc];
            float w1 = W_s[to * 2 + 1][kc];
#pragma unroll
            for (int j = 0; j < 8; j++) { acc[0][j] += w0 * xr[j]; acc[1][j] += w1 * xr[j]; }
        }
    }
#pragma unroll
    for (int i = 0; i < 2; i++) {
        int o = o0 + to * 2 + i;
        float bv = bias[o];
        unsigned short hs[8];
#pragma unroll
        for (int j = 0; j < 8; j++)
            hs[j] = __bfloat16_as_ushort(__float2bfloat16(acc[i][j] + bv));
        *(uint4*)&vhi[(size_t)(b * C_ + o) * N_ + n0 + tn * 8] = *(uint4*)hs;
    }
}

// ---------------------------------------------------------------------------
// Two-group skewed flash attention.
// Group A = warps 0-7 (queries 0-63, also the loader group t<256),
// Group B = warps 8-15 (queries 64-127).
// A: [softmax_i ; bar1 ; prefetch ; MMA_i ; arrive chain ; bar1]
// B: [wait chain_i ; MMA_i ; arrive empty ; bar2 ; softmax_{i+1} ; bar2]
// => A's softmax overlaps B's MMA and vice versa.
// mbarriers: 0 k0full, 8 k1full, 16 v0full, 24 v1full, 32 chain(256),
//            40 e0(256), 48 e1(256)
// ---------------------------------------------------------------------------
#define OFF_LSUM 64
#define OFF_Q    1024
#define OFF_K0   19456
#define OFF_K1   28672
#define OFF_PH   37888
#define OFF_PL   56320
#define OFF_VH0  74752
#define OFF_VH1  111616
#define ATTN_SMEM 148480
#define K_TX 8192
#define V_TX 32768

__global__ __launch_bounds__(512, 1)
void attn_mma_kernel(const __nv_bfloat16* __restrict__ qp,
                     const __nv_bfloat16* __restrict__ kp,
                     const __nv_bfloat16* __restrict__ vhi,
                     __nv_bfloat16* __restrict__ aohi,
                     __nv_bfloat16* __restrict__ aolo)
{
    extern __shared__ char sm[];
    const uint32_t sb = smem_u32(sm);
    const int t = threadIdx.x;
    const int wid = t >> 5, lane = t & 31;
    const int g = lane >> 2, tg = lane & 3;
    const int oA = aoffA(lane), oB = aoffB(lane);
    const int grp = wid >> 3;
    const int wg = wid & 7;
    const int wm = wg >> 2, wn = wg & 3;
    const int rowA = grp * 64 + wm * 32;   // query rows of this warp
    const int kb = wn * 16;                // key-column base (S phase)
    const int b = blockIdx.y, m0 = blockIdx.x * 128;

    const __nv_bfloat16* qp_b = qp + (size_t)b * N_ * 64;
    const __nv_bfloat16* kp_b = kp + (size_t)b * N_ * 64;
    const __nv_bfloat16* vh_b = vhi + (size_t)b * C_ * N_;

    float* lsum_s = (float*)(sm + OFF_LSUM);
    if (t == 0) {
        MBARRIER_INIT(sb + 0, 1);   MBARRIER_INIT(sb + 8, 1);
        MBARRIER_INIT(sb + 16, 1);  MBARRIER_INIT(sb + 24, 1);
        MBARRIER_INIT(sb + 32, 256);                   // chain (A arrives)
        MBARRIER_INIT(sb + 40, 256); MBARRIER_INIT(sb + 48, 256);  // e0/e1 (B arrives)
    }
    if (t < 128) lsum_s[t] = 0.f;

#pragma unroll
    for (int i = 0; i < 2; i++) {
        int idx = t + i * 512;
        int r = idx >> 3, ch = idx & 7;
        cpasync16(sb + OFF_Q + r * RS + ch * 16, qp_b + (size_t)(m0 + r) * 64 + ch * 8);
    }
    {
        int r = t >> 3, ch = t & 7;
        cpasync16(sb + OFF_K0 + r * RS + ch * 16, kp_b + (size_t)r * 64 + ch * 8);
    }
    CP_COMMIT();
    __syncthreads();

    if (t == 0) { MBARRIER_EXPECT_TX(sb + 16, V_TX); MBARRIER_EXPECT_TX(sb + 8, K_TX); }
    if (t < 256) bulk128(sb + OFF_VH0 + t * RS, vh_b + (size_t)t * N_, sb + 16);
    if (t < 64)  bulk128(sb + OFF_K1 + t * RS, kp_b + (size_t)(64 + t) * 64, sb + 8);

    CP_WAIT(0);
    __syncthreads();

    uint32_t qfh[2][2][4];
#pragma unroll
    for (int mf = 0; mf < 2; mf++)
#pragma unroll
        for (int c = 0; c < 2; c++)
            ldsm4(qfh[mf][c], sb + OFF_Q + (rowA + mf * 16) * RS + c * 32 + oA);

    const uint32_t sbPH = sb + OFF_PH, sbPL = sb + OFF_PL, sbQ = sb + OFF_Q;

    float sacc[2][2][4];
    float oacc[2][8][4];
#pragma unroll
    for (int i = 0; i < 2; i++)
#pragma unroll
        for (int j = 0; j < 8; j++)
#pragma unroll
            for (int c = 0; c < 4; c++) oacc[i][j][c] = 0.f;
    float lpart[2][2] = {{0.f, 0.f}, {0.f, 0.f}};
    int vcnt0 = 0, vcnt1 = 0, kcnt0 = 0, kcnt1 = 0;

    // S = Q K^T (split-precision, 24 MMAs) from K tile at Kbase
    auto do_smma = [&](uint32_t Kbase) {
#pragma unroll
        for (int a = 0; a < 2; a++)
#pragma unroll
            for (int j2 = 0; j2 < 2; j2++)
#pragma unroll
                for (int c = 0; c < 4; c++) sacc[a][j2][c] = 0.f;
        const uint32_t Kb = Kbase + kb * RS + oB;
        uint32_t bK[4];
        ldsm4(bK, Kb + 0);
#pragma unroll
        for (int mf = 0; mf < 2; mf++) { mma16816(sacc[mf][0], qfh[mf][0], &bK[0]); mma16816(sacc[mf][1], qfh[mf][0], &bK[2]); }
        {
            uint32_t ql[4];
#pragma unroll
            for (int mf = 0; mf < 2; mf++) {
                ldsm4(ql, sbQ + (rowA + mf * 16) * RS + 64 + oA);
                mma16816(sacc[mf][0], ql, &bK[0]); mma16816(sacc[mf][1], ql, &bK[2]);
            }
        }
        ldsm4(bK, Kb + 32);
#pragma unroll
        for (int mf = 0; mf < 2; mf++) { mma16816(sacc[mf][0], qfh[mf][1], &bK[0]); mma16816(sacc[mf][1], qfh[mf][1], &bK[2]); }
        {
            uint32_t ql[4];
#pragma unroll
            for (int mf = 0; mf < 2; mf++) {
                ldsm4(ql, sbQ + (rowA + mf * 16) * RS + 96 + oA);
                mma16816(sacc[mf][0], ql, &bK[0]); mma16816(sacc[mf][1], ql, &bK[2]);
            }
        }
        ldsm4(bK, Kb + 64);
#pragma unroll
        for (int mf = 0; mf < 2; mf++) { mma16816(sacc[mf][0], qfh[mf][0], &bK[0]); mma16816(sacc[mf][1], qfh[mf][0], &bK[2]); }
        ldsm4(bK, Kb + 96);
#pragma unroll
        for (int mf = 0; mf < 2; mf++) { mma16816(sacc[mf][0], qfh[mf][1], &bK[0]); mma16816(sacc[mf][1], qfh[mf][1], &bK[2]); }
    };

    // softmax(sacc) -> PH/PL rows rowA..rowA+31, cols kb..kb+15
    auto do_softmax = [&]() {
#pragma unroll
        for (int mf = 0; mf < 2; mf++) {
            const int r0 = rowA + mf * 16 + g;
#pragma unroll
            for (int nf = 0; nf < 2; nf++) {
                const int cb = kb + nf * 8 + 2 * tg;
                float p0 = __expf(fminf(sacc[mf][nf][0], 60.f));
                float p1 = __expf(fminf(sacc[mf][nf][1], 60.f));
                float p2 = __expf(fminf(sacc[mf][nf][2], 60.f));
                float p3 = __expf(fminf(sacc[mf][nf][3], 60.f));
                lpart[mf][0] += p0 + p1;
                lpart[mf][1] += p2 + p3;
                uint32_t hA = pack_bf16x2(p0, p1);
                uint32_t hB = pack_bf16x2(p2, p3);
                __nv_bfloat162 hv0 = *(__nv_bfloat162*)&hA;
                __nv_bfloat162 hv1 = *(__nv_bfloat162*)&hB;
                *(uint32_t*)(sm + OFF_PH + r0 * RS + cb * 2) = hA;
                *(uint32_t*)(sm + OFF_PH + (r0 + 8) * RS + cb * 2) = hB;
                *(uint32_t*)(sm + OFF_PL + r0 * RS + cb * 2) =
                    pack_bf16x2(p0 - __bfloat162float(hv0.x), p1 - __bfloat162float(hv0.y));
                *(uint32_t*)(sm + OFF_PL + (r0 + 8) * RS + cb * 2) =
                    pack_bf16x2(p2 - __bfloat162float(hv1.x), p3 - __bfloat162float(hv1.y));
            }
        }
    };

    // PV (2-term) from V tile at Vb
    auto do_pv = [&](uint32_t Vb) {
#pragma unroll
        for (int kk = 0; kk < 4; kk++) {
            uint32_t aH[2][4], aL[2][4];
#pragma unroll
            for (int mf = 0; mf < 2; mf++) {
                ldsm4(aH[mf], sbPH + (rowA + mf * 16) * RS + kk * 32 + oA);
                ldsm4(aL[mf], sbPL + (rowA + mf * 16) * RS + kk * 32 + oA);
            }
#pragma unroll
            for (int j = 0; j < 4; j++) {
                uint32_t bV[4];
                ldsm4(bV, Vb + (wn * 64 + j * 16) * RS + kk * 32 + oB);
#pragma unroll
                for (int mf = 0; mf < 2; mf++) {
                    mma16816(oacc[mf][2 * j],     aH[mf], &bV[0]);
                    mma16816(oacc[mf][2 * j],     aL[mf], &bV[0]);
                    mma16816(oacc[mf][2 * j + 1], aH[mf], &bV[2]);
                    mma16816(oacc[mf][2 * j + 1], aL[mf], &bV[2]);
                }
            }
        }
    };

    do_smma(sb + OFF_K0);   // S_0 (both groups)
    __syncthreads();        // everyone past K_0 reads before its slot is reloaded

    if (grp == 0) {
        // ---------------- group A (also loader) ----------------
        for (int i = 0; i < 64; i++) {
            do_softmax();                       // P^A_i
            NBAR(1);
            if (i + 1 < 64) {
                if (i >= 1)                     // slots released by B-MMA_{i-1}
                    MBARRIER_WAIT_PARITY(sb + 40 + ((i - 1) & 1) * 8, ((i - 1) >> 1) & 1);
                const int s = (i + 1) & 1, nn = (i + 1) * 64;
                const uint32_t vdst = sb + (s ? OFF_VH1 : OFF_VH0);
                if (t == 0) MBARRIER_EXPECT_TX(sb + 16 + s * 8, V_TX);
                bulk128(vdst + t * RS, vh_b + (size_t)t * N_ + nn, sb + 16 + s * 8);
                if (i + 2 < 64) {
                    const int s2 = i & 1, nn2 = (i + 2) * 64;
                    const uint32_t kdst = sb + (s2 ? OFF_K1 : OFF_K0);
                    if (t == 0) MBARRIER_EXPECT_TX(sb + s2 * 8, K_TX);
                    if (t < 64) bulk128(kdst + t * RS, kp_b + (size_t)(nn2 + t) * 64, sb + s2 * 8);
                }
            }
            if (i & 1) { MBARRIER_WAIT_PARITY(sb + 24, vcnt1 & 1); vcnt1++; }
            else       { MBARRIER_WAIT_PARITY(sb + 16, vcnt0 & 1); vcnt0++; }
            if (i + 1 < 64) {
                if ((i + 1) & 1) { MBARRIER_WAIT_PARITY(sb + 8, kcnt1 & 1); kcnt1++; }
                else             { MBARRIER_WAIT_PARITY(sb + 0, kcnt0 & 1); kcnt0++; }
                do_smma(sb + (((i + 1) & 1) ? OFF_K1 : OFF_K0));
            }
            do_pv(sb + ((i & 1) ? OFF_VH1 : OFF_VH0));
            MBARRIER_ARRIVE(sb + 32);           // chain: A-MMA_i done
            NBAR(1);
        }
    } else {
        // ---------------- group B ----------------
        do_softmax();                           // P^B_0
        NBAR(2);
        for (int i = 0; i < 64; i++) {
            MBARRIER_WAIT_PARITY(sb + 32, i & 1);   // A-MMA_i done
            if (i & 1) { MBARRIER_WAIT_PARITY(sb + 24, vcnt1 & 1); vcnt1++; }
            else       { MBARRIER_WAIT_PARITY(sb + 16, vcnt0 & 1); vcnt0++; }
            if (i + 1 < 64) {
                if ((i + 1) & 1) { MBARRIER_WAIT_PARITY(sb + 8, kcnt1 & 1); kcnt1++; }
                else             { MBARRIER_WAIT_PARITY(sb + 0, kcnt0 & 1); kcnt0++; }
                do_smma(sb + (((i + 1) & 1) ? OFF_K1 : OFF_K0));
            }
            do_pv(sb + ((i & 1) ? OFF_VH1 : OFF_VH0));
            MBARRIER_ARRIVE(sb + 40 + (i & 1) * 8); // e[i&1]: slots released
            NBAR(2);
            if (i + 1 < 64) do_softmax();           // P^B_{i+1}
            NBAR(2);
        }
    }

#pragma unroll
    for (int mf = 0; mf < 2; mf++) {
        atomicAdd(&lsum_s[rowA + mf * 16 + g],     lpart[mf][0]);
        atomicAdd(&lsum_s[rowA + mf * 16 + 8 + g], lpart[mf][1]);
    }
    __syncthreads();

    // epilogue: O/lsum -> bf16 hi/lo AO
#pragma unroll
    for (int mf = 0; mf < 2; mf++) {
        const int rA = rowA + mf * 16 + g;
        const int rB = rA + 8;
        const float invA = 1.f / lsum_s[rA];
        const float invB = 1.f / lsum_s[rB];
        __nv_bfloat16* hA = aohi + (size_t)(b * N_ + m0 + rA) * C_;
        __nv_bfloat16* hB = aohi + (size_t)(b * N_ + m0 + rB) * C_;
        __nv_bfloat16* lA = aolo + (size_t)(b * N_ + m0 + rA) * C_;
        __nv_bfloat16* lB = aolo + (size_t)(b * N_ + m0 + rB) * C_;
#pragma unroll
        for (int nf = 0; nf < 8; nf++) {
            const int cb = wn * 64 + nf * 8 + 2 * tg;
            float a0 = oacc[mf][nf][0] * invA, a1 = oacc[mf][nf][1] * invA;
            float b0v = oacc[mf][nf][2] * invB, b1v = oacc[mf][nf][3] * invB;
            uint32_t ha = pack_bf16x2(a0, a1);
            uint32_t hb = pack_bf16x2(b0v, b1v);
            __nv_bfloat162 va = *(__nv_bfloat162*)&ha;
            __nv_bfloat162 vb = *(__nv_bfloat162*)&hb;
            *(uint32_t*)(hA + cb) = ha;
            *(uint32_t*)(hB + cb) = hb;
            *(uint32_t*)(lA + cb) = pack_bf16x2(a0 - __bfloat162float(va.x), a1 - __bfloat162float(va.y));
            *(uint32_t*)(lB + cb) = pack_bf16x2(b0v - __bfloat162float(vb.x), b1v - __bfloat162float(vb.y));
        }
    }
}

// ---------------------------------------------------------------------------
// Output projection via split-bf16 mma.sync: out = wo*AO + bo + x
// ---------------------------------------------------------------------------
#define OP_WH 0
#define OP_WL 18432
#define OP_AH 36864
#define OP_AL 55296
#define OP_BUF 73728
#define OPROJ_SMEM 147456

__global__ __launch_bounds__(512, 1)
void oproj_mma_kernel(const __nv_bfloat16* __restrict__ aohi,
                      const __nv_bfloat16* __restrict__ aolo,
                      const __nv_bfloat16* __restrict__ whi,
                      const __nv_bfloat16* __restrict__ wlo,
                      const float* __restrict__ bo,
                      const float* __restrict__ x,
                      float* __restrict__ out)
{
    extern __shared__ char sm[];
    const uint32_t sb = smem_u32(sm);
    const int t = threadIdx.x;
    const int wid = t >> 5, lane = t & 31;
    const int g = lane >> 2, tg = lane & 3;
    const int oA = aoffA(lane), oB = aoffB(lane);
    const int wm = wid >> 2, wn = wid & 3;
    const int b = blockIdx.z, o0 = blockIdx.y * 128, m0 = blockIdx.x * 128;

    float oac[2][4][4];
#pragma unroll
    for (int i = 0; i < 2; i++)
#pragma unroll
        for (int j = 0; j < 4; j++)
#pragma unroll
            for (int c = 0; c < 4; c++) oac[i][j][c] = 0.f;

    auto load_stage = [&](int kt, int buf) {
        const uint32_t base = sb + buf * OP_BUF;
#pragma unroll
        for (int it = 0; it < 8; it++) {
            int idx = t + it * 512;
            int arr = idx >> 10, rr = (idx >> 3) & 127, cc = idx & 7;
            uint32_t dst = base + arr * 18432 + rr * RS + cc * 16;
            const __nv_bfloat16* src;
            if (arr == 0)      src = whi + (size_t)(o0 + rr) * C_ + kt + cc * 8;
            else if (arr == 1) src = wlo + (size_t)(o0 + rr) * C_ + kt + cc * 8;
            else if (arr == 2) src = aohi + (size_t)(b * N_ + m0 + rr) * C_ + kt + cc * 8;
            else               src = aolo + (size_t)(b * N_ + m0 + rr) * C_ + kt + cc * 8;
            cpasync16(dst, src);
        }
        CP_COMMIT();
    };

    load_stage(0, 0);
    for (int s = 0; s < 4; s++) {
        if (s + 1 < 4) { load_stage((s + 1) * 64, (s + 1) & 1); CP_WAIT(1); }
        else CP_WAIT(0);
        __syncthreads();
        const uint32_t base = sb + (s & 1) * OP_BUF;
        const uint32_t Wh = base + OP_WH + (wm * 32) * RS + oA;
        const uint32_t Wl = base + OP_WL + (wm * 32) * RS + oA;
        const uint32_t Ah = base + OP_AH + (wn * 32) * RS + oB;
        const uint32_t Al = base + OP_AL + (wn * 32) * RS + oB;
#pragma unroll
        for (int ks = 0; ks < 4; ks++) {
            uint32_t awh[2][4], awl[2][4];
#pragma unroll
            for (int mf = 0; mf < 2; mf++) {
                ldsm4(awh[mf], Wh + mf * 16 * RS + ks * 32);
                ldsm4(awl[mf], Wl + mf * 16 * RS + ks * 32);
            }
#pragma unroll
            for (int j = 0; j < 2; j++) {
                uint32_t bh[4], bl[4];
                ldsm4(bh, Ah + j * 16 * RS + ks * 32);
                ldsm4(bl, Al + j * 16 * RS + ks * 32);
#pragma unroll
                for (int h = 0; h < 2; h++) {
                    const int nf = 2 * j + h;
#pragma unroll
                    for (int mf = 0; mf < 2; mf++) {
                        mma16816(oac[mf][nf], awh[mf], &bh[2 * h]);
                        mma16816(oac[mf][nf], awl[mf], &bh[2 * h]);
                        mma16816(oac[mf][nf], awh[mf], &bl[2 * h]);
                    }
                }
            }
        }
        __syncthreads();
    }

#pragma unroll
    for (int mf = 0; mf < 2; mf++) {
        const int rA = o0 + wm * 32 + mf * 16 + g;
        const int rB = rA + 8;
        const float bvA = bo[rA], bvB = bo[rB];
#pragma unroll
        for (int nf = 0; nf < 4; nf++) {
            const int m = m0 + wn * 32 + nf * 8 + 2 * tg;
            size_t iA = (size_t)(b * C_ + rA) * N_ + m;
            size_t iB = (size_t)(b * C_ + rB) * N_ + m;
            float2 xA = *(const float2*)&x[iA];
            float2 xB = *(const float2*)&x[iB];
            *(float2*)&out[iA] = make_float2(oac[mf][nf][0] + bvA + xA.x, oac[mf][nf][1] + bvA + xA.y);
            *(float2*)&out[iB] = make_float2(oac[mf][nf][2] + bvB + xB.x, oac[mf][nf][3] + bvB + xB.y);
        }
    }
}

// ---------------------------------------------------------------------------
extern "C" void kernel_launch(void* const* d_in, const int* in_sizes, int n_in,
                              void* d_out, int out_size)
{
    const float* x  = (const float*)d_in[0];
    const float* wq = (const float*)d_in[1];
    const float* bq = (const float*)d_in[2];
    const float* wk = (const float*)d_in[3];
    const float* bk = (const float*)d_in[4];
    const float* wv = (const float*)d_in[5];
    const float* bv = (const float*)d_in[6];
    const float* wo = (const float*)d_in[7];
    const float* bo = (const float*)d_in[8];
    float* out = (float*)d_out;

    __nv_bfloat16 *gqp, *gkp, *gvh, *gaoh, *gaol, *gwh, *gwl;
    cudaGetSymbolAddress((void**)&gqp,  g_qp);
    cudaGetSymbolAddress((void**)&gkp,  g_kp);
    cudaGetSymbolAddress((void**)&gvh,  g_vhi);
    cudaGetSymbolAddress((void**)&gaoh, g_aohi);
    cudaGetSymbolAddress((void**)&gaol, g_aolo);
    cudaGetSymbolAddress((void**)&gwh,  g_wohi);
    cudaGetSymbolAddress((void**)&gwl,  g_wolo);

    cudaFuncSetAttribute(attn_mma_kernel, cudaFuncAttributeMaxDynamicSharedMemorySize, ATTN_SMEM);
    cudaFuncSetAttribute(oproj_mma_kernel, cudaFuncAttributeMaxDynamicSharedMemorySize, OPROJ_SMEM);

    dim3 blk(256);
    wprep_kernel   <<<C_, C_>>>(wo, gwh, gwl);
    qk2_pack_kernel<<<dim3(N_ / 128, 2, B_), blk>>>(x, wq, bq, wk, bk, gqp, gkp);
    v_proj_kernel  <<<dim3(N_ / 128, C_ / 32, B_), blk>>>(x, wv, bv, gvh);
    attn_mma_kernel<<<dim3(N_ / 128, B_), 512, ATTN_SMEM>>>(gqp, gkp, gvh, gaoh, gaol);
    oproj_mma_kernel<<<dim3(N_ / 128, C_ / 128, B_), 512, OPROJ_SMEM>>>(gaoh, gaol, gwh, gwl, bo, x, out);
}

// round 8
// speedup vs baseline: 2.8112x; 1.0059x over previous
#include <cuda_runtime.h>
#include <cuda_bf16.h>
#include <math.h>
#include <stdint.h>

#define B_ 4
#define C_ 256
#define N_ 4096
#define D_ 32

// ---------------------------------------------------------------------------
// PTX helpers (base sm_100-safe: mma.sync, ldmatrix, cp.async[.bulk], mbarrier)
// ---------------------------------------------------------------------------
__device__ __forceinline__ uint32_t smem_u32(const void* p) {
    uint32_t a;
    asm("{ .reg .u64 t; cvta.to.shared.u64 t, %1; cvt.u32.u64 %0, t; }" : "=r"(a) : "l"(p));
    return a;
}
#define MBARRIER_INIT(a, c) \
    asm volatile("mbarrier.init.shared.b64 [%0], %1;" :: "r"((uint32_t)(a)), "r"((uint32_t)(c)) : "memory")
#define MBARRIER_EXPECT_TX(a, n) \
    asm volatile("mbarrier.arrive.expect_tx.shared.b64 _, [%0], %1;" :: "r"((uint32_t)(a)), "r"((uint32_t)(n)) : "memory")
#define MBARRIER_WAIT_PARITY(a, ph) do { \
    uint32_t _m = (uint32_t)(a); uint32_t _p = (uint32_t)(ph); uint32_t _d; \
    asm volatile("{\n\t.reg .pred p;\n\tmbarrier.try_wait.parity.shared.b64 p, [%1], %2;\n\tselp.b32 %0,1,0,p;\n\t}" \
        : "=r"(_d) : "r"(_m), "r"(_p) : "memory"); \
    if (!_d) { \
        asm volatile("{\n\t.reg .pred P1;\n\tWL_%=:\n\tmbarrier.try_wait.parity.shared.b64 P1, [%0], %1;\n\t@P1 bra.uni WD_%=;\n\tbra.uni WL_%=;\n\tWD_%=:\n\t}" \
            :: "r"(_m), "r"(_p) : "memory"); \
    } } while (0)

__device__ __forceinline__ void cpasync16(uint32_t dst, const void* src) {
    asm volatile("cp.async.cg.shared.global [%0], [%1], 16;" :: "r"(dst), "l"(src) : "memory");
}
#define CP_COMMIT() asm volatile("cp.async.commit_group;" ::: "memory")
#define CP_WAIT(n)  asm volatile("cp.async.wait_group %0;" :: "n"(n) : "memory")

__device__ __forceinline__ void bulk128(uint32_t dst, const void* src, uint32_t mbar) {
    asm volatile("cp.async.bulk.shared::cta.global.mbarrier::complete_tx::bytes [%0], [%1], 128, [%2];"
                 :: "r"(dst), "l"(src), "r"(mbar) : "memory");
}

__device__ __forceinline__ void mma16816(float* d, const uint32_t* a, const uint32_t* b) {
    asm volatile("mma.sync.aligned.m16n8k16.row.col.f32.bf16.bf16.f32 "
                 "{%0,%1,%2,%3}, {%4,%5,%6,%7}, {%8,%9}, {%0,%1,%2,%3};"
                 : "+f"(d[0]), "+f"(d[1]), "+f"(d[2]), "+f"(d[3])
                 : "r"(a[0]), "r"(a[1]), "r"(a[2]), "r"(a[3]), "r"(b[0]), "r"(b[1]));
}
__device__ __forceinline__ void ldsm4(uint32_t* r, uint32_t addr) {
    asm volatile("ldmatrix.sync.aligned.m8n8.x4.shared.b16 {%0,%1,%2,%3}, [%4];"
                 : "=r"(r[0]), "=r"(r[1]), "=r"(r[2]), "=r"(r[3]) : "r"(addr));
}
__device__ __forceinline__ uint32_t pack_bf16x2(float x, float y) {
    __nv_bfloat162 h = __floats2bfloat162_rn(x, y);
    return *(uint32_t*)&h;
}

#define RS 144
__device__ __forceinline__ int aoffA(int lane) { return (lane & 15) * RS + (lane >> 4) * 16; }
__device__ __forceinline__ int aoffB(int lane) { return ((lane & 7) + ((lane >> 4) << 3)) * RS + (lane & 8) * 2; }

// ---------------------------------------------------------------------------
// Scratch
// ---------------------------------------------------------------------------
__device__ __nv_bfloat16 g_qp  [B_*N_*64];   // [b][n][qh(32)|ql(32)]
__device__ __nv_bfloat16 g_kp  [B_*N_*64];
__device__ __nv_bfloat16 g_vhi [B_*C_*N_];   // [b][c][n]
__device__ __nv_bfloat16 g_aohi[B_*N_*C_];   // [b][n][c]
__device__ __nv_bfloat16 g_aolo[B_*N_*C_];
__device__ __nv_bfloat16 g_wohi[C_*C_];
__device__ __nv_bfloat16 g_wolo[C_*C_];

// ---------------------------------------------------------------------------
__global__ void wprep_kernel(const float* __restrict__ wo,
                             __nv_bfloat16* __restrict__ whi, __nv_bfloat16* __restrict__ wlo)
{
    int i = blockIdx.x * 256 + threadIdx.x;
    float f = wo[i];
    __nv_bfloat16 h = __float2bfloat16(f);
    whi[i] = h;
    wlo[i] = __float2bfloat16(f - __bfloat162float(h));
}

// ---------------------------------------------------------------------------
// fused Q+K projection -> packed hi|lo bf16 rows (O=32); blockIdx.y: 0=q 1=k
// ---------------------------------------------------------------------------
__global__ __launch_bounds__(256)
void qk2_pack_kernel(const float* __restrict__ X,
                     const float* __restrict__ Wq, const float* __restrict__ Bq,
                     const float* __restrict__ Wk, const float* __restrict__ Bk,
                     __nv_bfloat16* __restrict__ outq, __nv_bfloat16* __restrict__ outk)
{
    __shared__ float W_s[32][68];
    __shared__ float X_s[64][132];
    const int b  = blockIdx.z;
    const int n0 = blockIdx.x * 128;
    const float* W = blockIdx.y ? Wk : Wq;
    const float* bias = blockIdx.y ? Bk : Bq;
    __nv_bfloat16* outp = blockIdx.y ? outk : outq;
    const int t  = threadIdx.x;
    const int to = t >> 4, tn = t & 15;
    const float* Xb = X + b * (C_ * N_);

    float acc[2][8];
#pragma unroll
    for (int i = 0; i < 2; i++)
#pragma unroll
        for (int j = 0; j < 8; j++) acc[i][j] = 0.f;

    for (int kt = 0; kt < C_; kt += 64) {
        __syncthreads();
#pragma unroll
        for (int it = 0; it < 2; it++) {
            int idx4 = t + it * 256;
            int o = idx4 >> 4, c4 = idx4 & 15;
            *(float4*)&W_s[o][c4 * 4] = *(const float4*)&W[o * C_ + kt + c4 * 4];
        }
#pragma unroll
        for (int it = 0; it < 8; it++) {
            int idx4 = t + it * 256;
            int kc = idx4 >> 5, n4 = idx4 & 31;
            *(float4*)&X_s[kc][n4 * 4] = *(const float4*)&Xb[(kt + kc) * N_ + n0 + n4 * 4];
        }
        __syncthreads();
#pragma unroll 4
        for (int kc = 0; kc < 64; kc++) {
            float xr[8];
            *(float4*)&xr[0] = *(const float4*)&X_s[kc][tn * 8];
            *(float4*)&xr[4] = *(const float4*)&X_s[kc][tn * 8 + 4];
            float w0 = W_s[to * 2 + 0][kc];
            float w1 = W_s[to * 2 + 1][kc];
#pragma unroll
            for (int j = 0; j < 8; j++) { acc[0][j] += w0 * xr[j]; acc[1][j] += w1 * xr[j]; }
        }
    }
    __syncthreads();
#pragma unroll
    for (int i = 0; i < 2; i++) {
        float bv = bias[to * 2 + i];
#pragma unroll
        for (int j = 0; j < 8; j++) X_s[to * 2 + i][tn * 8 + j] = acc[i][j] + bv;
    }
    __syncthreads();
#pragma unroll
    for (int it = 0; it < 8; it++) {
        int idx = t + it * 256;
        int n = idx >> 4, g = idx & 15;
        unsigned short us[4];
#pragma unroll
        for (int e = 0; e < 4; e++) {
            int col = g * 4 + e;
            if (col < 32) {
                us[e] = __bfloat16_as_ushort(__float2bfloat16(X_s[col][n]));
            } else {
                float f = X_s[col - 32][n];
                __nv_bfloat16 h = __float2bfloat16(f);
                us[e] = __bfloat16_as_ushort(__float2bfloat16(f - __bfloat162float(h)));
            }
        }
        *(uint2*)&outp[(size_t)(b * N_ + n0 + n) * 64 + g * 4] = *(uint2*)us;
    }
}

// ---------------------------------------------------------------------------
// V projection -> v_hi bf16 [b][c][n]
// ---------------------------------------------------------------------------
__global__ __launch_bounds__(256)
void v_proj_kernel(const float* __restrict__ X, const float* __restrict__ W,
                   const float* __restrict__ bias, __nv_bfloat16* __restrict__ vhi)
{
    __shared__ float W_s[32][68];
    __shared__ float X_s[64][132];
    const int b  = blockIdx.z;
    const int o0 = blockIdx.y * 32;
    const int n0 = blockIdx.x * 128;
    const int t  = threadIdx.x;
    const int to = t >> 4, tn = t & 15;
    const float* Xb = X + b * (C_ * N_);

    float acc[2][8];
#pragma unroll
    for (int i = 0; i < 2; i++)
#pragma unroll
        for (int j = 0; j < 8; j++) acc[i][j] = 0.f;

    for (int kt = 0; kt < C_; kt += 64) {
        __syncthreads();
#pragma unroll
        for (int it = 0; it < 2; it++) {
            int idx4 = t + it * 256;
            int o = idx4 >> 4, c4 = idx4 & 15;
            *(float4*)&W_s[o][c4 * 4] = *(const float4*)&W[(o0 + o) * C_ + kt + c4 * 4];
        }
#pragma unroll
        for (int it = 0; it < 8; it++) {
            int idx4 = t + it * 256;
            int kc = idx4 >> 5, n4 = idx4 & 31;
            *(float4*)&X_s[kc][n4 * 4] = *(const float4*)&Xb[(kt + kc) * N_ + n0 + n4 * 4];
        }
        __syncthreads();
#pragma unroll 4
        for (int kc = 0; kc < 64; kc++) {
            float xr[8];
            *(float4*)&xr[0] = *(const float4*)&X_s[kc][tn * 8];
            *(float4*)&xr[4] = *(const float4*)&X_s[kc][tn * 8 + 4];
            float w0 = W_s[to * 2 + 0][kc];
            float w1 = W_s[to * 2 + 1][kc];
#pragma unroll
            for (int j = 0; j < 8; j++) { acc[0][j] += w0 * xr[j]; acc[1][j] += w1 * xr[j]; }
        }
    }
#pragma unroll
    for (int i = 0; i < 2; i++) {
        int o = o0 + to * 2 + i;
        float bv = bias[o];
        unsigned short hs[8];
#pragma unroll
        for (int j = 0; j < 8; j++)
            hs[j] = __bfloat16_as_ushort(__float2bfloat16(acc[i][j] + bv));
        *(uint4*)&vhi[(size_t)(b * C_ + o) * N_ + n0 + tn * 8] = *(uint4*)hs;
    }
}

// ---------------------------------------------------------------------------
// Flash attention, 2 CTAs/SM. 256 threads, M=64 q/CTA, 64-key tiles.
// K single-buffered (consumed once per iter, reloaded at iter end with a full
// iteration of latency slack); V double-buffered. HW interleaves the two
// resident CTAs (one in softmax phase while the other issues MMAs).
// mbarriers: 0 kfull, 8 v0full, 16 v1full.
// ---------------------------------------------------------------------------
#define OFF_LSUM 64
#define OFF_Q    1024
#define OFF_K    10240
#define OFF_PH   19456
#define OFF_PL   28672
#define OFF_VH0  37888
#define OFF_VH1  74752
#define ATTN_SMEM 111616
#define K_TX 8192
#define V_TX 32768

__global__ __launch_bounds__(256, 2)
void attn_mma_kernel(const __nv_bfloat16* __restrict__ qp,
                     const __nv_bfloat16* __restrict__ kp,
                     const __nv_bfloat16* __restrict__ vhi,
                     __nv_bfloat16* __restrict__ aohi,
                     __nv_bfloat16* __restrict__ aolo)
{
    extern __shared__ char sm[];
    const uint32_t sb = smem_u32(sm);
    const int t = threadIdx.x;
    const int wid = t >> 5, lane = t & 31;
    const int g = lane >> 2, tg = lane & 3;
    const int oA = aoffA(lane), oB = aoffB(lane);
    const int wm = wid >> 2, wn = wid & 3;   // 2x4 warp grid
    const int rowA = wm * 32;                // query rows of this warp (0..63)
    const int kb = wn * 16;                  // key-column base (S phase)
    const int b = blockIdx.y, m0 = blockIdx.x * 64;

    const __nv_bfloat16* qp_b = qp + (size_t)b * N_ * 64;
    const __nv_bfloat16* kp_b = kp + (size_t)b * N_ * 64;
    const __nv_bfloat16* vh_b = vhi + (size_t)b * C_ * N_;

    float* lsum_s = (float*)(sm + OFF_LSUM);
    if (t == 0) {
        MBARRIER_INIT(sb + 0, 1);   // K full
        MBARRIER_INIT(sb + 8, 1);   // V slot0 full
        MBARRIER_INIT(sb + 16, 1);  // V slot1 full
    }
    if (t < 64) lsum_s[t] = 0.f;

    // Q (64 rows) + K_0 (64 rows) via cp.async, 16B chunks
#pragma unroll
    for (int i = 0; i < 2; i++) {
        int idx = t + i * 256;
        int r = idx >> 3, ch = idx & 7;
        cpasync16(sb + OFF_Q + r * RS + ch * 16, qp_b + (size_t)(m0 + r) * 64 + ch * 8);
        cpasync16(sb + OFF_K + r * RS + ch * 16, kp_b + (size_t)r * 64 + ch * 8);
    }
    CP_COMMIT();
    __syncthreads();   // mbarrier init + lsum visible

    // V_0 -> slot0
    if (t == 0) MBARRIER_EXPECT_TX(sb + 8, V_TX);
    bulk128(sb + OFF_VH0 + t * RS, vh_b + (size_t)t * N_, sb + 8);

    CP_WAIT(0);
    __syncthreads();   // Q, K_0 resident

    // Q-hi fragments resident in registers
    uint32_t qfh[2][2][4];
#pragma unroll
    for (int mf = 0; mf < 2; mf++)
#pragma unroll
        for (int c = 0; c < 2; c++)
            ldsm4(qfh[mf][c], sb + OFF_Q + (rowA + mf * 16) * RS + c * 32 + oA);

    const uint32_t sbPH = sb + OFF_PH, sbPL = sb + OFF_PL, sbQ = sb + OFF_Q;

    float sacc[2][2][4];
    float oacc[2][8][4];
#pragma unroll
    for (int i = 0; i < 2; i++)
#pragma unroll
        for (int j = 0; j < 8; j++)
#pragma unroll
            for (int c = 0; c < 4; c++) oacc[i][j][c] = 0.f;
    float lpart[2][2] = {{0.f, 0.f}, {0.f, 0.f}};
    int kcnt = 0, vcnt0 = 0, vcnt1 = 0;

    auto do_smma = [&]() {
#pragma unroll
        for (int a = 0; a < 2; a++)
#pragma unroll
            for (int j2 = 0; j2 < 2; j2++)
#pragma unroll
                for (int c = 0; c < 4; c++) sacc[a][j2][c] = 0.f;
        const uint32_t Kb = sb + OFF_K + kb * RS + oB;
        uint32_t bK[4];
        ldsm4(bK, Kb + 0);
#pragma unroll
        for (int mf = 0; mf < 2; mf++) { mma16816(sacc[mf][0], qfh[mf][0], &bK[0]); mma16816(sacc[mf][1], qfh[mf][0], &bK[2]); }
        {
            uint32_t ql[4];
#pragma unroll
            for (int mf = 0; mf < 2; mf++) {
                ldsm4(ql, sbQ + (rowA + mf * 16) * RS + 64 + oA);
                mma16816(sacc[mf][0], ql, &bK[0]); mma16816(sacc[mf][1], ql, &bK[2]);
            }
        }
        ldsm4(bK, Kb + 32);
#pragma unroll
        for (int mf = 0; mf < 2; mf++) { mma16816(sacc[mf][0], qfh[mf][1], &bK[0]); mma16816(sacc[mf][1], qfh[mf][1], &bK[2]); }
        {
            uint32_t ql[4];
#pragma unroll
            for (int mf = 0; mf < 2; mf++) {
                ldsm4(ql, sbQ + (rowA + mf * 16) * RS + 96 + oA);
                mma16816(sacc[mf][0], ql, &bK[0]); mma16816(sacc[mf][1], ql, &bK[2]);
            }
        }
        ldsm4(bK, Kb + 64);
#pragma unroll
        for (int mf = 0; mf < 2; mf++) { mma16816(sacc[mf][0], qfh[mf][0], &bK[0]); mma16816(sacc[mf][1], qfh[mf][0], &bK[2]); }
        ldsm4(bK, Kb + 96);
#pragma unroll
        for (int mf = 0; mf < 2; mf++) { mma16816(sacc[mf][0], qfh[mf][1], &bK[0]); mma16816(sacc[mf][1], qfh[mf][1], &bK[2]); }
    };

    auto do_softmax = [&]() {
#pragma unroll
        for (int mf = 0; mf < 2; mf++) {
            const int r0 = rowA + mf * 16 + g;
#pragma unroll
            for (int nf = 0; nf < 2; nf++) {
                const int cb = kb + nf * 8 + 2 * tg;
                float p0 = __expf(fminf(sacc[mf][nf][0], 60.f));
                float p1 = __expf(fminf(sacc[mf][nf][1], 60.f));
                float p2 = __expf(fminf(sacc[mf][nf][2], 60.f));
                float p3 = __expf(fminf(sacc[mf][nf][3], 60.f));
                lpart[mf][0] += p0 + p1;
                lpart[mf][1] += p2 + p3;
                uint32_t hA = pack_bf16x2(p0, p1);
                uint32_t hB = pack_bf16x2(p2, p3);
                __nv_bfloat162 hv0 = *(__nv_bfloat162*)&hA;
                __nv_bfloat162 hv1 = *(__nv_bfloat162*)&hB;
                *(uint32_t*)(sm + OFF_PH + r0 * RS + cb * 2) = hA;
                *(uint32_t*)(sm + OFF_PH + (r0 + 8) * RS + cb * 2) = hB;
                *(uint32_t*)(sm + OFF_PL + r0 * RS + cb * 2) =
                    pack_bf16x2(p0 - __bfloat162float(hv0.x), p1 - __bfloat162float(hv0.y));
                *(uint32_t*)(sm + OFF_PL + (r0 + 8) * RS + cb * 2) =
                    pack_bf16x2(p2 - __bfloat162float(hv1.x), p3 - __bfloat162float(hv1.y));
            }
        }
    };

    auto do_pv = [&](uint32_t Vb) {
#pragma unroll
        for (int kk = 0; kk < 4; kk++) {
            uint32_t aH[2][4], aL[2][4];
#pragma unroll
            for (int mf = 0; mf < 2; mf++) {
                ldsm4(aH[mf], sbPH + (rowA + mf * 16) * RS + kk * 32 + oA);
                ldsm4(aL[mf], sbPL + (rowA + mf * 16) * RS + kk * 32 + oA);
            }
#pragma unroll
            for (int j = 0; j < 4; j++) {
                uint32_t bV[4];
                ldsm4(bV, Vb + (wn * 64 + j * 16) * RS + kk * 32 + oB);
#pragma unroll
                for (int mf = 0; mf < 2; mf++) {
                    mma16816(oacc[mf][2 * j],     aH[mf], &bV[0]);
                    mma16816(oacc[mf][2 * j],     aL[mf], &bV[0]);
                    mma16816(oacc[mf][2 * j + 1], aH[mf], &bV[2]);
                    mma16816(oacc[mf][2 * j + 1], aL[mf], &bV[2]);
                }
            }
        }
    };

    do_smma();          // S_0 from K_0
    __syncthreads();    // all warps done reading K buffer

    // issue K_1 (overwrite K buffer) and V_1 (slot1)
    if (t == 0) { MBARRIER_EXPECT_TX(sb + 0, K_TX); MBARRIER_EXPECT_TX(sb + 16, V_TX); }
    if (t < 64) bulk128(sb + OFF_K + t * RS, kp_b + (size_t)(64 + t) * 64, sb + 0);
    bulk128(sb + OFF_VH1 + t * RS, vh_b + (size_t)t * N_ + 64, sb + 16);

    for (int i = 0; i < 64; i++) {
        do_softmax();                     // S_i -> P_i
        __syncthreads();                  // P_i visible

        if (i + 1 < 64) {                 // S_{i+1} from K buffer (holds K_{i+1})
            MBARRIER_WAIT_PARITY(sb + 0, kcnt & 1); kcnt++;
            do_smma();
        }
        if (i & 1) { MBARRIER_WAIT_PARITY(sb + 16, vcnt1 & 1); vcnt1++; }
        else       { MBARRIER_WAIT_PARITY(sb + 8,  vcnt0 & 1); vcnt0++; }
        do_pv(sb + ((i & 1) ? OFF_VH1 : OFF_VH0));
        __syncthreads();                  // K_{i+1}, P_i, V_i reads complete

        if (i + 2 < 64) {                 // reload K buffer + freed V slot
            const int nn = (i + 2) * 64;
            const uint32_t vdst = sb + ((i & 1) ? OFF_VH1 : OFF_VH0);
            const uint32_t vmb  = sb + 8 + (i & 1) * 8;
            if (t == 0) { MBARRIER_EXPECT_TX(sb + 0, K_TX); MBARRIER_EXPECT_TX(vmb, V_TX); }
            if (t < 64) bulk128(sb + OFF_K + t * RS, kp_b + (size_t)(nn + t) * 64, sb + 0);
            bulk128(vdst + t * RS, vh_b + (size_t)t * N_ + nn, vmb);
        }
    }

#pragma unroll
    for (int mf = 0; mf < 2; mf++) {
        atomicAdd(&lsum_s[rowA + mf * 16 + g],     lpart[mf][0]);
        atomicAdd(&lsum_s[rowA + mf * 16 + 8 + g], lpart[mf][1]);
    }
    __syncthreads();

    // epilogue: O/lsum -> bf16 hi/lo AO
#pragma unroll
    for (int mf = 0; mf < 2; mf++) {
        const int rA = rowA + mf * 16 + g;
        const int rB = rA + 8;
        const float invA = 1.f / lsum_s[rA];
        const float invB = 1.f / lsum_s[rB];
        __nv_bfloat16* hA = aohi + (size_t)(b * N_ + m0 + rA) * C_;
        __nv_bfloat16* hB = aohi + (size_t)(b * N_ + m0 + rB) * C_;
        __nv_bfloat16* lA = aolo + (size_t)(b * N_ + m0 + rA) * C_;
        __nv_bfloat16* lB = aolo + (size_t)(b * N_ + m0 + rB) * C_;
#pragma unroll
        for (int nf = 0; nf < 8; nf++) {
            const int cb = wn * 64 + nf * 8 + 2 * tg;
            float a0 = oacc[mf][nf][0] * invA, a1 = oacc[mf][nf][1] * invA;
            float b0v = oacc[mf][nf][2] * invB, b1v = oacc[mf][nf][3] * invB;
            uint32_t ha = pack_bf16x2(a0, a1);
            uint32_t hb = pack_bf16x2(b0v, b1v);
            __nv_bfloat162 va = *(__nv_bfloat162*)&ha;
            __nv_bfloat162 vb = *(__nv_bfloat162*)&hb;
            *(uint32_t*)(hA + cb) = ha;
            *(uint32_t*)(hB + cb) = hb;
            *(uint32_t*)(lA + cb) = pack_bf16x2(a0 - __bfloat162float(va.x), a1 - __bfloat162float(va.y));
            *(uint32_t*)(lB + cb) = pack_bf16x2(b0v - __bfloat162float(vb.x), b1v - __bfloat162float(vb.y));
        }
    }
}

// ---------------------------------------------------------------------------
// Output projection via split-bf16 mma.sync: out = wo*AO + bo + x
// ---------------------------------------------------------------------------
#define OP_WH 0
#define OP_WL 18432
#define OP_AH 36864
#define OP_AL 55296
#define OP_BUF 73728
#define OPROJ_SMEM 147456

__global__ __launch_bounds__(512, 1)
void oproj_mma_kernel(const __nv_bfloat16* __restrict__ aohi,
                      const __nv_bfloat16* __restrict__ aolo,
                      const __nv_bfloat16* __restrict__ whi,
                      const __nv_bfloat16* __restrict__ wlo,
                      const float* __restrict__ bo,
                      const float* __restrict__ x,
                      float* __restrict__ out)
{
    extern __shared__ char sm[];
    const uint32_t sb = smem_u32(sm);
    const int t = threadIdx.x;
    const int wid = t >> 5, lane = t & 31;
    const int g = lane >> 2, tg = lane & 3;
    const int oA = aoffA(lane), oB = aoffB(lane);
    const int wm = wid >> 2, wn = wid & 3;
    const int b = blockIdx.z, o0 = blockIdx.y * 128, m0 = blockIdx.x * 128;

    float oac[2][4][4];
#pragma unroll
    for (int i = 0; i < 2; i++)
#pragma unroll
        for (int j = 0; j < 4; j++)
#pragma unroll
            for (int c = 0; c < 4; c++) oac[i][j][c] = 0.f;

    auto load_stage = [&](int kt, int buf) {
        const uint32_t base = sb + buf * OP_BUF;
#pragma unroll
        for (int it = 0; it < 8; it++) {
            int idx = t + it * 512;
            int arr = idx >> 10, rr = (idx >> 3) & 127, cc = idx & 7;
            uint32_t dst = base + arr * 18432 + rr * RS + cc * 16;
            const __nv_bfloat16* src;
            if (arr == 0)      src = whi + (size_t)(o0 + rr) * C_ + kt + cc * 8;
            else if (arr == 1) src = wlo + (size_t)(o0 + rr) * C_ + kt + cc * 8;
            else if (arr == 2) src = aohi + (size_t)(b * N_ + m0 + rr) * C_ + kt + cc * 8;
            else               src = aolo + (size_t)(b * N_ + m0 + rr) * C_ + kt + cc * 8;
            cpasync16(dst, src);
        }
        CP_COMMIT();
    };

    load_stage(0, 0);
    for (int s = 0; s < 4; s++) {
        if (s + 1 < 4) { load_stage((s + 1) * 64, (s + 1) & 1); CP_WAIT(1); }
        else CP_WAIT(0);
        __syncthreads();
        const uint32_t base = sb + (s & 1) * OP_BUF;
        const uint32_t Wh = base + OP_WH + (wm * 32) * RS + oA;
        const uint32_t Wl = base + OP_WL + (wm * 32) * RS + oA;
        const uint32_t Ah = base + OP_AH + (wn * 32) * RS + oB;
        const uint32_t Al = base + OP_AL + (wn * 32) * RS + oB;
#pragma unroll
        for (int ks = 0; ks < 4; ks++) {
            uint32_t awh[2][4], awl[2][4];
#pragma unroll
            for (int mf = 0; mf < 2; mf++) {
                ldsm4(awh[mf], Wh + mf * 16 * RS + ks * 32);
                ldsm4(awl[mf], Wl + mf * 16 * RS + ks * 32);
            }
#pragma unroll
            for (int j = 0; j < 2; j++) {
                uint32_t bh[4], bl[4];
                ldsm4(bh, Ah + j * 16 * RS + ks * 32);
                ldsm4(bl, Al + j * 16 * RS + ks * 32);
#pragma unroll
                for (int h = 0; h < 2; h++) {
                    const int nf = 2 * j + h;
#pragma unroll
                    for (int mf = 0; mf < 2; mf++) {
                        mma16816(oac[mf][nf], awh[mf], &bh[2 * h]);
                        mma16816(oac[mf][nf], awl[mf], &bh[2 * h]);
                        mma16816(oac[mf][nf], awh[mf], &bl[2 * h]);
                    }
                }
            }
        }
        __syncthreads();
    }

#pragma unroll
    for (int mf = 0; mf < 2; mf++) {
        const int rA = o0 + wm * 32 + mf * 16 + g;
        const int rB = rA + 8;
        const float bvA = bo[rA], bvB = bo[rB];
#pragma unroll
        for (int nf = 0; nf < 4; nf++) {
            const int m = m0 + wn * 32 + nf * 8 + 2 * tg;
            size_t iA = (size_t)(b * C_ + rA) * N_ + m;
            size_t iB = (size_t)(b * C_ + rB) * N_ + m;
            float2 xA = *(const float2*)&x[iA];
            float2 xB = *(const float2*)&x[iB];
            *(float2*)&out[iA] = make_float2(oac[mf][nf][0] + bvA + xA.x, oac[mf][nf][1] + bvA + xA.y);
            *(float2*)&out[iB] = make_float2(oac[mf][nf][2] + bvB + xB.x, oac[mf][nf][3] + bvB + xB.y);
        }
    }
}

// ---------------------------------------------------------------------------
extern "C" void kernel_launch(void* const* d_in, const int* in_sizes, int n_in,
                              void* d_out, int out_size)
{
    const float* x  = (const float*)d_in[0];
    const float* wq = (const float*)d_in[1];
    const float* bq = (const float*)d_in[2];
    const float* wk = (const float*)d_in[3];
    const float* bk = (const float*)d_in[4];
    const float* wv = (const float*)d_in[5];
    const float* bv = (const float*)d_in[6];
    const float* wo = (const float*)d_in[7];
    const float* bo = (const float*)d_in[8];
    float* out = (float*)d_out;

    __nv_bfloat16 *gqp, *gkp, *gvh, *gaoh, *gaol, *gwh, *gwl;
    cudaGetSymbolAddress((void**)&gqp,  g_qp);
    cudaGetSymbolAddress((void**)&gkp,  g_kp);
    cudaGetSymbolAddress((void**)&gvh,  g_vhi);
    cudaGetSymbolAddress((void**)&gaoh, g_aohi);
    cudaGetSymbolAddress((void**)&gaol, g_aolo);
    cudaGetSymbolAddress((void**)&gwh,  g_wohi);
    cudaGetSymbolAddress((void**)&gwl,  g_wolo);

    cudaFuncSetAttribute(attn_mma_kernel, cudaFuncAttributeMaxDynamicSharedMemorySize, ATTN_SMEM);
    cudaFuncSetAttribute(oproj_mma_kernel, cudaFuncAttributeMaxDynamicSharedMemorySize, OPROJ_SMEM);

    dim3 blk(256);
    wprep_kernel   <<<C_, C_>>>(wo, gwh, gwl);
    qk2_pack_kernel<<<dim3(N_ / 128, 2, B_), blk>>>(x, wq, bq, wk, bk, gqp, gkp);
    v_proj_kernel  <<<dim3(N_ / 128, C_ / 32, B_), blk>>>(x, wv, bv, gvh);
    attn_mma_kernel<<<dim3(N_ / 64, B_), 256, ATTN_SMEM>>>(gqp, gkp, gvh, gaoh, gaol);
    oproj_mma_kernel<<<dim3(N_ / 128, C_ / 128, B_), 512, OPROJ_SMEM>>>(gaoh, gaol, gwh, gwl, bo, x, out);
}

// round 9
// speedup vs baseline: 3.3876x; 1.2050x over previous
#include <cuda_runtime.h>
#include <cuda_bf16.h>
#include <math.h>
#include <stdint.h>

#define B_ 4
#define C_ 256
#define N_ 4096
#define D_ 32

// ---------------------------------------------------------------------------
// PTX helpers (base sm_100-safe: mma.sync, ldmatrix, cp.async[.bulk], mbarrier)
// ---------------------------------------------------------------------------
__device__ __forceinline__ uint32_t smem_u32(const void* p) {
    uint32_t a;
    asm("{ .reg .u64 t; cvta.to.shared.u64 t, %1; cvt.u32.u64 %0, t; }" : "=r"(a) : "l"(p));
    return a;
}
#define MBARRIER_INIT(a, c) \
    asm volatile("mbarrier.init.shared.b64 [%0], %1;" :: "r"((uint32_t)(a)), "r"((uint32_t)(c)) : "memory")
#define MBARRIER_EXPECT_TX(a, n) \
    asm volatile("mbarrier.arrive.expect_tx.shared.b64 _, [%0], %1;" :: "r"((uint32_t)(a)), "r"((uint32_t)(n)) : "memory")
#define MBARRIER_WAIT_PARITY(a, ph) do { \
    uint32_t _m = (uint32_t)(a); uint32_t _p = (uint32_t)(ph); uint32_t _d; \
    asm volatile("{\n\t.reg .pred p;\n\tmbarrier.try_wait.parity.shared.b64 p, [%1], %2;\n\tselp.b32 %0,1,0,p;\n\t}" \
        : "=r"(_d) : "r"(_m), "r"(_p) : "memory"); \
    if (!_d) { \
        asm volatile("{\n\t.reg .pred P1;\n\tWL_%=:\n\tmbarrier.try_wait.parity.shared.b64 P1, [%0], %1;\n\t@P1 bra.uni WD_%=;\n\tbra.uni WL_%=;\n\tWD_%=:\n\t}" \
            :: "r"(_m), "r"(_p) : "memory"); \
    } } while (0)

__device__ __forceinline__ void cpasync16(uint32_t dst, const void* src) {
    asm volatile("cp.async.cg.shared.global [%0], [%1], 16;" :: "r"(dst), "l"(src) : "memory");
}
#define CP_COMMIT() asm volatile("cp.async.commit_group;" ::: "memory")
#define CP_WAIT(n)  asm volatile("cp.async.wait_group %0;" :: "n"(n) : "memory")

__device__ __forceinline__ void bulk128(uint32_t dst, const void* src, uint32_t mbar) {
    asm volatile("cp.async.bulk.shared::cta.global.mbarrier::complete_tx::bytes [%0], [%1], 128, [%2];"
                 :: "r"(dst), "l"(src), "r"(mbar) : "memory");
}

__device__ __forceinline__ void mma16816(float* d, const uint32_t* a, const uint32_t* b) {
    asm volatile("mma.sync.aligned.m16n8k16.row.col.f32.bf16.bf16.f32 "
                 "{%0,%1,%2,%3}, {%4,%5,%6,%7}, {%8,%9}, {%0,%1,%2,%3};"
                 : "+f"(d[0]), "+f"(d[1]), "+f"(d[2]), "+f"(d[3])
                 : "r"(a[0]), "r"(a[1]), "r"(a[2]), "r"(a[3]), "r"(b[0]), "r"(b[1]));
}
__device__ __forceinline__ void ldsm4(uint32_t* r, uint32_t addr) {
    asm volatile("ldmatrix.sync.aligned.m8n8.x4.shared.b16 {%0,%1,%2,%3}, [%4];"
                 : "=r"(r[0]), "=r"(r[1]), "=r"(r[2]), "=r"(r[3]) : "r"(addr));
}
__device__ __forceinline__ uint32_t pack_bf16x2(float x, float y) {
    __nv_bfloat162 h = __floats2bfloat162_rn(x, y);
    return *(uint32_t*)&h;
}

#define RS 144
__device__ __forceinline__ int aoffA(int lane) { return (lane & 15) * RS + (lane >> 4) * 16; }
__device__ __forceinline__ int aoffB(int lane) { return ((lane & 7) + ((lane >> 4) << 3)) * RS + (lane & 8) * 2; }

// ---------------------------------------------------------------------------
// Scratch
// ---------------------------------------------------------------------------
__device__ __nv_bfloat16 g_qp  [B_*N_*64];   // [b][n][qh(32)|ql(32)]
__device__ __nv_bfloat16 g_kp  [B_*N_*64];
__device__ __nv_bfloat16 g_vhi [B_*C_*N_];   // [b][c][n]
__device__ __nv_bfloat16 g_aohi[B_*N_*C_];   // [b][n][c]
__device__ __nv_bfloat16 g_aolo[B_*N_*C_];
__device__ __nv_bfloat16 g_wohi[C_*C_];
__device__ __nv_bfloat16 g_wolo[C_*C_];

// ---------------------------------------------------------------------------
__global__ void wprep_kernel(const float* __restrict__ wo,
                             __nv_bfloat16* __restrict__ whi, __nv_bfloat16* __restrict__ wlo)
{
    int i = blockIdx.x * 256 + threadIdx.x;
    float f = wo[i];
    __nv_bfloat16 h = __float2bfloat16(f);
    whi[i] = h;
    wlo[i] = __float2bfloat16(f - __bfloat162float(h));
}

// ---------------------------------------------------------------------------
// fused Q+K projection -> packed hi|lo bf16 rows (O=32); blockIdx.y: 0=q 1=k
// ---------------------------------------------------------------------------
__global__ __launch_bounds__(256)
void qk2_pack_kernel(const float* __restrict__ X,
                     const float* __restrict__ Wq, const float* __restrict__ Bq,
                     const float* __restrict__ Wk, const float* __restrict__ Bk,
                     __nv_bfloat16* __restrict__ outq, __nv_bfloat16* __restrict__ outk)
{
    __shared__ float W_s[32][68];
    __shared__ float X_s[64][132];
    const int b  = blockIdx.z;
    const int n0 = blockIdx.x * 128;
    const float* W = blockIdx.y ? Wk : Wq;
    const float* bias = blockIdx.y ? Bk : Bq;
    __nv_bfloat16* outp = blockIdx.y ? outk : outq;
    const int t  = threadIdx.x;
    const int to = t >> 4, tn = t & 15;
    const float* Xb = X + b * (C_ * N_);

    float acc[2][8];
#pragma unroll
    for (int i = 0; i < 2; i++)
#pragma unroll
        for (int j = 0; j < 8; j++) acc[i][j] = 0.f;

    for (int kt = 0; kt < C_; kt += 64) {
        __syncthreads();
#pragma unroll
        for (int it = 0; it < 2; it++) {
            int idx4 = t + it * 256;
            int o = idx4 >> 4, c4 = idx4 & 15;
            *(float4*)&W_s[o][c4 * 4] = *(const float4*)&W[o * C_ + kt + c4 * 4];
        }
#pragma unroll
        for (int it = 0; it < 8; it++) {
            int idx4 = t + it * 256;
            int kc = idx4 >> 5, n4 = idx4 & 31;
            *(float4*)&X_s[kc][n4 * 4] = *(const float4*)&Xb[(kt + kc) * N_ + n0 + n4 * 4];
        }
        __syncthreads();
#pragma unroll 4
        for (int kc = 0; kc < 64; kc++) {
            float xr[8];
            *(float4*)&xr[0] = *(const float4*)&X_s[kc][tn * 8];
            *(float4*)&xr[4] = *(const float4*)&X_s[kc][tn * 8 + 4];
            float w0 = W_s[to * 2 + 0][kc];
            float w1 = W_s[to * 2 + 1][kc];
#pragma unroll
            for (int j = 0; j < 8; j++) { acc[0][j] += w0 * xr[j]; acc[1][j] += w1 * xr[j]; }
        }
    }
    __syncthreads();
#pragma unroll
    for (int i = 0; i < 2; i++) {
        float bv = bias[to * 2 + i];
#pragma unroll
        for (int j = 0; j < 8; j++) X_s[to * 2 + i][tn * 8 + j] = acc[i][j] + bv;
    }
    __syncthreads();
#pragma unroll
    for (int it = 0; it < 8; it++) {
        int idx = t + it * 256;
        int n = idx >> 4, g = idx & 15;
        unsigned short us[4];
#pragma unroll
        for (int e = 0; e < 4; e++) {
            int col = g * 4 + e;
            if (col < 32) {
                us[e] = __bfloat16_as_ushort(__float2bfloat16(X_s[col][n]));
            } else {
                float f = X_s[col - 32][n];
                __nv_bfloat16 h = __float2bfloat16(f);
                us[e] = __bfloat16_as_ushort(__float2bfloat16(f - __bfloat162float(h)));
            }
        }
        *(uint2*)&outp[(size_t)(b * N_ + n0 + n) * 64 + g * 4] = *(uint2*)us;
    }
}

// ---------------------------------------------------------------------------
// V projection -> v_hi bf16 [b][c][n]
// ---------------------------------------------------------------------------
__global__ __launch_bounds__(256)
void v_proj_kernel(const float* __restrict__ X, const float* __restrict__ W,
                   const float* __restrict__ bias, __nv_bfloat16* __restrict__ vhi)
{
    __shared__ float W_s[32][68];
    __shared__ float X_s[64][132];
    const int b  = blockIdx.z;
    const int o0 = blockIdx.y * 32;
    const int n0 = blockIdx.x * 128;
    const int t  = threadIdx.x;
    const int to = t >> 4, tn = t & 15;
    const float* Xb = X + b * (C_ * N_);

    float acc[2][8];
#pragma unroll
    for (int i = 0; i < 2; i++)
#pragma unroll
        for (int j = 0; j < 8; j++) acc[i][j] = 0.f;

    for (int kt = 0; kt < C_; kt += 64) {
        __syncthreads();
#pragma unroll
        for (int it = 0; it < 2; it++) {
            int idx4 = t + it * 256;
            int o = idx4 >> 4, c4 = idx4 & 15;
            *(float4*)&W_s[o][c4 * 4] = *(const float4*)&W[(o0 + o) * C_ + kt + c4 * 4];
        }
#pragma unroll
        for (int it = 0; it < 8; it++) {
            int idx4 = t + it * 256;
            int kc = idx4 >> 5, n4 = idx4 & 31;
            *(float4*)&X_s[kc][n4 * 4] = *(const float4*)&Xb[(kt + kc) * N_ + n0 + n4 * 4];
        }
        __syncthreads();
#pragma unroll 4
        for (int kc = 0; kc < 64; kc++) {
            float xr[8];
            *(float4*)&xr[0] = *(const float4*)&X_s[kc][tn * 8];
            *(float4*)&xr[4] = *(const float4*)&X_s[kc][tn * 8 + 4];
            float w0 = W_s[to * 2 + 0][kc];
            float w1 = W_s[to * 2 + 1][kc];
#pragma unroll
            for (int j = 0; j < 8; j++) { acc[0][j] += w0 * xr[j]; acc[1][j] += w1 * xr[j]; }
        }
    }
#pragma unroll
    for (int i = 0; i < 2; i++) {
        int o = o0 + to * 2 + i;
        float bv = bias[o];
        unsigned short hs[8];
#pragma unroll
        for (int j = 0; j < 8; j++)
            hs[j] = __bfloat16_as_ushort(__float2bfloat16(acc[i][j] + bv));
        *(uint4*)&vhi[(size_t)(b * C_ + o) * N_ + n0 + tn * 8] = *(uint4*)hs;
    }
}

// ---------------------------------------------------------------------------
// Flash attention, 2 CTAs/SM, SINGLE-term PV (p bf16-rounded; lsum accumulated
// from the ROUNDED p so softmax weights stay a consistent convex combination).
// 256 threads, M=64 q/CTA, 64-key tiles. K single-buffered, V double-buffered.
// mbarriers: 0 kfull, 8 v0full, 16 v1full.
// ---------------------------------------------------------------------------
#define OFF_LSUM 64
#define OFF_Q    1024
#define OFF_K    10240
#define OFF_PH   19456
#define OFF_VH0  28672
#define OFF_VH1  65536
#define ATTN_SMEM 102400
#define K_TX 8192
#define V_TX 32768

__global__ __launch_bounds__(256, 2)
void attn_mma_kernel(const __nv_bfloat16* __restrict__ qp,
                     const __nv_bfloat16* __restrict__ kp,
                     const __nv_bfloat16* __restrict__ vhi,
                     __nv_bfloat16* __restrict__ aohi,
                     __nv_bfloat16* __restrict__ aolo)
{
    extern __shared__ char sm[];
    const uint32_t sb = smem_u32(sm);
    const int t = threadIdx.x;
    const int wid = t >> 5, lane = t & 31;
    const int g = lane >> 2, tg = lane & 3;
    const int oA = aoffA(lane), oB = aoffB(lane);
    const int wm = wid >> 2, wn = wid & 3;   // 2x4 warp grid
    const int rowA = wm * 32;                // query rows of this warp (0..63)
    const int kb = wn * 16;                  // key-column base (S phase)
    const int b = blockIdx.y, m0 = blockIdx.x * 64;

    const __nv_bfloat16* qp_b = qp + (size_t)b * N_ * 64;
    const __nv_bfloat16* kp_b = kp + (size_t)b * N_ * 64;
    const __nv_bfloat16* vh_b = vhi + (size_t)b * C_ * N_;

    float* lsum_s = (float*)(sm + OFF_LSUM);
    if (t == 0) {
        MBARRIER_INIT(sb + 0, 1);   // K full
        MBARRIER_INIT(sb + 8, 1);   // V slot0 full
        MBARRIER_INIT(sb + 16, 1);  // V slot1 full
    }
    if (t < 64) lsum_s[t] = 0.f;

    // Q (64 rows) + K_0 (64 rows) via cp.async, 16B chunks
#pragma unroll
    for (int i = 0; i < 2; i++) {
        int idx = t + i * 256;
        int r = idx >> 3, ch = idx & 7;
        cpasync16(sb + OFF_Q + r * RS + ch * 16, qp_b + (size_t)(m0 + r) * 64 + ch * 8);
        cpasync16(sb + OFF_K + r * RS + ch * 16, kp_b + (size_t)r * 64 + ch * 8);
    }
    CP_COMMIT();
    __syncthreads();   // mbarrier init + lsum visible

    // V_0 -> slot0
    if (t == 0) MBARRIER_EXPECT_TX(sb + 8, V_TX);
    bulk128(sb + OFF_VH0 + t * RS, vh_b + (size_t)t * N_, sb + 8);

    CP_WAIT(0);
    __syncthreads();   // Q, K_0 resident

    // Q-hi fragments resident in registers
    uint32_t qfh[2][2][4];
#pragma unroll
    for (int mf = 0; mf < 2; mf++)
#pragma unroll
        for (int c = 0; c < 2; c++)
            ldsm4(qfh[mf][c], sb + OFF_Q + (rowA + mf * 16) * RS + c * 32 + oA);

    const uint32_t sbPH = sb + OFF_PH, sbQ = sb + OFF_Q;

    float sacc[2][2][4];
    float oacc[2][8][4];
#pragma unroll
    for (int i = 0; i < 2; i++)
#pragma unroll
        for (int j = 0; j < 8; j++)
#pragma unroll
            for (int c = 0; c < 4; c++) oacc[i][j][c] = 0.f;
    float lpart[2][2] = {{0.f, 0.f}, {0.f, 0.f}};
    int kcnt = 0, vcnt0 = 0, vcnt1 = 0;

    auto do_smma = [&]() {
#pragma unroll
        for (int a = 0; a < 2; a++)
#pragma unroll
            for (int j2 = 0; j2 < 2; j2++)
#pragma unroll
                for (int c = 0; c < 4; c++) sacc[a][j2][c] = 0.f;
        const uint32_t Kb = sb + OFF_K + kb * RS + oB;
        uint32_t bK[4];
        ldsm4(bK, Kb + 0);
#pragma unroll
        for (int mf = 0; mf < 2; mf++) { mma16816(sacc[mf][0], qfh[mf][0], &bK[0]); mma16816(sacc[mf][1], qfh[mf][0], &bK[2]); }
        {
            uint32_t ql[4];
#pragma unroll
            for (int mf = 0; mf < 2; mf++) {
                ldsm4(ql, sbQ + (rowA + mf * 16) * RS + 64 + oA);
                mma16816(sacc[mf][0], ql, &bK[0]); mma16816(sacc[mf][1], ql, &bK[2]);
            }
        }
        ldsm4(bK, Kb + 32);
#pragma unroll
        for (int mf = 0; mf < 2; mf++) { mma16816(sacc[mf][0], qfh[mf][1], &bK[0]); mma16816(sacc[mf][1], qfh[mf][1], &bK[2]); }
        {
            uint32_t ql[4];
#pragma unroll
            for (int mf = 0; mf < 2; mf++) {
                ldsm4(ql, sbQ + (rowA + mf * 16) * RS + 96 + oA);
                mma16816(sacc[mf][0], ql, &bK[0]); mma16816(sacc[mf][1], ql, &bK[2]);
            }
        }
        ldsm4(bK, Kb + 64);
#pragma unroll
        for (int mf = 0; mf < 2; mf++) { mma16816(sacc[mf][0], qfh[mf][0], &bK[0]); mma16816(sacc[mf][1], qfh[mf][0], &bK[2]); }
        ldsm4(bK, Kb + 96);
#pragma unroll
        for (int mf = 0; mf < 2; mf++) { mma16816(sacc[mf][0], qfh[mf][1], &bK[0]); mma16816(sacc[mf][1], qfh[mf][1], &bK[2]); }
    };

    // softmax: round p to bf16 FIRST, accumulate lsum from the ROUNDED values
    // (numerator and denominator then use identical weights -> rounding error
    //  is a weight perturbation inside an exact convex combination).
    auto do_softmax = [&]() {
#pragma unroll
        for (int mf = 0; mf < 2; mf++) {
            const int r0 = rowA + mf * 16 + g;
#pragma unroll
            for (int nf = 0; nf < 2; nf++) {
                const int cb = kb + nf * 8 + 2 * tg;
                float p0 = __expf(fminf(sacc[mf][nf][0], 60.f));
                float p1 = __expf(fminf(sacc[mf][nf][1], 60.f));
                float p2 = __expf(fminf(sacc[mf][nf][2], 60.f));
                float p3 = __expf(fminf(sacc[mf][nf][3], 60.f));
                uint32_t hA = pack_bf16x2(p0, p1);
                uint32_t hB = pack_bf16x2(p2, p3);
                __nv_bfloat162 hv0 = *(__nv_bfloat162*)&hA;
                __nv_bfloat162 hv1 = *(__nv_bfloat162*)&hB;
                lpart[mf][0] += __bfloat162float(hv0.x) + __bfloat162float(hv0.y);
                lpart[mf][1] += __bfloat162float(hv1.x) + __bfloat162float(hv1.y);
                *(uint32_t*)(sm + OFF_PH + r0 * RS + cb * 2) = hA;
                *(uint32_t*)(sm + OFF_PH + (r0 + 8) * RS + cb * 2) = hB;
            }
        }
    };

    // PV single-term
    auto do_pv = [&](uint32_t Vb) {
#pragma unroll
        for (int kk = 0; kk < 4; kk++) {
            uint32_t aH[2][4];
#pragma unroll
            for (int mf = 0; mf < 2; mf++)
                ldsm4(aH[mf], sbPH + (rowA + mf * 16) * RS + kk * 32 + oA);
#pragma unroll
            for (int j = 0; j < 4; j++) {
                uint32_t bV[4];
                ldsm4(bV, Vb + (wn * 64 + j * 16) * RS + kk * 32 + oB);
#pragma unroll
                for (int mf = 0; mf < 2; mf++) {
                    mma16816(oacc[mf][2 * j],     aH[mf], &bV[0]);
                    mma16816(oacc[mf][2 * j + 1], aH[mf], &bV[2]);
                }
            }
        }
    };

    do_smma();          // S_0 from K_0
    __syncthreads();    // all warps done reading K buffer

    // issue K_1 (overwrite K buffer) and V_1 (slot1)
    if (t == 0) { MBARRIER_EXPECT_TX(sb + 0, K_TX); MBARRIER_EXPECT_TX(sb + 16, V_TX); }
    if (t < 64) bulk128(sb + OFF_K + t * RS, kp_b + (size_t)(64 + t) * 64, sb + 0);
    bulk128(sb + OFF_VH1 + t * RS, vh_b + (size_t)t * N_ + 64, sb + 16);

    for (int i = 0; i < 64; i++) {
        do_softmax();                     // S_i -> P_i
        __syncthreads();                  // P_i visible

        if (i + 1 < 64) {                 // S_{i+1} from K buffer (holds K_{i+1})
            MBARRIER_WAIT_PARITY(sb + 0, kcnt & 1); kcnt++;
            do_smma();
        }
        if (i & 1) { MBARRIER_WAIT_PARITY(sb + 16, vcnt1 & 1); vcnt1++; }
        else       { MBARRIER_WAIT_PARITY(sb + 8,  vcnt0 & 1); vcnt0++; }
        do_pv(sb + ((i & 1) ? OFF_VH1 : OFF_VH0));
        __syncthreads();                  // K_{i+1}, P_i, V_i reads complete

        if (i + 2 < 64) {                 // reload K buffer + freed V slot
            const int nn = (i + 2) * 64;
            const uint32_t vdst = sb + ((i & 1) ? OFF_VH1 : OFF_VH0);
            const uint32_t vmb  = sb + 8 + (i & 1) * 8;
            if (t == 0) { MBARRIER_EXPECT_TX(sb + 0, K_TX); MBARRIER_EXPECT_TX(vmb, V_TX); }
            if (t < 64) bulk128(sb + OFF_K + t * RS, kp_b + (size_t)(nn + t) * 64, sb + 0);
            bulk128(vdst + t * RS, vh_b + (size_t)t * N_ + nn, vmb);
        }
    }

#pragma unroll
    for (int mf = 0; mf < 2; mf++) {
        atomicAdd(&lsum_s[rowA + mf * 16 + g],     lpart[mf][0]);
        atomicAdd(&lsum_s[rowA + mf * 16 + 8 + g], lpart[mf][1]);
    }
    __syncthreads();

    // epilogue: O/lsum -> bf16 hi/lo AO
#pragma unroll
    for (int mf = 0; mf < 2; mf++) {
        const int rA = rowA + mf * 16 + g;
        const int rB = rA + 8;
        const float invA = 1.f / lsum_s[rA];
        const float invB = 1.f / lsum_s[rB];
        __nv_bfloat16* hA = aohi + (size_t)(b * N_ + m0 + rA) * C_;
        __nv_bfloat16* hB = aohi + (size_t)(b * N_ + m0 + rB) * C_;
        __nv_bfloat16* lA = aolo + (size_t)(b * N_ + m0 + rA) * C_;
        __nv_bfloat16* lB = aolo + (size_t)(b * N_ + m0 + rB) * C_;
#pragma unroll
        for (int nf = 0; nf < 8; nf++) {
            const int cb = wn * 64 + nf * 8 + 2 * tg;
            float a0 = oacc[mf][nf][0] * invA, a1 = oacc[mf][nf][1] * invA;
            float b0v = oacc[mf][nf][2] * invB, b1v = oacc[mf][nf][3] * invB;
            uint32_t ha = pack_bf16x2(a0, a1);
            uint32_t hb = pack_bf16x2(b0v, b1v);
            __nv_bfloat162 va = *(__nv_bfloat162*)&ha;
            __nv_bfloat162 vb = *(__nv_bfloat162*)&hb;
            *(uint32_t*)(hA + cb) = ha;
            *(uint32_t*)(hB + cb) = hb;
            *(uint32_t*)(lA + cb) = pack_bf16x2(a0 - __bfloat162float(va.x), a1 - __bfloat162float(va.y));
            *(uint32_t*)(lB + cb) = pack_bf16x2(b0v - __bfloat162float(vb.x), b1v - __bfloat162float(vb.y));
        }
    }
}

// ---------------------------------------------------------------------------
// Output projection via split-bf16 mma.sync: out = wo*AO + bo + x
// ---------------------------------------------------------------------------
#define OP_WH 0
#define OP_WL 18432
#define OP_AH 36864
#define OP_AL 55296
#define OP_BUF 73728
#define OPROJ_SMEM 147456

__global__ __launch_bounds__(512, 1)
void oproj_mma_kernel(const __nv_bfloat16* __restrict__ aohi,
                      const __nv_bfloat16* __restrict__ aolo,
                      const __nv_bfloat16* __restrict__ whi,
                      const __nv_bfloat16* __restrict__ wlo,
                      const float* __restrict__ bo,
                      const float* __restrict__ x,
                      float* __restrict__ out)
{
    extern __shared__ char sm[];
    const uint32_t sb = smem_u32(sm);
    const int t = threadIdx.x;
    const int wid = t >> 5, lane = t & 31;
    const int g = lane >> 2, tg = lane & 3;
    const int oA = aoffA(lane), oB = aoffB(lane);
    const int wm = wid >> 2, wn = wid & 3;
    const int b = blockIdx.z, o0 = blockIdx.y * 128, m0 = blockIdx.x * 128;

    float oac[2][4][4];
#pragma unroll
    for (int i = 0; i < 2; i++)
#pragma unroll
        for (int j = 0; j < 4; j++)
#pragma unroll
            for (int c = 0; c < 4; c++) oac[i][j][c] = 0.f;

    auto load_stage = [&](int kt, int buf) {
        const uint32_t base = sb + buf * OP_BUF;
#pragma unroll
        for (int it = 0; it < 8; it++) {
            int idx = t + it * 512;
            int arr = idx >> 10, rr = (idx >> 3) & 127, cc = idx & 7;
            uint32_t dst = base + arr * 18432 + rr * RS + cc * 16;
            const __nv_bfloat16* src;
            if (arr == 0)      src = whi + (size_t)(o0 + rr) * C_ + kt + cc * 8;
            else if (arr == 1) src = wlo + (size_t)(o0 + rr) * C_ + kt + cc * 8;
            else if (arr == 2) src = aohi + (size_t)(b * N_ + m0 + rr) * C_ + kt + cc * 8;
            else               src = aolo + (size_t)(b * N_ + m0 + rr) * C_ + kt + cc * 8;
            cpasync16(dst, src);
        }
        CP_COMMIT();
    };

    load_stage(0, 0);
    for (int s = 0; s < 4; s++) {
        if (s + 1 < 4) { load_stage((s + 1) * 64, (s + 1) & 1); CP_WAIT(1); }
        else CP_WAIT(0);
        __syncthreads();
        const uint32_t base = sb + (s & 1) * OP_BUF;
        const uint32_t Wh = base + OP_WH + (wm * 32) * RS + oA;
        const uint32_t Wl = base + OP_WL + (wm * 32) * RS + oA;
        const uint32_t Ah = base + OP_AH + (wn * 32) * RS + oB;
        const uint32_t Al = base + OP_AL + (wn * 32) * RS + oB;
#pragma unroll
        for (int ks = 0; ks < 4; ks++) {
            uint32_t awh[2][4], awl[2][4];
#pragma unroll
            for (int mf = 0; mf < 2; mf++) {
                ldsm4(awh[mf], Wh + mf * 16 * RS + ks * 32);
                ldsm4(awl[mf], Wl + mf * 16 * RS + ks * 32);
            }
#pragma unroll
            for (int j = 0; j < 2; j++) {
                uint32_t bh[4], bl[4];
                ldsm4(bh, Ah + j * 16 * RS + ks * 32);
                ldsm4(bl, Al + j * 16 * RS + ks * 32);
#pragma unroll
                for (int h = 0; h < 2; h++) {
                    const int nf = 2 * j + h;
#pragma unroll
                    for (int mf = 0; mf < 2; mf++) {
                        mma16816(oac[mf][nf], awh[mf], &bh[2 * h]);
                        mma16816(oac[mf][nf], awl[mf], &bh[2 * h]);
                        mma16816(oac[mf][nf], awh[mf], &bl[2 * h]);
                    }
                }
            }
        }
        __syncthreads();
    }

#pragma unroll
    for (int mf = 0; mf < 2; mf++) {
        const int rA = o0 + wm * 32 + mf * 16 + g;
        const int rB = rA + 8;
        const float bvA = bo[rA], bvB = bo[rB];
#pragma unroll
        for (int nf = 0; nf < 4; nf++) {
            const int m = m0 + wn * 32 + nf * 8 + 2 * tg;
            size_t iA = (size_t)(b * C_ + rA) * N_ + m;
            size_t iB = (size_t)(b * C_ + rB) * N_ + m;
            float2 xA = *(const float2*)&x[iA];
            float2 xB = *(const float2*)&x[iB];
            *(float2*)&out[iA] = make_float2(oac[mf][nf][0] + bvA + xA.x, oac[mf][nf][1] + bvA + xA.y);
            *(float2*)&out[iB] = make_float2(oac[mf][nf][2] + bvB + xB.x, oac[mf][nf][3] + bvB + xB.y);
        }
    }
}

// ---------------------------------------------------------------------------
extern "C" void kernel_launch(void* const* d_in, const int* in_sizes, int n_in,
                              void* d_out, int out_size)
{
    const float* x  = (const float*)d_in[0];
    const float* wq = (const float*)d_in[1];
    const float* bq = (const float*)d_in[2];
    const float* wk = (const float*)d_in[3];
    const float* bk = (const float*)d_in[4];
    const float* wv = (const float*)d_in[5];
    const float* bv = (const float*)d_in[6];
    const float* wo = (const float*)d_in[7];
    const float* bo = (const float*)d_in[8];
    float* out = (float*)d_out;

    __nv_bfloat16 *gqp, *gkp, *gvh, *gaoh, *gaol, *gwh, *gwl;
    cudaGetSymbolAddress((void**)&gqp,  g_qp);
    cudaGetSymbolAddress((void**)&gkp,  g_kp);
    cudaGetSymbolAddress((void**)&gvh,  g_vhi);
    cudaGetSymbolAddress((void**)&gaoh, g_aohi);
    cudaGetSymbolAddress((void**)&gaol, g_aolo);
    cudaGetSymbolAddress((void**)&gwh,  g_wohi);
    cudaGetSymbolAddress((void**)&gwl,  g_wolo);

    cudaFuncSetAttribute(attn_mma_kernel, cudaFuncAttributeMaxDynamicSharedMemorySize, ATTN_SMEM);
    cudaFuncSetAttribute(oproj_mma_kernel, cudaFuncAttributeMaxDynamicSharedMemorySize, OPROJ_SMEM);

    dim3 blk(256);
    wprep_kernel   <<<C_, C_>>>(wo, gwh, gwl);
    qk2_pack_kernel<<<dim3(N_ / 128, 2, B_), blk>>>(x, wq, bq, wk, bk, gqp, gkp);
    v_proj_kernel  <<<dim3(N_ / 128, C_ / 32, B_), blk>>>(x, wv, bv, gvh);
    attn_mma_kernel<<<dim3(N_ / 64, B_), 256, ATTN_SMEM>>>(gqp, gkp, gvh, gaoh, gaol);
    oproj_mma_kernel<<<dim3(N_ / 128, C_ / 128, B_), 512, OPROJ_SMEM>>>(gaoh, gaol, gwh, gwl, bo, x, out);
}

// round 10
// speedup vs baseline: 4.8104x; 1.4200x over previous
#include <cuda_runtime.h>
#include <cuda_bf16.h>
#include <math.h>
#include <stdint.h>

#define B_ 4
#define C_ 256
#define N_ 4096
#define D_ 32

// ---------------------------------------------------------------------------
// PTX helpers (base sm_100-safe: mma.sync, ldmatrix, cp.async[.bulk], mbarrier)
// ---------------------------------------------------------------------------
__device__ __forceinline__ uint32_t smem_u32(const void* p) {
    uint32_t a;
    asm("{ .reg .u64 t; cvta.to.shared.u64 t, %1; cvt.u32.u64 %0, t; }" : "=r"(a) : "l"(p));
    return a;
}
#define MBARRIER_INIT(a, c) \
    asm volatile("mbarrier.init.shared.b64 [%0], %1;" :: "r"((uint32_t)(a)), "r"((uint32_t)(c)) : "memory")
#define MBARRIER_EXPECT_TX(a, n) \
    asm volatile("mbarrier.arrive.expect_tx.shared.b64 _, [%0], %1;" :: "r"((uint32_t)(a)), "r"((uint32_t)(n)) : "memory")
#define MBARRIER_WAIT_PARITY(a, ph) do { \
    uint32_t _m = (uint32_t)(a); uint32_t _p = (uint32_t)(ph); uint32_t _d; \
    asm volatile("{\n\t.reg .pred p;\n\tmbarrier.try_wait.parity.shared.b64 p, [%1], %2;\n\tselp.b32 %0,1,0,p;\n\t}" \
        : "=r"(_d) : "r"(_m), "r"(_p) : "memory"); \
    if (!_d) { \
        asm volatile("{\n\t.reg .pred P1;\n\tWL_%=:\n\tmbarrier.try_wait.parity.shared.b64 P1, [%0], %1;\n\t@P1 bra.uni WD_%=;\n\tbra.uni WL_%=;\n\tWD_%=:\n\t}" \
            :: "r"(_m), "r"(_p) : "memory"); \
    } } while (0)

__device__ __forceinline__ void cpasync16(uint32_t dst, const void* src) {
    asm volatile("cp.async.cg.shared.global [%0], [%1], 16;" :: "r"(dst), "l"(src) : "memory");
}
#define CP_COMMIT() asm volatile("cp.async.commit_group;" ::: "memory")
#define CP_WAIT(n)  asm volatile("cp.async.wait_group %0;" :: "n"(n) : "memory")

__device__ __forceinline__ void bulk128(uint32_t dst, const void* src, uint32_t mbar) {
    asm volatile("cp.async.bulk.shared::cta.global.mbarrier::complete_tx::bytes [%0], [%1], 128, [%2];"
                 :: "r"(dst), "l"(src), "r"(mbar) : "memory");
}

__device__ __forceinline__ void mma16816(float* d, const uint32_t* a, const uint32_t* b) {
    asm volatile("mma.sync.aligned.m16n8k16.row.col.f32.bf16.bf16.f32 "
                 "{%0,%1,%2,%3}, {%4,%5,%6,%7}, {%8,%9}, {%0,%1,%2,%3};"
                 : "+f"(d[0]), "+f"(d[1]), "+f"(d[2]), "+f"(d[3])
                 : "r"(a[0]), "r"(a[1]), "r"(a[2]), "r"(a[3]), "r"(b[0]), "r"(b[1]));
}
__device__ __forceinline__ void ldsm4(uint32_t* r, uint32_t addr) {
    asm volatile("ldmatrix.sync.aligned.m8n8.x4.shared.b16 {%0,%1,%2,%3}, [%4];"
                 : "=r"(r[0]), "=r"(r[1]), "=r"(r[2]), "=r"(r[3]) : "r"(addr));
}
__device__ __forceinline__ uint32_t pack_bf16x2(float x, float y) {
    __nv_bfloat162 h = __floats2bfloat162_rn(x, y);
    return *(uint32_t*)&h;
}

#define RS 144
__device__ __forceinline__ int aoffA(int lane) { return (lane & 15) * RS + (lane >> 4) * 16; }
__device__ __forceinline__ int aoffB(int lane) { return ((lane & 7) + ((lane >> 4) << 3)) * RS + (lane & 8) * 2; }

// ---------------------------------------------------------------------------
// Scratch
// ---------------------------------------------------------------------------
__device__ __nv_bfloat16 g_qp  [B_*N_*64];   // [b][n][qh(32)|ql(32)]
__device__ __nv_bfloat16 g_kp  [B_*N_*64];
__device__ __nv_bfloat16 g_vhi [B_*C_*N_];   // [b][c][n]
__device__ __nv_bfloat16 g_aohi[B_*N_*C_];   // [b][n][c]
__device__ __nv_bfloat16 g_aolo[B_*N_*C_];
__device__ __nv_bfloat16 g_xth [B_*N_*C_];   // x^T hi  [b][n][c]
__device__ __nv_bfloat16 g_xtl [B_*N_*C_];   // x^T lo
__device__ __nv_bfloat16 g_wohi[C_*C_];
__device__ __nv_bfloat16 g_wolo[C_*C_];
__device__ __nv_bfloat16 g_wvhi[C_*C_];
__device__ __nv_bfloat16 g_wvlo[C_*C_];
__device__ __nv_bfloat16 g_wqhi[D_*C_];
__device__ __nv_bfloat16 g_wqlo[D_*C_];
__device__ __nv_bfloat16 g_wkhi[D_*C_];
__device__ __nv_bfloat16 g_wklo[D_*C_];

// ---------------------------------------------------------------------------
// generic weight hi/lo split
// ---------------------------------------------------------------------------
__global__ void wprep_kernel(const float* __restrict__ w,
                             __nv_bfloat16* __restrict__ hi, __nv_bfloat16* __restrict__ lo)
{
    int i = blockIdx.x * 256 + threadIdx.x;
    float f = w[i];
    __nv_bfloat16 h = __float2bfloat16(f);
    hi[i] = h;
    lo[i] = __float2bfloat16(f - __bfloat162float(h));
}

// ---------------------------------------------------------------------------
// x [b][c][n] fp32 -> xt hi/lo [b][n][c] bf16 (64x64 smem transpose tiles)
// ---------------------------------------------------------------------------
__global__ __launch_bounds__(256)
void xt_pack_kernel(const float* __restrict__ x,
                    __nv_bfloat16* __restrict__ xth, __nv_bfloat16* __restrict__ xtl)
{
    __shared__ float ts[64][65];
    const int b = blockIdx.z, c0 = blockIdx.y * 64, n0 = blockIdx.x * 64;
    const int t = threadIdx.x;
    const int rr = t >> 4, c4 = t & 15;

#pragma unroll
    for (int it = 0; it < 4; it++) {
        int row = it * 16 + rr;                 // c index
        float4 v = *(const float4*)&x[(size_t)(b * C_ + c0 + row) * N_ + n0 + c4 * 4];
        ts[row][c4 * 4 + 0] = v.x;
        ts[row][c4 * 4 + 1] = v.y;
        ts[row][c4 * 4 + 2] = v.z;
        ts[row][c4 * 4 + 3] = v.w;
    }
    __syncthreads();
#pragma unroll
    for (int it = 0; it < 4; it++) {
        int n = it * 16 + rr;                   // token index in tile
        unsigned short hs[4], ls[4];
#pragma unroll
        for (int e = 0; e < 4; e++) {
            float f = ts[c4 * 4 + e][n];
            __nv_bfloat16 h = __float2bfloat16(f);
            hs[e] = __bfloat16_as_ushort(h);
            ls[e] = __bfloat16_as_ushort(__float2bfloat16(f - __bfloat162float(h)));
        }
        size_t base = (size_t)(b * N_ + n0 + n) * C_ + c0 + c4 * 4;
        *(uint2*)&xth[base] = *(uint2*)hs;
        *(uint2*)&xtl[base] = *(uint2*)ls;
    }
}

// ---------------------------------------------------------------------------
// Q+K projection GEMM: [n][o] = xt[n][c] * [wq;wk][o][c], 3-term split bf16.
// CTA: 128 tokens x 64 outs (q 0-31, k 32-63), K=256 fully smem-resident.
// 256 threads: wm = wid>>1 (tokens 32), wn = wid&1 (outs 32).
// smem chunked per 64-col K-chunk with RS=144 rows.
// ---------------------------------------------------------------------------
#define QK_XTH 0
#define QK_XTL 73728
#define QK_WBH 147456
#define QK_WBL 184320
#define QK_SMEM 221184

__global__ __launch_bounds__(256, 1)
void qk_mma_kernel(const __nv_bfloat16* __restrict__ xth, const __nv_bfloat16* __restrict__ xtl,
                   const __nv_bfloat16* __restrict__ wqh, const __nv_bfloat16* __restrict__ wql,
                   const __nv_bfloat16* __restrict__ wkh, const __nv_bfloat16* __restrict__ wkl,
                   const float* __restrict__ bq, const float* __restrict__ bk,
                   __nv_bfloat16* __restrict__ outq, __nv_bfloat16* __restrict__ outk)
{
    extern __shared__ char sm[];
    const uint32_t sb = smem_u32(sm);
    const int t = threadIdx.x;
    const int wid = t >> 5, lane = t & 31;
    const int g = lane >> 2, tg = lane & 3;
    const int oA = aoffA(lane), oB = aoffB(lane);
    const int wm = wid >> 1, wn = wid & 1;
    const int b = blockIdx.y, n0 = blockIdx.x * 128;

    // load xt tiles (128 rows x 32 16B-chunks each, chunked layout)
#pragma unroll
    for (int it = 0; it < 16; it++) {
        int idx = t + it * 256;
        int r = idx >> 5, cc = idx & 31;
        uint32_t off = (cc >> 3) * 18432 + r * RS + (cc & 7) * 16;
        size_t src = (size_t)(b * N_ + n0 + r) * C_ + cc * 8;
        cpasync16(sb + QK_XTH + off, xth + src);
        cpasync16(sb + QK_XTL + off, xtl + src);
    }
    // load stacked weights [wq(32); wk(32)] hi/lo
#pragma unroll
    for (int it = 0; it < 8; it++) {
        int idx = t + it * 256;
        int o = idx >> 5, cc = idx & 31;
        uint32_t off = (cc >> 3) * 9216 + o * RS + (cc & 7) * 16;
        const __nv_bfloat16* sh = (o < 32) ? (wqh + (size_t)o * C_) : (wkh + (size_t)(o - 32) * C_);
        const __nv_bfloat16* sl = (o < 32) ? (wql + (size_t)o * C_) : (wkl + (size_t)(o - 32) * C_);
        cpasync16(sb + QK_WBH + off, sh + cc * 8);
        cpasync16(sb + QK_WBL + off, sl + cc * 8);
    }
    CP_COMMIT();
    CP_WAIT(0);
    __syncthreads();

    float oac[2][4][4];
#pragma unroll
    for (int i = 0; i < 2; i++)
#pragma unroll
        for (int j = 0; j < 4; j++)
#pragma unroll
            for (int c = 0; c < 4; c++) oac[i][j][c] = 0.f;

#pragma unroll
    for (int kc = 0; kc < 4; kc++) {
#pragma unroll
        for (int ks = 0; ks < 4; ks++) {
            uint32_t ah[2][4], al[2][4];
#pragma unroll
            for (int mf = 0; mf < 2; mf++) {
                uint32_t ab = (wm * 32 + mf * 16) * RS + ks * 32 + oA;
                ldsm4(ah[mf], sb + QK_XTH + kc * 18432 + ab);
                ldsm4(al[mf], sb + QK_XTL + kc * 18432 + ab);
            }
#pragma unroll
            for (int j = 0; j < 2; j++) {
                uint32_t bh[4], bl[4];
                uint32_t bb = (wn * 32 + j * 16) * RS + ks * 32 + oB;
                ldsm4(bh, sb + QK_WBH + kc * 9216 + bb);
                ldsm4(bl, sb + QK_WBL + kc * 9216 + bb);
#pragma unroll
                for (int h = 0; h < 2; h++)
#pragma unroll
                    for (int mf = 0; mf < 2; mf++) {
                        mma16816(oac[mf][j * 2 + h], ah[mf], &bh[2 * h]);
                        mma16816(oac[mf][j * 2 + h], al[mf], &bh[2 * h]);
                        mma16816(oac[mf][j * 2 + h], ah[mf], &bl[2 * h]);
                    }
            }
        }
    }

    // epilogue: +bias, split hi/lo, write packed rows
#pragma unroll
    for (int mf = 0; mf < 2; mf++) {
        const int rA = wm * 32 + mf * 16 + g;
        const int rB = rA + 8;
#pragma unroll
        for (int hh = 0; hh < 4; hh++) {
            int o = wn * 32 + hh * 8 + 2 * tg;
            bool isq = (o < 32);
            int oo = isq ? o : (o - 32);
            float bb0 = isq ? bq[oo] : bk[oo];
            float bb1 = isq ? bq[oo + 1] : bk[oo + 1];
            float d0 = oac[mf][hh][0] + bb0, d1 = oac[mf][hh][1] + bb1;
            float d2 = oac[mf][hh][2] + bb0, d3 = oac[mf][hh][3] + bb1;
            __nv_bfloat16* dst = isq ? outq : outk;
            uint32_t hA = pack_bf16x2(d0, d1);
            uint32_t hB = pack_bf16x2(d2, d3);
            __nv_bfloat162 vA = *(__nv_bfloat162*)&hA;
            __nv_bfloat162 vB = *(__nv_bfloat162*)&hB;
            size_t baseA = (size_t)(b * N_ + n0 + rA) * 64;
            size_t baseB = (size_t)(b * N_ + n0 + rB) * 64;
            *(uint32_t*)&dst[baseA + oo]      = hA;
            *(uint32_t*)&dst[baseA + 32 + oo] =
                pack_bf16x2(d0 - __bfloat162float(vA.x), d1 - __bfloat162float(vA.y));
            *(uint32_t*)&dst[baseB + oo]      = hB;
            *(uint32_t*)&dst[baseB + 32 + oo] =
                pack_bf16x2(d2 - __bfloat162float(vB.x), d3 - __bfloat162float(vB.y));
        }
    }
}

// ---------------------------------------------------------------------------
// V projection GEMM (oproj clone): vhi[c][n] = bf16(wv*x + bv)
// ---------------------------------------------------------------------------
#define OP_WH 0
#define OP_WL 18432
#define OP_AH 36864
#define OP_AL 55296
#define OP_BUF 73728
#define OPROJ_SMEM 147456

__global__ __launch_bounds__(512, 1)
void v_mma_kernel(const __nv_bfloat16* __restrict__ xth, const __nv_bfloat16* __restrict__ xtl,
                  const __nv_bfloat16* __restrict__ wvh, const __nv_bfloat16* __restrict__ wvl,
                  const float* __restrict__ bv,
                  __nv_bfloat16* __restrict__ vhi)
{
    extern __shared__ char sm[];
    const uint32_t sb = smem_u32(sm);
    const int t = threadIdx.x;
    const int wid = t >> 5, lane = t & 31;
    const int g = lane >> 2, tg = lane & 3;
    const int oA = aoffA(lane), oB = aoffB(lane);
    const int wm = wid >> 2, wn = wid & 3;
    const int b = blockIdx.z, o0 = blockIdx.y * 128, m0 = blockIdx.x * 128;

    float oac[2][4][4];
#pragma unroll
    for (int i = 0; i < 2; i++)
#pragma unroll
        for (int j = 0; j < 4; j++)
#pragma unroll
            for (int c = 0; c < 4; c++) oac[i][j][c] = 0.f;

    auto load_stage = [&](int kt, int buf) {
        const uint32_t base = sb + buf * OP_BUF;
#pragma unroll
        for (int it = 0; it < 8; it++) {
            int idx = t + it * 512;
            int arr = idx >> 10, rr = (idx >> 3) & 127, cc = idx & 7;
            uint32_t dst = base + arr * 18432 + rr * RS + cc * 16;
            const __nv_bfloat16* src;
            if (arr == 0)      src = wvh + (size_t)(o0 + rr) * C_ + kt + cc * 8;
            else if (arr == 1) src = wvl + (size_t)(o0 + rr) * C_ + kt + cc * 8;
            else if (arr == 2) src = xth + (size_t)(b * N_ + m0 + rr) * C_ + kt + cc * 8;
            else               src = xtl + (size_t)(b * N_ + m0 + rr) * C_ + kt + cc * 8;
            cpasync16(dst, src);
        }
        CP_COMMIT();
    };

    load_stage(0, 0);
    for (int s = 0; s < 4; s++) {
        if (s + 1 < 4) { load_stage((s + 1) * 64, (s + 1) & 1); CP_WAIT(1); }
        else CP_WAIT(0);
        __syncthreads();
        const uint32_t base = sb + (s & 1) * OP_BUF;
        const uint32_t Wh = base + OP_WH + (wm * 32) * RS + oA;
        const uint32_t Wl = base + OP_WL + (wm * 32) * RS + oA;
        const uint32_t Ah = base + OP_AH + (wn * 32) * RS + oB;
        const uint32_t Al = base + OP_AL + (wn * 32) * RS + oB;
#pragma unroll
        for (int ks = 0; ks < 4; ks++) {
            uint32_t awh[2][4], awl[2][4];
#pragma unroll
            for (int mf = 0; mf < 2; mf++) {
                ldsm4(awh[mf], Wh + mf * 16 * RS + ks * 32);
                ldsm4(awl[mf], Wl + mf * 16 * RS + ks * 32);
            }
#pragma unroll
            for (int j = 0; j < 2; j++) {
                uint32_t bh[4], bl[4];
                ldsm4(bh, Ah + j * 16 * RS + ks * 32);
                ldsm4(bl, Al + j * 16 * RS + ks * 32);
#pragma unroll
                for (int h = 0; h < 2; h++) {
                    const int nf = 2 * j + h;
#pragma unroll
                    for (int mf = 0; mf < 2; mf++) {
                        mma16816(oac[mf][nf], awh[mf], &bh[2 * h]);
                        mma16816(oac[mf][nf], awl[mf], &bh[2 * h]);
                        mma16816(oac[mf][nf], awh[mf], &bl[2 * h]);
                    }
                }
            }
        }
        __syncthreads();
    }

    // epilogue: +bv, bf16 store [c][n]
#pragma unroll
    for (int mf = 0; mf < 2; mf++) {
        const int rA = o0 + wm * 32 + mf * 16 + g;
        const int rB = rA + 8;
        const float bvA = bv[rA], bvB = bv[rB];
#pragma unroll
        for (int nf = 0; nf < 4; nf++) {
            const int m = m0 + wn * 32 + nf * 8 + 2 * tg;
            *(uint32_t*)&vhi[(size_t)(b * C_ + rA) * N_ + m] =
                pack_bf16x2(oac[mf][nf][0] + bvA, oac[mf][nf][1] + bvA);
            *(uint32_t*)&vhi[(size_t)(b * C_ + rB) * N_ + m] =
                pack_bf16x2(oac[mf][nf][2] + bvB, oac[mf][nf][3] + bvB);
        }
    }
}

// ---------------------------------------------------------------------------
// Flash attention (unchanged from R9): 2 CTAs/SM, single-term PV with
// consistent rounded-p lsum.
// ---------------------------------------------------------------------------
#define OFF_LSUM 64
#define OFF_Q    1024
#define OFF_K    10240
#define OFF_PH   19456
#define OFF_VH0  28672
#define OFF_VH1  65536
#define ATTN_SMEM 102400
#define K_TX 8192
#define V_TX 32768

__global__ __launch_bounds__(256, 2)
void attn_mma_kernel(const __nv_bfloat16* __restrict__ qp,
                     const __nv_bfloat16* __restrict__ kp,
                     const __nv_bfloat16* __restrict__ vhi,
                     __nv_bfloat16* __restrict__ aohi,
                     __nv_bfloat16* __restrict__ aolo)
{
    extern __shared__ char sm[];
    const uint32_t sb = smem_u32(sm);
    const int t = threadIdx.x;
    const int wid = t >> 5, lane = t & 31;
    const int g = lane >> 2, tg = lane & 3;
    const int oA = aoffA(lane), oB = aoffB(lane);
    const int wm = wid >> 2, wn = wid & 3;
    const int rowA = wm * 32;
    const int kb = wn * 16;
    const int b = blockIdx.y, m0 = blockIdx.x * 64;

    const __nv_bfloat16* qp_b = qp + (size_t)b * N_ * 64;
    const __nv_bfloat16* kp_b = kp + (size_t)b * N_ * 64;
    const __nv_bfloat16* vh_b = vhi + (size_t)b * C_ * N_;

    float* lsum_s = (float*)(sm + OFF_LSUM);
    if (t == 0) {
        MBARRIER_INIT(sb + 0, 1);
        MBARRIER_INIT(sb + 8, 1);
        MBARRIER_INIT(sb + 16, 1);
    }
    if (t < 64) lsum_s[t] = 0.f;

#pragma unroll
    for (int i = 0; i < 2; i++) {
        int idx = t + i * 256;
        int r = idx >> 3, ch = idx & 7;
        cpasync16(sb + OFF_Q + r * RS + ch * 16, qp_b + (size_t)(m0 + r) * 64 + ch * 8);
        cpasync16(sb + OFF_K + r * RS + ch * 16, kp_b + (size_t)r * 64 + ch * 8);
    }
    CP_COMMIT();
    __syncthreads();

    if (t == 0) MBARRIER_EXPECT_TX(sb + 8, V_TX);
    bulk128(sb + OFF_VH0 + t * RS, vh_b + (size_t)t * N_, sb + 8);

    CP_WAIT(0);
    __syncthreads();

    uint32_t qfh[2][2][4];
#pragma unroll
    for (int mf = 0; mf < 2; mf++)
#pragma unroll
        for (int c = 0; c < 2; c++)
            ldsm4(qfh[mf][c], sb + OFF_Q + (rowA + mf * 16) * RS + c * 32 + oA);

    const uint32_t sbPH = sb + OFF_PH, sbQ = sb + OFF_Q;

    float sacc[2][2][4];
    float oacc[2][8][4];
#pragma unroll
    for (int i = 0; i < 2; i++)
#pragma unroll
        for (int j = 0; j < 8; j++)
#pragma unroll
            for (int c = 0; c < 4; c++) oacc[i][j][c] = 0.f;
    float lpart[2][2] = {{0.f, 0.f}, {0.f, 0.f}};
    int kcnt = 0, vcnt0 = 0, vcnt1 = 0;

    auto do_smma = [&]() {
#pragma unroll
        for (int a = 0; a < 2; a++)
#pragma unroll
            for (int j2 = 0; j2 < 2; j2++)
#pragma unroll
                for (int c = 0; c < 4; c++) sacc[a][j2][c] = 0.f;
        const uint32_t Kb = sb + OFF_K + kb * RS + oB;
        uint32_t bK[4];
        ldsm4(bK, Kb + 0);
#pragma unroll
        for (int mf = 0; mf < 2; mf++) { mma16816(sacc[mf][0], qfh[mf][0], &bK[0]); mma16816(sacc[mf][1], qfh[mf][0], &bK[2]); }
        {
            uint32_t ql[4];
#pragma unroll
            for (int mf = 0; mf < 2; mf++) {
                ldsm4(ql, sbQ + (rowA + mf * 16) * RS + 64 + oA);
                mma16816(sacc[mf][0], ql, &bK[0]); mma16816(sacc[mf][1], ql, &bK[2]);
            }
        }
        ldsm4(bK, Kb + 32);
#pragma unroll
        for (int mf = 0; mf < 2; mf++) { mma16816(sacc[mf][0], qfh[mf][1], &bK[0]); mma16816(sacc[mf][1], qfh[mf][1], &bK[2]); }
        {
            uint32_t ql[4];
#pragma unroll
            for (int mf = 0; mf < 2; mf++) {
                ldsm4(ql, sbQ + (rowA + mf * 16) * RS + 96 + oA);
                mma16816(sacc[mf][0], ql, &bK[0]); mma16816(sacc[mf][1], ql, &bK[2]);
            }
        }
        ldsm4(bK, Kb + 64);
#pragma unroll
        for (int mf = 0; mf < 2; mf++) { mma16816(sacc[mf][0], qfh[mf][0], &bK[0]); mma16816(sacc[mf][1], qfh[mf][0], &bK[2]); }
        ldsm4(bK, Kb + 96);
#pragma unroll
        for (int mf = 0; mf < 2; mf++) { mma16816(sacc[mf][0], qfh[mf][1], &bK[0]); mma16816(sacc[mf][1], qfh[mf][1], &bK[2]); }
    };

    auto do_softmax = [&]() {
#pragma unroll
        for (int mf = 0; mf < 2; mf++) {
            const int r0 = rowA + mf * 16 + g;
#pragma unroll
            for (int nf = 0; nf < 2; nf++) {
                const int cb = kb + nf * 8 + 2 * tg;
                float p0 = __expf(fminf(sacc[mf][nf][0], 60.f));
                float p1 = __expf(fminf(sacc[mf][nf][1], 60.f));
                float p2 = __expf(fminf(sacc[mf][nf][2], 60.f));
                float p3 = __expf(fminf(sacc[mf][nf][3], 60.f));
                uint32_t hA = pack_bf16x2(p0, p1);
                uint32_t hB = pack_bf16x2(p2, p3);
                __nv_bfloat162 hv0 = *(__nv_bfloat162*)&hA;
                __nv_bfloat162 hv1 = *(__nv_bfloat162*)&hB;
                lpart[mf][0] += __bfloat162float(hv0.x) + __bfloat162float(hv0.y);
                lpart[mf][1] += __bfloat162float(hv1.x) + __bfloat162float(hv1.y);
                *(uint32_t*)(sm + OFF_PH + r0 * RS + cb * 2) = hA;
                *(uint32_t*)(sm + OFF_PH + (r0 + 8) * RS + cb * 2) = hB;
            }
        }
    };

    auto do_pv = [&](uint32_t Vb) {
#pragma unroll
        for (int kk = 0; kk < 4; kk++) {
            uint32_t aH[2][4];
#pragma unroll
            for (int mf = 0; mf < 2; mf++)
                ldsm4(aH[mf], sbPH + (rowA + mf * 16) * RS + kk * 32 + oA);
#pragma unroll
            for (int j = 0; j < 4; j++) {
                uint32_t bV[4];
                ldsm4(bV, Vb + (wn * 64 + j * 16) * RS + kk * 32 + oB);
#pragma unroll
                for (int mf = 0; mf < 2; mf++) {
                    mma16816(oacc[mf][2 * j],     aH[mf], &bV[0]);
                    mma16816(oacc[mf][2 * j + 1], aH[mf], &bV[2]);
                }
            }
        }
    };

    do_smma();
    __syncthreads();

    if (t == 0) { MBARRIER_EXPECT_TX(sb + 0, K_TX); MBARRIER_EXPECT_TX(sb + 16, V_TX); }
    if (t < 64) bulk128(sb + OFF_K + t * RS, kp_b + (size_t)(64 + t) * 64, sb + 0);
    bulk128(sb + OFF_VH1 + t * RS, vh_b + (size_t)t * N_ + 64, sb + 16);

    for (int i = 0; i < 64; i++) {
        do_softmax();
        __syncthreads();

        if (i + 1 < 64) {
            MBARRIER_WAIT_PARITY(sb + 0, kcnt & 1); kcnt++;
            do_smma();
        }
        if (i & 1) { MBARRIER_WAIT_PARITY(sb + 16, vcnt1 & 1); vcnt1++; }
        else       { MBARRIER_WAIT_PARITY(sb + 8,  vcnt0 & 1); vcnt0++; }
        do_pv(sb + ((i & 1) ? OFF_VH1 : OFF_VH0));
        __syncthreads();

        if (i + 2 < 64) {
            const int nn = (i + 2) * 64;
            const uint32_t vdst = sb + ((i & 1) ? OFF_VH1 : OFF_VH0);
            const uint32_t vmb  = sb + 8 + (i & 1) * 8;
            if (t == 0) { MBARRIER_EXPECT_TX(sb + 0, K_TX); MBARRIER_EXPECT_TX(vmb, V_TX); }
            if (t < 64) bulk128(sb + OFF_K + t * RS, kp_b + (size_t)(nn + t) * 64, sb + 0);
            bulk128(vdst + t * RS, vh_b + (size_t)t * N_ + nn, vmb);
        }
    }

#pragma unroll
    for (int mf = 0; mf < 2; mf++) {
        atomicAdd(&lsum_s[rowA + mf * 16 + g],     lpart[mf][0]);
        atomicAdd(&lsum_s[rowA + mf * 16 + 8 + g], lpart[mf][1]);
    }
    __syncthreads();

#pragma unroll
    for (int mf = 0; mf < 2; mf++) {
        const int rA = rowA + mf * 16 + g;
        const int rB = rA + 8;
        const float invA = 1.f / lsum_s[rA];
        const float invB = 1.f / lsum_s[rB];
        __nv_bfloat16* hA = aohi + (size_t)(b * N_ + m0 + rA) * C_;
        __nv_bfloat16* hB = aohi + (size_t)(b * N_ + m0 + rB) * C_;
        __nv_bfloat16* lA = aolo + (size_t)(b * N_ + m0 + rA) * C_;
        __nv_bfloat16* lB = aolo + (size_t)(b * N_ + m0 + rB) * C_;
#pragma unroll
        for (int nf = 0; nf < 8; nf++) {
            const int cb = wn * 64 + nf * 8 + 2 * tg;
            float a0 = oacc[mf][nf][0] * invA, a1 = oacc[mf][nf][1] * invA;
            float b0v = oacc[mf][nf][2] * invB, b1v = oacc[mf][nf][3] * invB;
            uint32_t ha = pack_bf16x2(a0, a1);
            uint32_t hb = pack_bf16x2(b0v, b1v);
            __nv_bfloat162 va = *(__nv_bfloat162*)&ha;
            __nv_bfloat162 vb = *(__nv_bfloat162*)&hb;
            *(uint32_t*)(hA + cb) = ha;
            *(uint32_t*)(hB + cb) = hb;
            *(uint32_t*)(lA + cb) = pack_bf16x2(a0 - __bfloat162float(va.x), a1 - __bfloat162float(va.y));
            *(uint32_t*)(lB + cb) = pack_bf16x2(b0v - __bfloat162float(vb.x), b1v - __bfloat162float(vb.y));
        }
    }
}

// ---------------------------------------------------------------------------
// Output projection (unchanged): out = wo*AO + bo + x
// ---------------------------------------------------------------------------
__global__ __launch_bounds__(512, 1)
void oproj_mma_kernel(const __nv_bfloat16* __restrict__ aohi,
                      const __nv_bfloat16* __restrict__ aolo,
                      const __nv_bfloat16* __restrict__ whi,
                      const __nv_bfloat16* __restrict__ wlo,
                      const float* __restrict__ bo,
                      const float* __restrict__ x,
                      float* __restrict__ out)
{
    extern __shared__ char sm[];
    const uint32_t sb = smem_u32(sm);
    const int t = threadIdx.x;
    const int wid = t >> 5, lane = t & 31;
    const int g = lane >> 2, tg = lane & 3;
    const int oA = aoffA(lane), oB = aoffB(lane);
    const int wm = wid >> 2, wn = wid & 3;
    const int b = blockIdx.z, o0 = blockIdx.y * 128, m0 = blockIdx.x * 128;

    float oac[2][4][4];
#pragma unroll
    for (int i = 0; i < 2; i++)
#pragma unroll
        for (int j = 0; j < 4; j++)
#pragma unroll
            for (int c = 0; c < 4; c++) oac[i][j][c] = 0.f;

    auto load_stage = [&](int kt, int buf) {
        const uint32_t base = sb + buf * OP_BUF;
#pragma unroll
        for (int it = 0; it < 8; it++) {
            int idx = t + it * 512;
            int arr = idx >> 10, rr = (idx >> 3) & 127, cc = idx & 7;
            uint32_t dst = base + arr * 18432 + rr * RS + cc * 16;
            const __nv_bfloat16* src;
            if (arr == 0)      src = whi + (size_t)(o0 + rr) * C_ + kt + cc * 8;
            else if (arr == 1) src = wlo + (size_t)(o0 + rr) * C_ + kt + cc * 8;
            else if (arr == 2) src = aohi + (size_t)(b * N_ + m0 + rr) * C_ + kt + cc * 8;
            else               src = aolo + (size_t)(b * N_ + m0 + rr) * C_ + kt + cc * 8;
            cpasync16(dst, src);
        }
        CP_COMMIT();
    };

    load_stage(0, 0);
    for (int s = 0; s < 4; s++) {
        if (s + 1 < 4) { load_stage((s + 1) * 64, (s + 1) & 1); CP_WAIT(1); }
        else CP_WAIT(0);
        __syncthreads();
        const uint32_t base = sb + (s & 1) * OP_BUF;
        const uint32_t Wh = base + OP_WH + (wm * 32) * RS + oA;
        const uint32_t Wl = base + OP_WL + (wm * 32) * RS + oA;
        const uint32_t Ah = base + OP_AH + (wn * 32) * RS + oB;
        const uint32_t Al = base + OP_AL + (wn * 32) * RS + oB;
#pragma unroll
        for (int ks = 0; ks < 4; ks++) {
            uint32_t awh[2][4], awl[2][4];
#pragma unroll
            for (int mf = 0; mf < 2; mf++) {
                ldsm4(awh[mf], Wh + mf * 16 * RS + ks * 32);
                ldsm4(awl[mf], Wl + mf * 16 * RS + ks * 32);
            }
#pragma unroll
            for (int j = 0; j < 2; j++) {
                uint32_t bh[4], bl[4];
                ldsm4(bh, Ah + j * 16 * RS + ks * 32);
                ldsm4(bl, Al + j * 16 * RS + ks * 32);
#pragma unroll
                for (int h = 0; h < 2; h++) {
                    const int nf = 2 * j + h;
#pragma unroll
                    for (int mf = 0; mf < 2; mf++) {
                        mma16816(oac[mf][nf], awh[mf], &bh[2 * h]);
                        mma16816(oac[mf][nf], awl[mf], &bh[2 * h]);
                        mma16816(oac[mf][nf], awh[mf], &bl[2 * h]);
                    }
                }
            }
        }
        __syncthreads();
    }

#pragma unroll
    for (int mf = 0; mf < 2; mf++) {
        const int rA = o0 + wm * 32 + mf * 16 + g;
        const int rB = rA + 8;
        const float bvA = bo[rA], bvB = bo[rB];
#pragma unroll
        for (int nf = 0; nf < 4; nf++) {
            const int m = m0 + wn * 32 + nf * 8 + 2 * tg;
            size_t iA = (size_t)(b * C_ + rA) * N_ + m;
            size_t iB = (size_t)(b * C_ + rB) * N_ + m;
            float2 xA = *(const float2*)&x[iA];
            float2 xB = *(const float2*)&x[iB];
            *(float2*)&out[iA] = make_float2(oac[mf][nf][0] + bvA + xA.x, oac[mf][nf][1] + bvA + xA.y);
            *(float2*)&out[iB] = make_float2(oac[mf][nf][2] + bvB + xB.x, oac[mf][nf][3] + bvB + xB.y);
        }
    }
}

// ---------------------------------------------------------------------------
extern "C" void kernel_launch(void* const* d_in, const int* in_sizes, int n_in,
                              void* d_out, int out_size)
{
    const float* x  = (const float*)d_in[0];
    const float* wq = (const float*)d_in[1];
    const float* bq = (const float*)d_in[2];
    const float* wk = (const float*)d_in[3];
    const float* bk = (const float*)d_in[4];
    const float* wv = (const float*)d_in[5];
    const float* bv = (const float*)d_in[6];
    const float* wo = (const float*)d_in[7];
    const float* bo = (const float*)d_in[8];
    float* out = (float*)d_out;

    __nv_bfloat16 *gqp, *gkp, *gvh, *gaoh, *gaol, *gxth, *gxtl;
    __nv_bfloat16 *gwoh, *gwol, *gwvh, *gwvl, *gwqh, *gwql, *gwkh, *gwkl;
    cudaGetSymbolAddress((void**)&gqp,  g_qp);
    cudaGetSymbolAddress((void**)&gkp,  g_kp);
    cudaGetSymbolAddress((void**)&gvh,  g_vhi);
    cudaGetSymbolAddress((void**)&gaoh, g_aohi);
    cudaGetSymbolAddress((void**)&gaol, g_aolo);
    cudaGetSymbolAddress((void**)&gxth, g_xth);
    cudaGetSymbolAddress((void**)&gxtl, g_xtl);
    cudaGetSymbolAddress((void**)&gwoh, g_wohi);
    cudaGetSymbolAddress((void**)&gwol, g_wolo);
    cudaGetSymbolAddress((void**)&gwvh, g_wvhi);
    cudaGetSymbolAddress((void**)&gwvl, g_wvlo);
    cudaGetSymbolAddress((void**)&gwqh, g_wqhi);
    cudaGetSymbolAddress((void**)&gwql, g_wqlo);
    cudaGetSymbolAddress((void**)&gwkh, g_wkhi);
    cudaGetSymbolAddress((void**)&gwkl, g_wklo);

    cudaFuncSetAttribute(attn_mma_kernel, cudaFuncAttributeMaxDynamicSharedMemorySize, ATTN_SMEM);
    cudaFuncSetAttribute(oproj_mma_kernel, cudaFuncAttributeMaxDynamicSharedMemorySize, OPROJ_SMEM);
    cudaFuncSetAttribute(v_mma_kernel, cudaFuncAttributeMaxDynamicSharedMemorySize, OPROJ_SMEM);
    cudaFuncSetAttribute(qk_mma_kernel, cudaFuncAttributeMaxDynamicSharedMemorySize, QK_SMEM);

    wprep_kernel<<<C_ * C_ / 256, 256>>>(wo, gwoh, gwol);
    wprep_kernel<<<C_ * C_ / 256, 256>>>(wv, gwvh, gwvl);
    wprep_kernel<<<D_ * C_ / 256, 256>>>(wq, gwqh, gwql);
    wprep_kernel<<<D_ * C_ / 256, 256>>>(wk, gwkh, gwkl);
    xt_pack_kernel<<<dim3(N_ / 64, C_ / 64, B_), 256>>>(x, gxth, gxtl);
    qk_mma_kernel<<<dim3(N_ / 128, B_), 256, QK_SMEM>>>(
        gxth, gxtl, gwqh, gwql, gwkh, gwkl, bq, bk, gqp, gkp);
    v_mma_kernel<<<dim3(N_ / 128, C_ / 128, B_), 512, OPROJ_SMEM>>>(
        gxth, gxtl, gwvh, gwvl, bv, gvh);
    attn_mma_kernel<<<dim3(N_ / 64, B_), 256, ATTN_SMEM>>>(gqp, gkp, gvh, gaoh, gaol);
    oproj_mma_kernel<<<dim3(N_ / 128, C_ / 128, B_), 512, OPROJ_SMEM>>>(
        gaoh, gaol, gwoh, gwol, bo, x, out);
}

// round 11
// speedup vs baseline: 6.6038x; 1.3728x over previous
#include <cuda_runtime.h>
#include <cuda_bf16.h>
#include <math.h>
#include <stdint.h>

#define B_ 4
#define C_ 256
#define N_ 4096
#define D_ 32
#define LOG2E 1.4426950408889634f

// ---------------------------------------------------------------------------
// PTX helpers (base sm_100-safe)
// ---------------------------------------------------------------------------
__device__ __forceinline__ uint32_t smem_u32(const void* p) {
    uint32_t a;
    asm("{ .reg .u64 t; cvta.to.shared.u64 t, %1; cvt.u32.u64 %0, t; }" : "=r"(a) : "l"(p));
    return a;
}
#define MBARRIER_INIT(a, c) \
    asm volatile("mbarrier.init.shared.b64 [%0], %1;" :: "r"((uint32_t)(a)), "r"((uint32_t)(c)) : "memory")
#define MBARRIER_EXPECT_TX(a, n) \
    asm volatile("mbarrier.arrive.expect_tx.shared.b64 _, [%0], %1;" :: "r"((uint32_t)(a)), "r"((uint32_t)(n)) : "memory")
#define MBARRIER_WAIT_PARITY(a, ph) do { \
    uint32_t _m = (uint32_t)(a); uint32_t _p = (uint32_t)(ph); uint32_t _d; \
    asm volatile("{\n\t.reg .pred p;\n\tmbarrier.try_wait.parity.shared.b64 p, [%1], %2;\n\tselp.b32 %0,1,0,p;\n\t}" \
        : "=r"(_d) : "r"(_m), "r"(_p) : "memory"); \
    if (!_d) { \
        asm volatile("{\n\t.reg .pred P1;\n\tWL_%=:\n\tmbarrier.try_wait.parity.shared.b64 P1, [%0], %1;\n\t@P1 bra.uni WD_%=;\n\tbra.uni WL_%=;\n\tWD_%=:\n\t}" \
            :: "r"(_m), "r"(_p) : "memory"); \
    } } while (0)

__device__ __forceinline__ void cpasync16(uint32_t dst, const void* src) {
    asm volatile("cp.async.cg.shared.global [%0], [%1], 16;" :: "r"(dst), "l"(src) : "memory");
}
#define CP_COMMIT() asm volatile("cp.async.commit_group;" ::: "memory")
#define CP_WAIT(n)  asm volatile("cp.async.wait_group %0;" :: "n"(n) : "memory")

__device__ __forceinline__ void bulkcp(uint32_t dst, const void* src, uint32_t bytes, uint32_t mbar) {
    asm volatile("cp.async.bulk.shared::cta.global.mbarrier::complete_tx::bytes [%0], [%1], %2, [%3];"
                 :: "r"(dst), "l"(src), "r"(bytes), "r"(mbar) : "memory");
}

__device__ __forceinline__ void mma16816(float* d, const uint32_t* a, const uint32_t* b) {
    asm volatile("mma.sync.aligned.m16n8k16.row.col.f32.bf16.bf16.f32 "
                 "{%0,%1,%2,%3}, {%4,%5,%6,%7}, {%8,%9}, {%0,%1,%2,%3};"
                 : "+f"(d[0]), "+f"(d[1]), "+f"(d[2]), "+f"(d[3])
                 : "r"(a[0]), "r"(a[1]), "r"(a[2]), "r"(a[3]), "r"(b[0]), "r"(b[1]));
}
__device__ __forceinline__ void ldsm4(uint32_t* r, uint32_t addr) {
    asm volatile("ldmatrix.sync.aligned.m8n8.x4.shared.b16 {%0,%1,%2,%3}, [%4];"
                 : "=r"(r[0]), "=r"(r[1]), "=r"(r[2]), "=r"(r[3]) : "r"(addr));
}
__device__ __forceinline__ uint32_t pack_bf16x2(float x, float y) {
    __nv_bfloat162 h = __floats2bfloat162_rn(x, y);
    return *(uint32_t*)&h;
}

#define RS 144
__device__ __forceinline__ int aoffA(int lane) { return (lane & 15) * RS + (lane >> 4) * 16; }
__device__ __forceinline__ int aoffB(int lane) { return ((lane & 7) + ((lane >> 4) << 3)) * RS + (lane & 8) * 2; }

// ---------------------------------------------------------------------------
// Scratch.  Tiled, pre-swizzled blobs for attention operands:
//   g_qt/g_kt: [b][tile(64)][64 rows x 128B]  (row = qh(32)|ql(32) bf16, SW128)
//   g_vt:      [b][tile(64)][256 ch x 128B]   (row = 64 keys bf16, SW128)
// ---------------------------------------------------------------------------
__device__ char          g_qt  [B_*64*64*128];
__device__ char          g_kt  [B_*64*64*128];
__device__ char          g_vt  [(size_t)B_*64*256*128];
__device__ __nv_bfloat16 g_aohi[B_*N_*C_];
__device__ __nv_bfloat16 g_aolo[B_*N_*C_];
__device__ __nv_bfloat16 g_xth [B_*N_*C_];
__device__ __nv_bfloat16 g_xtl [B_*N_*C_];
__device__ __nv_bfloat16 g_wohi[C_*C_];
__device__ __nv_bfloat16 g_wolo[C_*C_];
__device__ __nv_bfloat16 g_wvhi[C_*C_];
__device__ __nv_bfloat16 g_wvlo[C_*C_];
__device__ __nv_bfloat16 g_wqhi[D_*C_];
__device__ __nv_bfloat16 g_wqlo[D_*C_];
__device__ __nv_bfloat16 g_wkhi[D_*C_];
__device__ __nv_bfloat16 g_wklo[D_*C_];

// ---------------------------------------------------------------------------
// all weight splits in ONE launch; wq scaled by log2(e)
// ---------------------------------------------------------------------------
__global__ void wprep_all_kernel(const float* __restrict__ wo, const float* __restrict__ wv,
                                 const float* __restrict__ wq, const float* __restrict__ wk,
                                 __nv_bfloat16* __restrict__ woh, __nv_bfloat16* __restrict__ wol,
                                 __nv_bfloat16* __restrict__ wvh, __nv_bfloat16* __restrict__ wvl,
                                 __nv_bfloat16* __restrict__ wqh, __nv_bfloat16* __restrict__ wql,
                                 __nv_bfloat16* __restrict__ wkh, __nv_bfloat16* __restrict__ wkl)
{
    int which = blockIdx.y;
    int i = blockIdx.x * 256 + threadIdx.x;
    const float* src; __nv_bfloat16 *hi, *lo; float scale = 1.f;
    if (which == 0)      { src = wo; hi = woh; lo = wol; }
    else if (which == 1) { src = wv; hi = wvh; lo = wvl; }
    else if (which == 2) { if (i >= D_ * C_) return; src = wq; hi = wqh; lo = wql; scale = LOG2E; }
    else                 { if (i >= D_ * C_) return; src = wk; hi = wkh; lo = wkl; }
    float f = src[i] * scale;
    __nv_bfloat16 h = __float2bfloat16(f);
    hi[i] = h;
    lo[i] = __float2bfloat16(f - __bfloat162float(h));
}

// ---------------------------------------------------------------------------
// x [b][c][n] fp32 -> xt hi/lo [b][n][c] bf16
// ---------------------------------------------------------------------------
__global__ __launch_bounds__(256)
void xt_pack_kernel(const float* __restrict__ x,
                    __nv_bfloat16* __restrict__ xth, __nv_bfloat16* __restrict__ xtl)
{
    __shared__ float ts[64][65];
    const int b = blockIdx.z, c0 = blockIdx.y * 64, n0 = blockIdx.x * 64;
    const int t = threadIdx.x;
    const int rr = t >> 4, c4 = t & 15;

#pragma unroll
    for (int it = 0; it < 4; it++) {
        int row = it * 16 + rr;
        float4 v = *(const float4*)&x[(size_t)(b * C_ + c0 + row) * N_ + n0 + c4 * 4];
        ts[row][c4 * 4 + 0] = v.x; ts[row][c4 * 4 + 1] = v.y;
        ts[row][c4 * 4 + 2] = v.z; ts[row][c4 * 4 + 3] = v.w;
    }
    __syncthreads();
#pragma unroll
    for (int it = 0; it < 4; it++) {
        int n = it * 16 + rr;
        unsigned short hs[4], ls[4];
#pragma unroll
        for (int e = 0; e < 4; e++) {
            float f = ts[c4 * 4 + e][n];
            __nv_bfloat16 h = __float2bfloat16(f);
            hs[e] = __bfloat16_as_ushort(h);
            ls[e] = __bfloat16_as_ushort(__float2bfloat16(f - __bfloat162float(h)));
        }
        size_t base = (size_t)(b * N_ + n0 + n) * C_ + c0 + c4 * 4;
        *(uint2*)&xth[base] = *(uint2*)hs;
        *(uint2*)&xtl[base] = *(uint2*)ls;
    }
}

// ---------------------------------------------------------------------------
// Q+K projection GEMM -> tiled/swizzled g_qt, g_kt (q pre-scaled by log2e)
// ---------------------------------------------------------------------------
#define QK_XTH 0
#define QK_XTL 73728
#define QK_WBH 147456
#define QK_WBL 184320
#define QK_SMEM 221184

__global__ __launch_bounds__(256, 1)
void qk_mma_kernel(const __nv_bfloat16* __restrict__ xth, const __nv_bfloat16* __restrict__ xtl,
                   const __nv_bfloat16* __restrict__ wqh, const __nv_bfloat16* __restrict__ wql,
                   const __nv_bfloat16* __restrict__ wkh, const __nv_bfloat16* __restrict__ wkl,
                   const float* __restrict__ bq, const float* __restrict__ bk,
                   char* __restrict__ qt, char* __restrict__ kt)
{
    extern __shared__ char sm[];
    const uint32_t sb = smem_u32(sm);
    const int t = threadIdx.x;
    const int wid = t >> 5, lane = t & 31;
    const int g = lane >> 2, tg = lane & 3;
    const int oA = aoffA(lane), oB = aoffB(lane);
    const int wm = wid >> 1, wn = wid & 1;
    const int b = blockIdx.y, n0 = blockIdx.x * 128;

#pragma unroll
    for (int it = 0; it < 16; it++) {
        int idx = t + it * 256;
        int r = idx >> 5, cc = idx & 31;
        uint32_t off = (cc >> 3) * 18432 + r * RS + (cc & 7) * 16;
        size_t src = (size_t)(b * N_ + n0 + r) * C_ + cc * 8;
        cpasync16(sb + QK_XTH + off, xth + src);
        cpasync16(sb + QK_XTL + off, xtl + src);
    }
#pragma unroll
    for (int it = 0; it < 8; it++) {
        int idx = t + it * 256;
        int o = idx >> 5, cc = idx & 31;
        uint32_t off = (cc >> 3) * 9216 + o * RS + (cc & 7) * 16;
        const __nv_bfloat16* sh = (o < 32) ? (wqh + (size_t)o * C_) : (wkh + (size_t)(o - 32) * C_);
        const __nv_bfloat16* sl = (o < 32) ? (wql + (size_t)o * C_) : (wkl + (size_t)(o - 32) * C_);
        cpasync16(sb + QK_WBH + off, sh + cc * 8);
        cpasync16(sb + QK_WBL + off, sl + cc * 8);
    }
    CP_COMMIT();
    CP_WAIT(0);
    __syncthreads();

    float oac[2][4][4];
#pragma unroll
    for (int i = 0; i < 2; i++)
#pragma unroll
        for (int j = 0; j < 4; j++)
#pragma unroll
            for (int c = 0; c < 4; c++) oac[i][j][c] = 0.f;

#pragma unroll
    for (int kc = 0; kc < 4; kc++) {
#pragma unroll
        for (int ks = 0; ks < 4; ks++) {
            uint32_t ah[2][4], al[2][4];
#pragma unroll
            for (int mf = 0; mf < 2; mf++) {
                uint32_t ab = (wm * 32 + mf * 16) * RS + ks * 32 + oA;
                ldsm4(ah[mf], sb + QK_XTH + kc * 18432 + ab);
                ldsm4(al[mf], sb + QK_XTL + kc * 18432 + ab);
            }
#pragma unroll
            for (int j = 0; j < 2; j++) {
                uint32_t bh[4], bl[4];
                uint32_t bb = (wn * 32 + j * 16) * RS + ks * 32 + oB;
                ldsm4(bh, sb + QK_WBH + kc * 9216 + bb);
                ldsm4(bl, sb + QK_WBL + kc * 9216 + bb);
#pragma unroll
                for (int h = 0; h < 2; h++)
#pragma unroll
                    for (int mf = 0; mf < 2; mf++) {
                        mma16816(oac[mf][j * 2 + h], ah[mf], &bh[2 * h]);
                        mma16816(oac[mf][j * 2 + h], al[mf], &bh[2 * h]);
                        mma16816(oac[mf][j * 2 + h], ah[mf], &bl[2 * h]);
                    }
            }
        }
    }

    // epilogue -> swizzled tiles
#pragma unroll
    for (int mf = 0; mf < 2; mf++) {
#pragma unroll
        for (int half = 0; half < 2; half++) {
            const int rA = wm * 32 + mf * 16 + half * 8 + g;     // 0..127
            const int n = n0 + rA;
            const int tile = n >> 6, rr = n & 63;
            const int swx = (rr & 7) << 4;
#pragma unroll
            for (int hh = 0; hh < 4; hh++) {
                int o = wn * 32 + hh * 8 + 2 * tg;
                bool isq = (o < 32);
                int oo = isq ? o : (o - 32);
                float bb0 = isq ? bq[oo] * LOG2E : bk[oo];
                float bb1 = isq ? bq[oo + 1] * LOG2E : bk[oo + 1];
                float d0 = oac[mf][hh][half * 2 + 0] + bb0;
                float d1 = oac[mf][hh][half * 2 + 1] + bb1;
                uint32_t hA = pack_bf16x2(d0, d1);
                __nv_bfloat162 vA = *(__nv_bfloat162*)&hA;
                char* dst = (isq ? qt : kt) + ((size_t)(b * 64 + tile) * 64 + rr) * 128;
                *(uint32_t*)(dst + ((oo * 2) ^ swx)) = hA;
                *(uint32_t*)(dst + ((64 + oo * 2) ^ swx)) =
                    pack_bf16x2(d0 - __bfloat162float(vA.x), d1 - __bfloat162float(vA.y));
            }
        }
    }
}

// ---------------------------------------------------------------------------
// V projection GEMM -> tiled/swizzled g_vt
// ---------------------------------------------------------------------------
#define OP_WH 0
#define OP_WL 18432
#define OP_AH 36864
#define OP_AL 55296
#define OP_BUF 73728
#define OPROJ_SMEM 147456

__global__ __launch_bounds__(512, 1)
void v_mma_kernel(const __nv_bfloat16* __restrict__ xth, const __nv_bfloat16* __restrict__ xtl,
                  const __nv_bfloat16* __restrict__ wvh, const __nv_bfloat16* __restrict__ wvl,
                  const float* __restrict__ bv,
                  char* __restrict__ vt)
{
    extern __shared__ char sm[];
    const uint32_t sb = smem_u32(sm);
    const int t = threadIdx.x;
    const int wid = t >> 5, lane = t & 31;
    const int g = lane >> 2, tg = lane & 3;
    const int oA = aoffA(lane), oB = aoffB(lane);
    const int wm = wid >> 2, wn = wid & 3;
    const int b = blockIdx.z, o0 = blockIdx.y * 128, m0 = blockIdx.x * 128;

    float oac[2][4][4];
#pragma unroll
    for (int i = 0; i < 2; i++)
#pragma unroll
        for (int j = 0; j < 4; j++)
#pragma unroll
            for (int c = 0; c < 4; c++) oac[i][j][c] = 0.f;

    auto load_stage = [&](int kt_, int buf) {
        const uint32_t base = sb + buf * OP_BUF;
#pragma unroll
        for (int it = 0; it < 8; it++) {
            int idx = t + it * 512;
            int arr = idx >> 10, rr = (idx >> 3) & 127, cc = idx & 7;
            uint32_t dst = base + arr * 18432 + rr * RS + cc * 16;
            const __nv_bfloat16* src;
            if (arr == 0)      src = wvh + (size_t)(o0 + rr) * C_ + kt_ + cc * 8;
            else if (arr == 1) src = wvl + (size_t)(o0 + rr) * C_ + kt_ + cc * 8;
            else if (arr == 2) src = xth + (size_t)(b * N_ + m0 + rr) * C_ + kt_ + cc * 8;
            else               src = xtl + (size_t)(b * N_ + m0 + rr) * C_ + kt_ + cc * 8;
            cpasync16(dst, src);
        }
        CP_COMMIT();
    };

    load_stage(0, 0);
    for (int s = 0; s < 4; s++) {
        if (s + 1 < 4) { load_stage((s + 1) * 64, (s + 1) & 1); CP_WAIT(1); }
        else CP_WAIT(0);
        __syncthreads();
        const uint32_t base = sb + (s & 1) * OP_BUF;
        const uint32_t Wh = base + OP_WH + (wm * 32) * RS + oA;
        const uint32_t Wl = base + OP_WL + (wm * 32) * RS + oA;
        const uint32_t Ah = base + OP_AH + (wn * 32) * RS + oB;
        const uint32_t Al = base + OP_AL + (wn * 32) * RS + oB;
#pragma unroll
        for (int ks = 0; ks < 4; ks++) {
            uint32_t awh[2][4], awl[2][4];
#pragma unroll
            for (int mf = 0; mf < 2; mf++) {
                ldsm4(awh[mf], Wh + mf * 16 * RS + ks * 32);
                ldsm4(awl[mf], Wl + mf * 16 * RS + ks * 32);
            }
#pragma unroll
            for (int j = 0; j < 2; j++) {
                uint32_t bh[4], bl[4];
                ldsm4(bh, Ah + j * 16 * RS + ks * 32);
                ldsm4(bl, Al + j * 16 * RS + ks * 32);
#pragma unroll
                for (int h = 0; h < 2; h++) {
                    const int nf = 2 * j + h;
#pragma unroll
                    for (int mf = 0; mf < 2; mf++) {
                        mma16816(oac[mf][nf], awh[mf], &bh[2 * h]);
                        mma16816(oac[mf][nf], awl[mf], &bh[2 * h]);
                        mma16816(oac[mf][nf], awh[mf], &bl[2 * h]);
                    }
                }
            }
        }
        __syncthreads();
    }

    // epilogue: +bv -> swizzled V tiles
#pragma unroll
    for (int mf = 0; mf < 2; mf++) {
#pragma unroll
        for (int half = 0; half < 2; half++) {
            const int rA = o0 + wm * 32 + mf * 16 + half * 8 + g;   // channel 0..255
            const float bvA = bv[rA];
            const int swx = (rA & 7) << 4;
#pragma unroll
            for (int nf = 0; nf < 4; nf++) {
                const int m = m0 + wn * 32 + nf * 8 + 2 * tg;
                const int tile = m >> 6, j = m & 63;
                char* dst = vt + ((size_t)(b * 64 + tile) * 256 + rA) * 128;
                *(uint32_t*)(dst + ((j * 2) ^ swx)) =
                    pack_bf16x2(oac[mf][nf][half * 2 + 0] + bvA, oac[mf][nf][half * 2 + 1] + bvA);
            }
        }
    }
}

// ---------------------------------------------------------------------------
// Flash attention: 2 CTAs/SM, single-term PV, consistent rounded-p lsum.
// K/V/Q now loaded as ONE bulk per tile from pre-swizzled gmem blobs.
// ---------------------------------------------------------------------------
#define OFF_LSUM 64
#define OFF_Q2   1024
#define OFF_K2   9216
#define OFF_PH   17408
#define OFF_V0   26624
#define OFF_V1   59392
#define ATTN_SMEM 92160

__global__ __launch_bounds__(256, 2)
void attn_mma_kernel(const char* __restrict__ qt,
                     const char* __restrict__ kt,
                     const char* __restrict__ vt,
                     __nv_bfloat16* __restrict__ aohi,
                     __nv_bfloat16* __restrict__ aolo)
{
    extern __shared__ char sm[];
    const uint32_t sb = smem_u32(sm);
    const int t = threadIdx.x;
    const int wid = t >> 5, lane = t & 31;
    const int g = lane >> 2, tg = lane & 3;
    const int oA = aoffA(lane);
    const int wm = wid >> 2, wn = wid & 3;
    const int rowA = wm * 32;
    const int kb = wn * 16;
    const int b = blockIdx.y, m0 = blockIdx.x * 64;

    // swizzled 128B-row ldsm address pieces
    const int arow = lane & 15, acol = (lane >> 4) * 16, ax = (lane & 7) << 4;
    const int brow = (lane & 7) + ((lane >> 4) << 3), bcol = (lane & 8) * 2, bx = (lane & 7) << 4;

    const char* qt_b = qt + ((size_t)(b * 64 + (m0 >> 6))) * 8192;
    const char* kt_b = kt + (size_t)b * 64 * 8192;
    const char* vt_b = vt + (size_t)b * 64 * 32768;

    float* lsum_s = (float*)(sm + OFF_LSUM);
    if (t == 0) {
        MBARRIER_INIT(sb + 0, 1);
        MBARRIER_INIT(sb + 8, 1);
        MBARRIER_INIT(sb + 16, 1);
    }
    if (t < 64) lsum_s[t] = 0.f;

    // Q + K_0: contiguous copies of pre-swizzled blobs
#pragma unroll
    for (int i = 0; i < 2; i++) {
        int idx = t + i * 256;
        cpasync16(sb + OFF_Q2 + idx * 16, qt_b + idx * 16);
        cpasync16(sb + OFF_K2 + idx * 16, kt_b + idx * 16);
    }
    CP_COMMIT();
    __syncthreads();   // mbarrier init + lsum visible

    if (t == 0) { MBARRIER_EXPECT_TX(sb + 8, 32768); bulkcp(sb + OFF_V0, vt_b, 32768, sb + 8); }

    CP_WAIT(0);
    __syncthreads();

    uint32_t qfh[2][2][4];
#pragma unroll
    for (int mf = 0; mf < 2; mf++)
#pragma unroll
        for (int c = 0; c < 2; c++)
            ldsm4(qfh[mf][c], sb + OFF_Q2 + (rowA + mf * 16 + arow) * 128 + ((c * 32 + acol) ^ ax));

    const uint32_t sbPH = sb + OFF_PH;

    float sacc[2][2][4];
    float oacc[2][8][4];
#pragma unroll
    for (int i = 0; i < 2; i++)
#pragma unroll
        for (int j = 0; j < 8; j++)
#pragma unroll
            for (int c = 0; c < 4; c++) oacc[i][j][c] = 0.f;
    float lpart[2][2] = {{0.f, 0.f}, {0.f, 0.f}};
    int kcnt = 0, vcnt0 = 0, vcnt1 = 0;

    auto do_smma = [&]() {
#pragma unroll
        for (int a = 0; a < 2; a++)
#pragma unroll
            for (int j2 = 0; j2 < 2; j2++)
#pragma unroll
                for (int c = 0; c < 4; c++) sacc[a][j2][c] = 0.f;
        const uint32_t Kr = sb + OFF_K2 + (kb + brow) * 128;
        uint32_t bK[4];
        ldsm4(bK, Kr + ((0 + bcol) ^ bx));
#pragma unroll
        for (int mf = 0; mf < 2; mf++) { mma16816(sacc[mf][0], qfh[mf][0], &bK[0]); mma16816(sacc[mf][1], qfh[mf][0], &bK[2]); }
        {
            uint32_t ql[4];
#pragma unroll
            for (int mf = 0; mf < 2; mf++) {
                ldsm4(ql, sb + OFF_Q2 + (rowA + mf * 16 + arow) * 128 + ((64 + acol) ^ ax));
                mma16816(sacc[mf][0], ql, &bK[0]); mma16816(sacc[mf][1], ql, &bK[2]);
            }
        }
        ldsm4(bK, Kr + ((32 + bcol) ^ bx));
#pragma unroll
        for (int mf = 0; mf < 2; mf++) { mma16816(sacc[mf][0], qfh[mf][1], &bK[0]); mma16816(sacc[mf][1], qfh[mf][1], &bK[2]); }
        {
            uint32_t ql[4];
#pragma unroll
            for (int mf = 0; mf < 2; mf++) {
                ldsm4(ql, sb + OFF_Q2 + (rowA + mf * 16 + arow) * 128 + ((96 + acol) ^ ax));
                mma16816(sacc[mf][0], ql, &bK[0]); mma16816(sacc[mf][1], ql, &bK[2]);
            }
        }
        ldsm4(bK, Kr + ((64 + bcol) ^ bx));
#pragma unroll
        for (int mf = 0; mf < 2; mf++) { mma16816(sacc[mf][0], qfh[mf][0], &bK[0]); mma16816(sacc[mf][1], qfh[mf][0], &bK[2]); }
        ldsm4(bK, Kr + ((96 + bcol) ^ bx));
#pragma unroll
        for (int mf = 0; mf < 2; mf++) { mma16816(sacc[mf][0], qfh[mf][1], &bK[0]); mma16816(sacc[mf][1], qfh[mf][1], &bK[2]); }
    };

    auto do_softmax = [&]() {
#pragma unroll
        for (int mf = 0; mf < 2; mf++) {
            const int r0 = rowA + mf * 16 + g;
#pragma unroll
            for (int nf = 0; nf < 2; nf++) {
                const int cb = kb + nf * 8 + 2 * tg;
                float p0 = exp2f(sacc[mf][nf][0]);
                float p1 = exp2f(sacc[mf][nf][1]);
                float p2 = exp2f(sacc[mf][nf][2]);
                float p3 = exp2f(sacc[mf][nf][3]);
                uint32_t hA = pack_bf16x2(p0, p1);
                uint32_t hB = pack_bf16x2(p2, p3);
                __nv_bfloat162 hv0 = *(__nv_bfloat162*)&hA;
                __nv_bfloat162 hv1 = *(__nv_bfloat162*)&hB;
                lpart[mf][0] += __bfloat162float(hv0.x) + __bfloat162float(hv0.y);
                lpart[mf][1] += __bfloat162float(hv1.x) + __bfloat162float(hv1.y);
                *(uint32_t*)(sm + OFF_PH + r0 * RS + cb * 2) = hA;
                *(uint32_t*)(sm + OFF_PH + (r0 + 8) * RS + cb * 2) = hB;
            }
        }
    };

    auto do_pv = [&](uint32_t Vb) {
#pragma unroll
        for (int kk = 0; kk < 4; kk++) {
            uint32_t aH[2][4];
#pragma unroll
            for (int mf = 0; mf < 2; mf++)
                ldsm4(aH[mf], sbPH + (rowA + mf * 16) * RS + kk * 32 + oA);
#pragma unroll
            for (int j = 0; j < 4; j++) {
                uint32_t bV[4];
                ldsm4(bV, Vb + (wn * 64 + j * 16 + brow) * 128 + ((kk * 32 + bcol) ^ bx));
#pragma unroll
                for (int mf = 0; mf < 2; mf++) {
                    mma16816(oacc[mf][2 * j],     aH[mf], &bV[0]);
                    mma16816(oacc[mf][2 * j + 1], aH[mf], &bV[2]);
                }
            }
        }
    };

    do_smma();
    __syncthreads();

    if (t == 0) {
        MBARRIER_EXPECT_TX(sb + 0, 8192);  bulkcp(sb + OFF_K2, kt_b + 8192, 8192, sb + 0);
        MBARRIER_EXPECT_TX(sb + 16, 32768); bulkcp(sb + OFF_V1, vt_b + 32768, 32768, sb + 16);
    }

    for (int i = 0; i < 64; i++) {
        do_softmax();
        __syncthreads();

        if (i + 1 < 64) {
            MBARRIER_WAIT_PARITY(sb + 0, kcnt & 1); kcnt++;
            do_smma();
        }
        if (i & 1) { MBARRIER_WAIT_PARITY(sb + 16, vcnt1 & 1); vcnt1++; }
        else       { MBARRIER_WAIT_PARITY(sb + 8,  vcnt0 & 1); vcnt0++; }
        do_pv(sb + ((i & 1) ? OFF_V1 : OFF_V0));
        __syncthreads();

        if (i + 2 < 64 && t == 0) {
            const int nn = i + 2;
            const uint32_t vdst = sb + ((i & 1) ? OFF_V1 : OFF_V0);
            const uint32_t vmb  = sb + 8 + (i & 1) * 8;
            MBARRIER_EXPECT_TX(sb + 0, 8192);
            bulkcp(sb + OFF_K2, kt_b + (size_t)nn * 8192, 8192, sb + 0);
            MBARRIER_EXPECT_TX(vmb, 32768);
            bulkcp(vdst, vt_b + (size_t)nn * 32768, 32768, vmb);
        }
    }

#pragma unroll
    for (int mf = 0; mf < 2; mf++) {
        atomicAdd(&lsum_s[rowA + mf * 16 + g],     lpart[mf][0]);
        atomicAdd(&lsum_s[rowA + mf * 16 + 8 + g], lpart[mf][1]);
    }
    __syncthreads();

#pragma unroll
    for (int mf = 0; mf < 2; mf++) {
        const int rA = rowA + mf * 16 + g;
        const int rB = rA + 8;
        const float invA = 1.f / lsum_s[rA];
        const float invB = 1.f / lsum_s[rB];
        __nv_bfloat16* hA = aohi + (size_t)(b * N_ + m0 + rA) * C_;
        __nv_bfloat16* hB = aohi + (size_t)(b * N_ + m0 + rB) * C_;
        __nv_bfloat16* lA = aolo + (size_t)(b * N_ + m0 + rA) * C_;
        __nv_bfloat16* lB = aolo + (size_t)(b * N_ + m0 + rB) * C_;
#pragma unroll
        for (int nf = 0; nf < 8; nf++) {
            const int cb = wn * 64 + nf * 8 + 2 * tg;
            float a0 = oacc[mf][nf][0] * invA, a1 = oacc[mf][nf][1] * invA;
            float b0v = oacc[mf][nf][2] * invB, b1v = oacc[mf][nf][3] * invB;
            uint32_t ha = pack_bf16x2(a0, a1);
            uint32_t hb = pack_bf16x2(b0v, b1v);
            __nv_bfloat162 va = *(__nv_bfloat162*)&ha;
            __nv_bfloat162 vb = *(__nv_bfloat162*)&hb;
            *(uint32_t*)(hA + cb) = ha;
            *(uint32_t*)(hB + cb) = hb;
            *(uint32_t*)(lA + cb) = pack_bf16x2(a0 - __bfloat162float(va.x), a1 - __bfloat162float(va.y));
            *(uint32_t*)(lB + cb) = pack_bf16x2(b0v - __bfloat162float(vb.x), b1v - __bfloat162float(vb.y));
        }
    }
}

// ---------------------------------------------------------------------------
// Output projection (unchanged): out = wo*AO + bo + x
// ---------------------------------------------------------------------------
__global__ __launch_bounds__(512, 1)
void oproj_mma_kernel(const __nv_bfloat16* __restrict__ aohi,
                      const __nv_bfloat16* __restrict__ aolo,
                      const __nv_bfloat16* __restrict__ whi,
                      const __nv_bfloat16* __restrict__ wlo,
                      const float* __restrict__ bo,
                      const float* __restrict__ x,
                      float* __restrict__ out)
{
    extern __shared__ char sm[];
    const uint32_t sb = smem_u32(sm);
    const int t = threadIdx.x;
    const int wid = t >> 5, lane = t & 31;
    const int g = lane >> 2, tg = lane & 3;
    const int oA = aoffA(lane), oB = aoffB(lane);
    const int wm = wid >> 2, wn = wid & 3;
    const int b = blockIdx.z, o0 = blockIdx.y * 128, m0 = blockIdx.x * 128;

    float oac[2][4][4];
#pragma unroll
    for (int i = 0; i < 2; i++)
#pragma unroll
        for (int j = 0; j < 4; j++)
#pragma unroll
            for (int c = 0; c < 4; c++) oac[i][j][c] = 0.f;

    auto load_stage = [&](int kt_, int buf) {
        const uint32_t base = sb + buf * OP_BUF;
#pragma unroll
        for (int it = 0; it < 8; it++) {
            int idx = t + it * 512;
            int arr = idx >> 10, rr = (idx >> 3) & 127, cc = idx & 7;
            uint32_t dst = base + arr * 18432 + rr * RS + cc * 16;
            const __nv_bfloat16* src;
            if (arr == 0)      src = whi + (size_t)(o0 + rr) * C_ + kt_ + cc * 8;
            else if (arr == 1) src = wlo + (size_t)(o0 + rr) * C_ + kt_ + cc * 8;
            else if (arr == 2) src = aohi + (size_t)(b * N_ + m0 + rr) * C_ + kt_ + cc * 8;
            else               src = aolo + (size_t)(b * N_ + m0 + rr) * C_ + kt_ + cc * 8;
            cpasync16(dst, src);
        }
        CP_COMMIT();
    };

    load_stage(0, 0);
    for (int s = 0; s < 4; s++) {
        if (s + 1 < 4) { load_stage((s + 1) * 64, (s + 1) & 1); CP_WAIT(1); }
        else CP_WAIT(0);
        __syncthreads();
        const uint32_t base = sb + (s & 1) * OP_BUF;
        const uint32_t Wh = base + OP_WH + (wm * 32) * RS + oA;
        const uint32_t Wl = base + OP_WL + (wm * 32) * RS + oA;
        const uint32_t Ah = base + OP_AH + (wn * 32) * RS + oB;
        const uint32_t Al = base + OP_AL + (wn * 32) * RS + oB;
#pragma unroll
        for (int ks = 0; ks < 4; ks++) {
            uint32_t awh[2][4], awl[2][4];
#pragma unroll
            for (int mf = 0; mf < 2; mf++) {
                ldsm4(awh[mf], Wh + mf * 16 * RS + ks * 32);
                ldsm4(awl[mf], Wl + mf * 16 * RS + ks * 32);
            }
#pragma unroll
            for (int j = 0; j < 2; j++) {
                uint32_t bh[4], bl[4];
                ldsm4(bh, Ah + j * 16 * RS + ks * 32);
                ldsm4(bl, Al + j * 16 * RS + ks * 32);
#pragma unroll
                for (int h = 0; h < 2; h++) {
                    const int nf = 2 * j + h;
#pragma unroll
                    for (int mf = 0; mf < 2; mf++) {
                        mma16816(oac[mf][nf], awh[mf], &bh[2 * h]);
                        mma16816(oac[mf][nf], awl[mf], &bh[2 * h]);
                        mma16816(oac[mf][nf], awh[mf], &bl[2 * h]);
                    }
                }
            }
        }
        __syncthreads();
    }

#pragma unroll
    for (int mf = 0; mf < 2; mf++) {
        const int rA = o0 + wm * 32 + mf * 16 + g;
        const int rB = rA + 8;
        const float bvA = bo[rA], bvB = bo[rB];
#pragma unroll
        for (int nf = 0; nf < 4; nf++) {
            const int m = m0 + wn * 32 + nf * 8 + 2 * tg;
            size_t iA = (size_t)(b * C_ + rA) * N_ + m;
            size_t iB = (size_t)(b * C_ + rB) * N_ + m;
            float2 xA = *(const float2*)&x[iA];
            float2 xB = *(const float2*)&x[iB];
            *(float2*)&out[iA] = make_float2(oac[mf][nf][0] + bvA + xA.x, oac[mf][nf][1] + bvA + xA.y);
            *(float2*)&out[iB] = make_float2(oac[mf][nf][2] + bvB + xB.x, oac[mf][nf][3] + bvB + xB.y);
        }
    }
}

// ---------------------------------------------------------------------------
extern "C" void kernel_launch(void* const* d_in, const int* in_sizes, int n_in,
                              void* d_out, int out_size)
{
    const float* x  = (const float*)d_in[0];
    const float* wq = (const float*)d_in[1];
    const float* bq = (const float*)d_in[2];
    const float* wk = (const float*)d_in[3];
    const float* bk = (const float*)d_in[4];
    const float* wv = (const float*)d_in[5];
    const float* bv = (const float*)d_in[6];
    const float* wo = (const float*)d_in[7];
    const float* bo = (const float*)d_in[8];
    float* out = (float*)d_out;

    char *gqt, *gkt, *gvt;
    __nv_bfloat16 *gaoh, *gaol, *gxth, *gxtl;
    __nv_bfloat16 *gwoh, *gwol, *gwvh, *gwvl, *gwqh, *gwql, *gwkh, *gwkl;
    cudaGetSymbolAddress((void**)&gqt,  g_qt);
    cudaGetSymbolAddress((void**)&gkt,  g_kt);
    cudaGetSymbolAddress((void**)&gvt,  g_vt);
    cudaGetSymbolAddress((void**)&gaoh, g_aohi);
    cudaGetSymbolAddress((void**)&gaol, g_aolo);
    cudaGetSymbolAddress((void**)&gxth, g_xth);
    cudaGetSymbolAddress((void**)&gxtl, g_xtl);
    cudaGetSymbolAddress((void**)&gwoh, g_wohi);
    cudaGetSymbolAddress((void**)&gwol, g_wolo);
    cudaGetSymbolAddress((void**)&gwvh, g_wvhi);
    cudaGetSymbolAddress((void**)&gwvl, g_wvlo);
    cudaGetSymbolAddress((void**)&gwqh, g_wqhi);
    cudaGetSymbolAddress((void**)&gwql, g_wqlo);
    cudaGetSymbolAddress((void**)&gwkh, g_wkhi);
    cudaGetSymbolAddress((void**)&gwkl, g_wklo);

    cudaFuncSetAttribute(attn_mma_kernel, cudaFuncAttributeMaxDynamicSharedMemorySize, ATTN_SMEM);
    cudaFuncSetAttribute(oproj_mma_kernel, cudaFuncAttributeMaxDynamicSharedMemorySize, OPROJ_SMEM);
    cudaFuncSetAttribute(v_mma_kernel, cudaFuncAttributeMaxDynamicSharedMemorySize, OPROJ_SMEM);
    cudaFuncSetAttribute(qk_mma_kernel, cudaFuncAttributeMaxDynamicSharedMemorySize, QK_SMEM);

    wprep_all_kernel<<<dim3(C_ * C_ / 256, 4), 256>>>(wo, wv, wq, wk,
        gwoh, gwol, gwvh, gwvl, gwqh, gwql, gwkh, gwkl);
    xt_pack_kernel<<<dim3(N_ / 64, C_ / 64, B_), 256>>>(x, gxth, gxtl);
    qk_mma_kernel<<<dim3(N_ / 128, B_), 256, QK_SMEM>>>(
        gxth, gxtl, gwqh, gwql, gwkh, gwkl, bq, bk, gqt, gkt);
    v_mma_kernel<<<dim3(N_ / 128, C_ / 128, B_), 512, OPROJ_SMEM>>>(
        gxth, gxtl, gwvh, gwvl, bv, gvt);
    attn_mma_kernel<<<dim3(N_ / 64, B_), 256, ATTN_SMEM>>>(gqt, gkt, gvt, gaoh, gaol);
    oproj_mma_kernel<<<dim3(N_ / 128, C_ / 128, B_), 512, OPROJ_SMEM>>>(
        gaoh, gaol, gwoh, gwol, bo, x, out);
}

// round 12
// speedup vs baseline: 8.5341x; 1.2923x over previous
#include <cuda_runtime.h>
#include <cuda_bf16.h>
#include <cuda_fp16.h>
#include <math.h>
#include <stdint.h>

#define B_ 4
#define C_ 256
#define N_ 4096
#define D_ 32
#define LOG2E 1.4426950408889634f

// ---------------------------------------------------------------------------
// PTX helpers (base sm_100-safe)
// ---------------------------------------------------------------------------
__device__ __forceinline__ uint32_t smem_u32(const void* p) {
    uint32_t a;
    asm("{ .reg .u64 t; cvta.to.shared.u64 t, %1; cvt.u32.u64 %0, t; }" : "=r"(a) : "l"(p));
    return a;
}
#define MBARRIER_INIT(a, c) \
    asm volatile("mbarrier.init.shared.b64 [%0], %1;" :: "r"((uint32_t)(a)), "r"((uint32_t)(c)) : "memory")
#define MBARRIER_EXPECT_TX(a, n) \
    asm volatile("mbarrier.arrive.expect_tx.shared.b64 _, [%0], %1;" :: "r"((uint32_t)(a)), "r"((uint32_t)(n)) : "memory")
#define MBARRIER_WAIT_PARITY(a, ph) do { \
    uint32_t _m = (uint32_t)(a); uint32_t _p = (uint32_t)(ph); uint32_t _d; \
    asm volatile("{\n\t.reg .pred p;\n\tmbarrier.try_wait.parity.shared.b64 p, [%1], %2;\n\tselp.b32 %0,1,0,p;\n\t}" \
        : "=r"(_d) : "r"(_m), "r"(_p) : "memory"); \
    if (!_d) { \
        asm volatile("{\n\t.reg .pred P1;\n\tWL_%=:\n\tmbarrier.try_wait.parity.shared.b64 P1, [%0], %1;\n\t@P1 bra.uni WD_%=;\n\tbra.uni WL_%=;\n\tWD_%=:\n\t}" \
            :: "r"(_m), "r"(_p) : "memory"); \
    } } while (0)

__device__ __forceinline__ void cpasync16(uint32_t dst, const void* src) {
    asm volatile("cp.async.cg.shared.global [%0], [%1], 16;" :: "r"(dst), "l"(src) : "memory");
}
#define CP_COMMIT() asm volatile("cp.async.commit_group;" ::: "memory")
#define CP_WAIT(n)  asm volatile("cp.async.wait_group %0;" :: "n"(n) : "memory")

__device__ __forceinline__ void bulkcp(uint32_t dst, const void* src, uint32_t bytes, uint32_t mbar) {
    asm volatile("cp.async.bulk.shared::cta.global.mbarrier::complete_tx::bytes [%0], [%1], %2, [%3];"
                 :: "r"(dst), "l"(src), "r"(bytes), "r"(mbar) : "memory");
}

// bf16 mma (PV path)
__device__ __forceinline__ void mma_bf(float* d, const uint32_t* a, const uint32_t* b) {
    asm volatile("mma.sync.aligned.m16n8k16.row.col.f32.bf16.bf16.f32 "
                 "{%0,%1,%2,%3}, {%4,%5,%6,%7}, {%8,%9}, {%0,%1,%2,%3};"
                 : "+f"(d[0]), "+f"(d[1]), "+f"(d[2]), "+f"(d[3])
                 : "r"(a[0]), "r"(a[1]), "r"(a[2]), "r"(a[3]), "r"(b[0]), "r"(b[1]));
}
// fp16 mma (S + projections)
__device__ __forceinline__ void mma_fp(float* d, const uint32_t* a, const uint32_t* b) {
    asm volatile("mma.sync.aligned.m16n8k16.row.col.f32.f16.f16.f32 "
                 "{%0,%1,%2,%3}, {%4,%5,%6,%7}, {%8,%9}, {%0,%1,%2,%3};"
                 : "+f"(d[0]), "+f"(d[1]), "+f"(d[2]), "+f"(d[3])
                 : "r"(a[0]), "r"(a[1]), "r"(a[2]), "r"(a[3]), "r"(b[0]), "r"(b[1]));
}
__device__ __forceinline__ void ldsm4(uint32_t* r, uint32_t addr) {
    asm volatile("ldmatrix.sync.aligned.m8n8.x4.shared.b16 {%0,%1,%2,%3}, [%4];"
                 : "=r"(r[0]), "=r"(r[1]), "=r"(r[2]), "=r"(r[3]) : "r"(addr));
}
__device__ __forceinline__ uint32_t pack_bf16x2(float x, float y) {
    __nv_bfloat162 h = __floats2bfloat162_rn(x, y);
    return *(uint32_t*)&h;
}
__device__ __forceinline__ uint32_t pack_h2(float x, float y) {
    __half2 h = __floats2half2_rn(x, y);
    return *(uint32_t*)&h;
}

#define RS 144
__device__ __forceinline__ int aoffA(int lane) { return (lane & 15) * RS + (lane >> 4) * 16; }
__device__ __forceinline__ int aoffB(int lane) { return ((lane & 7) + ((lane >> 4) << 3)) * RS + (lane & 8) * 2; }
// 64B-row swizzle: chunk ^= (row>>1)&3  (conflict-free for ldsm)
__device__ __forceinline__ uint32_t swz64(int row, int chunk) {
    return (uint32_t)(row * 64 + ((chunk ^ ((row >> 1) & 3)) << 4));
}

// ---------------------------------------------------------------------------
// Scratch.
//  g_qt/g_kt: [b][tile64][64 rows x 64B]  (row = 32 fp16; q pre-scaled log2e)
//  g_vt:      [b][tile64][256 ch x 128B]  (row = 64 keys bf16, SW128)
//  g_ao:      [b][n][c] fp16 ;  g_xt: [b][n][c] fp16
// ---------------------------------------------------------------------------
__device__ char   g_qt [B_*64*64*64];
__device__ char   g_kt [B_*64*64*64];
__device__ char   g_vt [(size_t)B_*64*256*128];
__device__ __half g_ao [B_*N_*C_];
__device__ __half g_xt [B_*N_*C_];
__device__ __half g_wohi[C_*C_];
__device__ __half g_wolo[C_*C_];
__device__ __half g_wv [C_*C_];
__device__ __half g_wq [D_*C_];
__device__ __half g_wk [D_*C_];

// ---------------------------------------------------------------------------
// weight prep: wo -> fp16 hi/lo; wv,wk fp16; wq fp16 * log2e
// ---------------------------------------------------------------------------
__global__ void wprep_all_kernel(const float* __restrict__ wo, const float* __restrict__ wv,
                                 const float* __restrict__ wq, const float* __restrict__ wk,
                                 __half* __restrict__ woh, __half* __restrict__ wol,
                                 __half* __restrict__ wvp, __half* __restrict__ wqp,
                                 __half* __restrict__ wkp)
{
    int which = blockIdx.y;
    int i = blockIdx.x * 256 + threadIdx.x;
    if (which == 0) {
        float f = wo[i];
        __half h = __float2half_rn(f);
        woh[i] = h;
        wol[i] = __float2half_rn(f - __half2float(h));
    } else if (which == 1) {
        wvp[i] = __float2half_rn(wv[i]);
    } else if (which == 2) {
        if (i < D_ * C_) wqp[i] = __float2half_rn(wq[i] * LOG2E);
    } else {
        if (i < D_ * C_) wkp[i] = __float2half_rn(wk[i]);
    }
}

// ---------------------------------------------------------------------------
// x [b][c][n] fp32 -> xt fp16 [b][n][c]
// ---------------------------------------------------------------------------
__global__ __launch_bounds__(256)
void xt_pack_kernel(const float* __restrict__ x, __half* __restrict__ xt)
{
    __shared__ float ts[64][65];
    const int b = blockIdx.z, c0 = blockIdx.y * 64, n0 = blockIdx.x * 64;
    const int t = threadIdx.x;
    const int rr = t >> 4, c4 = t & 15;

#pragma unroll
    for (int it = 0; it < 4; it++) {
        int row = it * 16 + rr;
        float4 v = *(const float4*)&x[(size_t)(b * C_ + c0 + row) * N_ + n0 + c4 * 4];
        ts[row][c4 * 4 + 0] = v.x; ts[row][c4 * 4 + 1] = v.y;
        ts[row][c4 * 4 + 2] = v.z; ts[row][c4 * 4 + 3] = v.w;
    }
    __syncthreads();
#pragma unroll
    for (int it = 0; it < 4; it++) {
        int n = it * 16 + rr;
        unsigned short hs[4];
#pragma unroll
        for (int e = 0; e < 4; e++)
            hs[e] = __half_as_ushort(__float2half_rn(ts[c4 * 4 + e][n]));
        *(uint2*)&xt[(size_t)(b * N_ + n0 + n) * C_ + c0 + c4 * 4] = *(uint2*)hs;
    }
}

// ---------------------------------------------------------------------------
// Q+K projection GEMM (single-term fp16) -> 64B-row swizzled g_qt, g_kt
// ---------------------------------------------------------------------------
#define QK_XT 0
#define QK_WB 73728
#define QK_SMEM 110592

__global__ __launch_bounds__(256, 1)
void qk_mma_kernel(const __half* __restrict__ xt,
                   const __half* __restrict__ wqp, const __half* __restrict__ wkp,
                   const float* __restrict__ bq, const float* __restrict__ bk,
                   char* __restrict__ qt, char* __restrict__ kt)
{
    extern __shared__ char sm[];
    const uint32_t sb = smem_u32(sm);
    const int t = threadIdx.x;
    const int wid = t >> 5, lane = t & 31;
    const int g = lane >> 2, tg = lane & 3;
    const int oA = aoffA(lane), oB = aoffB(lane);
    const int wm = wid >> 1, wn = wid & 1;
    const int b = blockIdx.y, n0 = blockIdx.x * 128;

#pragma unroll
    for (int it = 0; it < 16; it++) {
        int idx = t + it * 256;
        int r = idx >> 5, cc = idx & 31;
        uint32_t off = (cc >> 3) * 18432 + r * RS + (cc & 7) * 16;
        cpasync16(sb + QK_XT + off, xt + (size_t)(b * N_ + n0 + r) * C_ + cc * 8);
    }
#pragma unroll
    for (int it = 0; it < 8; it++) {
        int idx = t + it * 256;
        int o = idx >> 5, cc = idx & 31;
        uint32_t off = (cc >> 3) * 9216 + o * RS + (cc & 7) * 16;
        const __half* sh = (o < 32) ? (wqp + (size_t)o * C_) : (wkp + (size_t)(o - 32) * C_);
        cpasync16(sb + QK_WB + off, sh + cc * 8);
    }
    CP_COMMIT();
    CP_WAIT(0);
    __syncthreads();

    float oac[2][4][4];
#pragma unroll
    for (int i = 0; i < 2; i++)
#pragma unroll
        for (int j = 0; j < 4; j++)
#pragma unroll
            for (int c = 0; c < 4; c++) oac[i][j][c] = 0.f;

#pragma unroll
    for (int kc = 0; kc < 4; kc++) {
#pragma unroll
        for (int ks = 0; ks < 4; ks++) {
            uint32_t ah[2][4];
#pragma unroll
            for (int mf = 0; mf < 2; mf++)
                ldsm4(ah[mf], sb + QK_XT + kc * 18432 + (wm * 32 + mf * 16) * RS + ks * 32 + oA);
#pragma unroll
            for (int j = 0; j < 2; j++) {
                uint32_t bh[4];
                ldsm4(bh, sb + QK_WB + kc * 9216 + (wn * 32 + j * 16) * RS + ks * 32 + oB);
#pragma unroll
                for (int h = 0; h < 2; h++)
#pragma unroll
                    for (int mf = 0; mf < 2; mf++)
                        mma_fp(oac[mf][j * 2 + h], ah[mf], &bh[2 * h]);
            }
        }
    }

    // epilogue -> 64B-row swizzled tiles (single fp16)
#pragma unroll
    for (int mf = 0; mf < 2; mf++) {
#pragma unroll
        for (int half = 0; half < 2; half++) {
            const int rA = wm * 32 + mf * 16 + half * 8 + g;     // 0..127
            const int n = n0 + rA;
            const int tile = n >> 6, rr = n & 63;
#pragma unroll
            for (int hh = 0; hh < 4; hh++) {
                int o = wn * 32 + hh * 8 + 2 * tg;
                bool isq = (o < 32);
                int oo = isq ? o : (o - 32);
                float bb0 = isq ? bq[oo] * LOG2E : bk[oo];
                float bb1 = isq ? bq[oo + 1] * LOG2E : bk[oo + 1];
                float d0 = oac[mf][hh][half * 2 + 0] + bb0;
                float d1 = oac[mf][hh][half * 2 + 1] + bb1;
                char* dst = (isq ? qt : kt) + ((size_t)(b * 64 + tile) * 64) * 64;
                *(uint32_t*)(dst + swz64(rr, oo >> 3) + ((oo * 2) & 15)) = pack_h2(d0, d1);
            }
        }
    }
}

// ---------------------------------------------------------------------------
// V projection GEMM (single-term fp16) -> swizzled bf16 g_vt
// ---------------------------------------------------------------------------
#define VP_W 0
#define VP_X 18432
#define VP_BUF 36864
#define VP_SMEM 73728

__global__ __launch_bounds__(512, 1)
void v_mma_kernel(const __half* __restrict__ xt, const __half* __restrict__ wvp,
                  const float* __restrict__ bv, char* __restrict__ vt)
{
    extern __shared__ char sm[];
    const uint32_t sb = smem_u32(sm);
    const int t = threadIdx.x;
    const int wid = t >> 5, lane = t & 31;
    const int g = lane >> 2, tg = lane & 3;
    const int oA = aoffA(lane), oB = aoffB(lane);
    const int wm = wid >> 2, wn = wid & 3;
    const int b = blockIdx.z, o0 = blockIdx.y * 128, m0 = blockIdx.x * 128;

    float oac[2][4][4];
#pragma unroll
    for (int i = 0; i < 2; i++)
#pragma unroll
        for (int j = 0; j < 4; j++)
#pragma unroll
            for (int c = 0; c < 4; c++) oac[i][j][c] = 0.f;

    auto load_stage = [&](int kt_, int buf) {
        const uint32_t base = sb + buf * VP_BUF;
#pragma unroll
        for (int it = 0; it < 4; it++) {
            int idx = t + it * 512;
            int arr = idx >> 10, rr = (idx >> 3) & 127, cc = idx & 7;
            uint32_t dst = base + arr * 18432 + rr * RS + cc * 16;
            const __half* src = arr ? (xt + (size_t)(b * N_ + m0 + rr) * C_ + kt_ + cc * 8)
                                    : (wvp + (size_t)(o0 + rr) * C_ + kt_ + cc * 8);
            cpasync16(dst, src);
        }
        CP_COMMIT();
    };

    load_stage(0, 0);
    for (int s = 0; s < 4; s++) {
        if (s + 1 < 4) { load_stage((s + 1) * 64, (s + 1) & 1); CP_WAIT(1); }
        else CP_WAIT(0);
        __syncthreads();
        const uint32_t base = sb + (s & 1) * VP_BUF;
        const uint32_t Wp = base + VP_W + (wm * 32) * RS + oA;
        const uint32_t Xp = base + VP_X + (wn * 32) * RS + oB;
#pragma unroll
        for (int ks = 0; ks < 4; ks++) {
            uint32_t aw[2][4];
#pragma unroll
            for (int mf = 0; mf < 2; mf++)
                ldsm4(aw[mf], Wp + mf * 16 * RS + ks * 32);
#pragma unroll
            for (int j = 0; j < 2; j++) {
                uint32_t bh[4];
                ldsm4(bh, Xp + j * 16 * RS + ks * 32);
#pragma unroll
                for (int h = 0; h < 2; h++)
#pragma unroll
                    for (int mf = 0; mf < 2; mf++)
                        mma_fp(oac[mf][j * 2 + h], aw[mf], &bh[2 * h]);
            }
        }
        __syncthreads();
    }

    // epilogue: +bv -> swizzled bf16 V tiles (128B rows, SW128)
#pragma unroll
    for (int mf = 0; mf < 2; mf++) {
#pragma unroll
        for (int half = 0; half < 2; half++) {
            const int rA = o0 + wm * 32 + mf * 16 + half * 8 + g;   // channel
            const float bvA = bv[rA];
            const int swx = (rA & 7) << 4;
#pragma unroll
            for (int nf = 0; nf < 4; nf++) {
                const int m = m0 + wn * 32 + nf * 8 + 2 * tg;
                const int tile = m >> 6, j = m & 63;
                char* dst = vt + ((size_t)(b * 64 + tile) * 256 + rA) * 128;
                *(uint32_t*)(dst + ((j * 2) ^ swx)) =
                    pack_bf16x2(oac[mf][nf][half * 2 + 0] + bvA, oac[mf][nf][half * 2 + 1] + bvA);
            }
        }
    }
}

// ---------------------------------------------------------------------------
// Flash attention: S in fp16 (single term, 8 MMAs), PV in bf16 (64 MMAs),
// consistent rounded-p lsum. 2 CTAs/SM.
// ---------------------------------------------------------------------------
#define OFF_LSUM 64
#define OFF_Q2   1024
#define OFF_K2   5120
#define OFF_PH   9216
#define OFF_V0   18432
#define OFF_V1   51200
#define ATTN_SMEM 83968

__global__ __launch_bounds__(256, 2)
void attn_mma_kernel(const char* __restrict__ qt,
                     const char* __restrict__ kt,
                     const char* __restrict__ vt,
                     __half* __restrict__ ao)
{
    extern __shared__ char sm[];
    const uint32_t sb = smem_u32(sm);
    const int t = threadIdx.x;
    const int wid = t >> 5, lane = t & 31;
    const int g = lane >> 2, tg = lane & 3;
    const int oA = aoffA(lane);
    const int wm = wid >> 2, wn = wid & 3;
    const int rowA = wm * 32;
    const int kb = wn * 16;
    const int b = blockIdx.y, m0 = blockIdx.x * 64;

    // 64B-row frag pieces (Q/K)
    const int arow = lane & 15, achk = lane >> 4;
    const int brow = (lane & 7) + ((lane >> 4) << 3), bchk = (lane >> 3) & 1;
    // 128B-row V pieces (unchanged from R11)
    const int vrow = (lane & 7) + ((lane >> 4) << 3), vcol = (lane & 8) * 2, vx = (lane & 7) << 4;

    const char* qt_b = qt + ((size_t)(b * 64 + (m0 >> 6))) * 4096;
    const char* kt_b = kt + (size_t)b * 64 * 4096;
    const char* vt_b = vt + (size_t)b * 64 * 32768;

    float* lsum_s = (float*)(sm + OFF_LSUM);
    if (t == 0) {
        MBARRIER_INIT(sb + 0, 1);
        MBARRIER_INIT(sb + 8, 1);
        MBARRIER_INIT(sb + 16, 1);
    }
    if (t < 64) lsum_s[t] = 0.f;

    // Q + K_0: contiguous pre-swizzled blobs (4 KB each)
    cpasync16(sb + OFF_Q2 + t * 16, qt_b + t * 16);
    cpasync16(sb + OFF_K2 + t * 16, kt_b + t * 16);
    CP_COMMIT();
    __syncthreads();

    if (t == 0) { MBARRIER_EXPECT_TX(sb + 8, 32768); bulkcp(sb + OFF_V0, vt_b, 32768, sb + 8); }

    CP_WAIT(0);
    __syncthreads();

    // Q fragments (2 m-frags x 2 k16-chunks) resident
    uint32_t qf[2][2][4];
#pragma unroll
    for (int mf = 0; mf < 2; mf++)
#pragma unroll
        for (int kc = 0; kc < 2; kc++) {
            int r = rowA + mf * 16 + arow;
            ldsm4(qf[mf][kc], sb + OFF_Q2 + swz64(r, kc * 2 + achk));
        }

    const uint32_t sbPH = sb + OFF_PH;

    float sacc[2][2][4];
    float oacc[2][8][4];
#pragma unroll
    for (int i = 0; i < 2; i++)
#pragma unroll
        for (int j = 0; j < 8; j++)
#pragma unroll
            for (int c = 0; c < 4; c++) oacc[i][j][c] = 0.f;
    float lpart[2][2] = {{0.f, 0.f}, {0.f, 0.f}};
    int kcnt = 0, vcnt0 = 0, vcnt1 = 0;

    auto do_smma = [&]() {
#pragma unroll
        for (int a = 0; a < 2; a++)
#pragma unroll
            for (int j2 = 0; j2 < 2; j2++)
#pragma unroll
                for (int c = 0; c < 4; c++) sacc[a][j2][c] = 0.f;
        const int kr = kb + brow;
#pragma unroll
        for (int kc = 0; kc < 2; kc++) {
            uint32_t bK[4];
            ldsm4(bK, sb + OFF_K2 + swz64(kr, kc * 2 + bchk));
#pragma unroll
            for (int mf = 0; mf < 2; mf++) {
                mma_fp(sacc[mf][0], qf[mf][kc], &bK[0]);
                mma_fp(sacc[mf][1], qf[mf][kc], &bK[2]);
            }
        }
    };

    auto do_softmax = [&]() {
#pragma unroll
        for (int mf = 0; mf < 2; mf++) {
            const int r0 = rowA + mf * 16 + g;
#pragma unroll
            for (int nf = 0; nf < 2; nf++) {
                const int cb = kb + nf * 8 + 2 * tg;
                float p0 = exp2f(sacc[mf][nf][0]);
                float p1 = exp2f(sacc[mf][nf][1]);
                float p2 = exp2f(sacc[mf][nf][2]);
                float p3 = exp2f(sacc[mf][nf][3]);
                uint32_t hA = pack_bf16x2(p0, p1);
                uint32_t hB = pack_bf16x2(p2, p3);
                // bf16 -> f32 is a 16-bit shift (cheap, no F2F)
                lpart[mf][0] += __uint_as_float(hA << 16) + __uint_as_float(hA & 0xffff0000u);
                lpart[mf][1] += __uint_as_float(hB << 16) + __uint_as_float(hB & 0xffff0000u);
                *(uint32_t*)(sm + OFF_PH + r0 * RS + cb * 2) = hA;
                *(uint32_t*)(sm + OFF_PH + (r0 + 8) * RS + cb * 2) = hB;
            }
        }
    };

    auto do_pv = [&](uint32_t Vb) {
#pragma unroll
        for (int kk = 0; kk < 4; kk++) {
            uint32_t aH[2][4];
#pragma unroll
            for (int mf = 0; mf < 2; mf++)
                ldsm4(aH[mf], sbPH + (rowA + mf * 16) * RS + kk * 32 + oA);
#pragma unroll
            for (int j = 0; j < 4; j++) {
                uint32_t bV[4];
                ldsm4(bV, Vb + (wn * 64 + j * 16 + vrow) * 128 + ((kk * 32 + vcol) ^ vx));
#pragma unroll
                for (int mf = 0; mf < 2; mf++) {
                    mma_bf(oacc[mf][2 * j],     aH[mf], &bV[0]);
                    mma_bf(oacc[mf][2 * j + 1], aH[mf], &bV[2]);
                }
            }
        }
    };

    do_smma();
    __syncthreads();

    if (t == 0) {
        MBARRIER_EXPECT_TX(sb + 0, 4096);   bulkcp(sb + OFF_K2, kt_b + 4096, 4096, sb + 0);
        MBARRIER_EXPECT_TX(sb + 16, 32768); bulkcp(sb + OFF_V1, vt_b + 32768, 32768, sb + 16);
    }

    for (int i = 0; i < 64; i++) {
        do_softmax();
        __syncthreads();

        if (i + 1 < 64) {
            MBARRIER_WAIT_PARITY(sb + 0, kcnt & 1); kcnt++;
            do_smma();
        }
        if (i & 1) { MBARRIER_WAIT_PARITY(sb + 16, vcnt1 & 1); vcnt1++; }
        else       { MBARRIER_WAIT_PARITY(sb + 8,  vcnt0 & 1); vcnt0++; }
        do_pv(sb + ((i & 1) ? OFF_V1 : OFF_V0));
        __syncthreads();

        if (i + 2 < 64 && t == 0) {
            const int nn = i + 2;
            const uint32_t vdst = sb + ((i & 1) ? OFF_V1 : OFF_V0);
            const uint32_t vmb  = sb + 8 + (i & 1) * 8;
            MBARRIER_EXPECT_TX(sb + 0, 4096);
            bulkcp(sb + OFF_K2, kt_b + (size_t)nn * 4096, 4096, sb + 0);
            MBARRIER_EXPECT_TX(vmb, 32768);
            bulkcp(vdst, vt_b + (size_t)nn * 32768, 32768, vmb);
        }
    }

#pragma unroll
    for (int mf = 0; mf < 2; mf++) {
        atomicAdd(&lsum_s[rowA + mf * 16 + g],     lpart[mf][0]);
        atomicAdd(&lsum_s[rowA + mf * 16 + 8 + g], lpart[mf][1]);
    }
    __syncthreads();

    // epilogue: O/lsum -> fp16 AO (single)
#pragma unroll
    for (int mf = 0; mf < 2; mf++) {
        const int rA = rowA + mf * 16 + g;
        const int rB = rA + 8;
        const float invA = 1.f / lsum_s[rA];
        const float invB = 1.f / lsum_s[rB];
        __half* hA = ao + (size_t)(b * N_ + m0 + rA) * C_;
        __half* hB = ao + (size_t)(b * N_ + m0 + rB) * C_;
#pragma unroll
        for (int nf = 0; nf < 8; nf++) {
            const int cb = wn * 64 + nf * 8 + 2 * tg;
            *(uint32_t*)(hA + cb) = pack_h2(oacc[mf][nf][0] * invA, oacc[mf][nf][1] * invA);
            *(uint32_t*)(hB + cb) = pack_h2(oacc[mf][nf][2] * invB, oacc[mf][nf][3] * invB);
        }
    }
}

// ---------------------------------------------------------------------------
// Output projection: out = wo*AO + bo + x  (wo 2-term fp16, AO single fp16)
// ---------------------------------------------------------------------------
#define OP_WH 0
#define OP_WL 18432
#define OP_A  36864
#define OP_BUF 55296
#define OPROJ_SMEM 110592

__global__ __launch_bounds__(512, 1)
void oproj_mma_kernel(const __half* __restrict__ ao,
                      const __half* __restrict__ whi,
                      const __half* __restrict__ wlo,
                      const float* __restrict__ bo,
                      const float* __restrict__ x,
                      float* __restrict__ out)
{
    extern __shared__ char sm[];
    const uint32_t sb = smem_u32(sm);
    const int t = threadIdx.x;
    const int wid = t >> 5, lane = t & 31;
    const int g = lane >> 2, tg = lane & 3;
    const int oA = aoffA(lane), oB = aoffB(lane);
    const int wm = wid >> 2, wn = wid & 3;
    const int b = blockIdx.z, o0 = blockIdx.y * 128, m0 = blockIdx.x * 128;

    float oac[2][4][4];
#pragma unroll
    for (int i = 0; i < 2; i++)
#pragma unroll
        for (int j = 0; j < 4; j++)
#pragma unroll
            for (int c = 0; c < 4; c++) oac[i][j][c] = 0.f;

    auto load_stage = [&](int kt_, int buf) {
        const uint32_t base = sb + buf * OP_BUF;
#pragma unroll
        for (int it = 0; it < 6; it++) {
            int idx = t + it * 512;
            int arr = idx >> 10, rr = (idx >> 3) & 127, cc = idx & 7;
            uint32_t dst = base + arr * 18432 + rr * RS + cc * 16;
            const __half* src;
            if (arr == 0)      src = whi + (size_t)(o0 + rr) * C_ + kt_ + cc * 8;
            else if (arr == 1) src = wlo + (size_t)(o0 + rr) * C_ + kt_ + cc * 8;
            else               src = ao + (size_t)(b * N_ + m0 + rr) * C_ + kt_ + cc * 8;
            cpasync16(dst, src);
        }
        CP_COMMIT();
    };

    load_stage(0, 0);
    for (int s = 0; s < 4; s++) {
        if (s + 1 < 4) { load_stage((s + 1) * 64, (s + 1) & 1); CP_WAIT(1); }
        else CP_WAIT(0);
        __syncthreads();
        const uint32_t base = sb + (s & 1) * OP_BUF;
        const uint32_t Wh = base + OP_WH + (wm * 32) * RS + oA;
        const uint32_t Wl = base + OP_WL + (wm * 32) * RS + oA;
        const uint32_t Ap = base + OP_A  + (wn * 32) * RS + oB;
#pragma unroll
        for (int ks = 0; ks < 4; ks++) {
            uint32_t awh[2][4], awl[2][4];
#pragma unroll
            for (int mf = 0; mf < 2; mf++) {
                ldsm4(awh[mf], Wh + mf * 16 * RS + ks * 32);
                ldsm4(awl[mf], Wl + mf * 16 * RS + ks * 32);
            }
#pragma unroll
            for (int j = 0; j < 2; j++) {
                uint32_t bh[4];
                ldsm4(bh, Ap + j * 16 * RS + ks * 32);
#pragma unroll
                for (int h = 0; h < 2; h++) {
                    const int nf = 2 * j + h;
#pragma unroll
                    for (int mf = 0; mf < 2; mf++) {
                        mma_fp(oac[mf][nf], awh[mf], &bh[2 * h]);
                        mma_fp(oac[mf][nf], awl[mf], &bh[2 * h]);
                    }
                }
            }
        }
        __syncthreads();
    }

#pragma unroll
    for (int mf = 0; mf < 2; mf++) {
        const int rA = o0 + wm * 32 + mf * 16 + g;
        const int rB = rA + 8;
        const float bvA = bo[rA], bvB = bo[rB];
#pragma unroll
        for (int nf = 0; nf < 4; nf++) {
            const int m = m0 + wn * 32 + nf * 8 + 2 * tg;
            size_t iA = (size_t)(b * C_ + rA) * N_ + m;
            size_t iB = (size_t)(b * C_ + rB) * N_ + m;
            float2 xA = *(const float2*)&x[iA];
            float2 xB = *(const float2*)&x[iB];
            *(float2*)&out[iA] = make_float2(oac[mf][nf][0] + bvA + xA.x, oac[mf][nf][1] + bvA + xA.y);
            *(float2*)&out[iB] = make_float2(oac[mf][nf][2] + bvB + xB.x, oac[mf][nf][3] + bvB + xB.y);
        }
    }
}

// ---------------------------------------------------------------------------
extern "C" void kernel_launch(void* const* d_in, const int* in_sizes, int n_in,
                              void* d_out, int out_size)
{
    const float* x  = (const float*)d_in[0];
    const float* wq = (const float*)d_in[1];
    const float* bq = (const float*)d_in[2];
    const float* wk = (const float*)d_in[3];
    const float* bk = (const float*)d_in[4];
    const float* wv = (const float*)d_in[5];
    const float* bv = (const float*)d_in[6];
    const float* wo = (const float*)d_in[7];
    const float* bo = (const float*)d_in[8];
    float* out = (float*)d_out;

    char *gqt, *gkt, *gvt;
    __half *gao, *gxt, *gwoh, *gwol, *gwv, *gwq, *gwk;
    cudaGetSymbolAddress((void**)&gqt,  g_qt);
    cudaGetSymbolAddress((void**)&gkt,  g_kt);
    cudaGetSymbolAddress((void**)&gvt,  g_vt);
    cudaGetSymbolAddress((void**)&gao,  g_ao);
    cudaGetSymbolAddress((void**)&gxt,  g_xt);
    cudaGetSymbolAddress((void**)&gwoh, g_wohi);
    cudaGetSymbolAddress((void**)&gwol, g_wolo);
    cudaGetSymbolAddress((void**)&gwv,  g_wv);
    cudaGetSymbolAddress((void**)&gwq,  g_wq);
    cudaGetSymbolAddress((void**)&gwk,  g_wk);

    cudaFuncSetAttribute(attn_mma_kernel, cudaFuncAttributeMaxDynamicSharedMemorySize, ATTN_SMEM);
    cudaFuncSetAttribute(oproj_mma_kernel, cudaFuncAttributeMaxDynamicSharedMemorySize, OPROJ_SMEM);
    cudaFuncSetAttribute(v_mma_kernel, cudaFuncAttributeMaxDynamicSharedMemorySize, VP_SMEM);
    cudaFuncSetAttribute(qk_mma_kernel, cudaFuncAttributeMaxDynamicSharedMemorySize, QK_SMEM);

    wprep_all_kernel<<<dim3(C_ * C_ / 256, 4), 256>>>(wo, wv, wq, wk,
        gwoh, gwol, gwv, gwq, gwk);
    xt_pack_kernel<<<dim3(N_ / 64, C_ / 64, B_), 256>>>(x, gxt);
    qk_mma_kernel<<<dim3(N_ / 128, B_), 256, QK_SMEM>>>(
        gxt, gwq, gwk, bq, bk, gqt, gkt);
    v_mma_kernel<<<dim3(N_ / 128, C_ / 128, B_), 512, VP_SMEM>>>(
        gxt, gwv, bv, gvt);
    attn_mma_kernel<<<dim3(N_ / 64, B_), 256, ATTN_SMEM>>>(gqt, gkt, gvt, gao);
    oproj_mma_kernel<<<dim3(N_ / 128, C_ / 128, B_), 512, OPROJ_SMEM>>>(
        gao, gwoh, gwol, bo, x, out);
}

// round 15
// speedup vs baseline: 9.7393x; 1.1412x over previous
#include <cuda_runtime.h>
#include <cuda_bf16.h>
#include <cuda_fp16.h>
#include <math.h>
#include <stdint.h>

#define B_ 4
#define C_ 256
#define N_ 4096
#define D_ 32
#define LOG2E 1.4426950408889634f

// ---------------------------------------------------------------------------
// PTX helpers (base sm_100-safe)
// ---------------------------------------------------------------------------
__device__ __forceinline__ uint32_t smem_u32(const void* p) {
    uint32_t a;
    asm("{ .reg .u64 t; cvta.to.shared.u64 t, %1; cvt.u32.u64 %0, t; }" : "=r"(a) : "l"(p));
    return a;
}
#define MBARRIER_INIT(a, c) \
    asm volatile("mbarrier.init.shared.b64 [%0], %1;" :: "r"((uint32_t)(a)), "r"((uint32_t)(c)) : "memory")
#define MBARRIER_EXPECT_TX(a, n) \
    asm volatile("mbarrier.arrive.expect_tx.shared.b64 _, [%0], %1;" :: "r"((uint32_t)(a)), "r"((uint32_t)(n)) : "memory")
#define MBARRIER_WAIT_PARITY(a, ph) do { \
    uint32_t _m = (uint32_t)(a); uint32_t _p = (uint32_t)(ph); uint32_t _d; \
    asm volatile("{\n\t.reg .pred p;\n\tmbarrier.try_wait.parity.shared.b64 p, [%1], %2;\n\tselp.b32 %0,1,0,p;\n\t}" \
        : "=r"(_d) : "r"(_m), "r"(_p) : "memory"); \
    if (!_d) { \
        asm volatile("{\n\t.reg .pred P1;\n\tWL_%=:\n\tmbarrier.try_wait.parity.shared.b64 P1, [%0], %1;\n\t@P1 bra.uni WD_%=;\n\tbra.uni WL_%=;\n\tWD_%=:\n\t}" \
            :: "r"(_m), "r"(_p) : "memory"); \
    } } while (0)

__device__ __forceinline__ void cpasync16(uint32_t dst, const void* src) {
    asm volatile("cp.async.cg.shared.global [%0], [%1], 16;" :: "r"(dst), "l"(src) : "memory");
}
#define CP_COMMIT() asm volatile("cp.async.commit_group;" ::: "memory")
#define CP_WAIT(n)  asm volatile("cp.async.wait_group %0;" :: "n"(n) : "memory")

__device__ __forceinline__ void bulkcp(uint32_t dst, const void* src, uint32_t bytes, uint32_t mbar) {
    asm volatile("cp.async.bulk.shared::cta.global.mbarrier::complete_tx::bytes [%0], [%1], %2, [%3];"
                 :: "r"(dst), "l"(src), "r"(bytes), "r"(mbar) : "memory");
}

__device__ __forceinline__ void mma_bf(float* d, const uint32_t* a, const uint32_t* b) {
    asm volatile("mma.sync.aligned.m16n8k16.row.col.f32.bf16.bf16.f32 "
                 "{%0,%1,%2,%3}, {%4,%5,%6,%7}, {%8,%9}, {%0,%1,%2,%3};"
                 : "+f"(d[0]), "+f"(d[1]), "+f"(d[2]), "+f"(d[3])
                 : "r"(a[0]), "r"(a[1]), "r"(a[2]), "r"(a[3]), "r"(b[0]), "r"(b[1]));
}
__device__ __forceinline__ void mma_fp(float* d, const uint32_t* a, const uint32_t* b) {
    asm volatile("mma.sync.aligned.m16n8k16.row.col.f32.f16.f16.f32 "
                 "{%0,%1,%2,%3}, {%4,%5,%6,%7}, {%8,%9}, {%0,%1,%2,%3};"
                 : "+f"(d[0]), "+f"(d[1]), "+f"(d[2]), "+f"(d[3])
                 : "r"(a[0]), "r"(a[1]), "r"(a[2]), "r"(a[3]), "r"(b[0]), "r"(b[1]));
}
__device__ __forceinline__ void ldsm4(uint32_t* r, uint32_t addr) {
    asm volatile("ldmatrix.sync.aligned.m8n8.x4.shared.b16 {%0,%1,%2,%3}, [%4];"
                 : "=r"(r[0]), "=r"(r[1]), "=r"(r[2]), "=r"(r[3]) : "r"(addr));
}
__device__ __forceinline__ uint32_t pack_bf16x2(float x, float y) {
    __nv_bfloat162 h = __floats2bfloat162_rn(x, y);
    return *(uint32_t*)&h;
}
__device__ __forceinline__ uint32_t pack_h2(float x, float y) {
    __half2 h = __floats2half2_rn(x, y);
    return *(uint32_t*)&h;
}

#define RS 144
__device__ __forceinline__ int aoffA(int lane) { return (lane & 15) * RS + (lane >> 4) * 16; }
__device__ __forceinline__ int aoffB(int lane) { return ((lane & 7) + ((lane >> 4) << 3)) * RS + (lane & 8) * 2; }
__device__ __forceinline__ uint32_t swz64(int row, int chunk) {
    return (uint32_t)(row * 64 + ((chunk ^ ((row >> 1) & 3)) << 4));
}

// ---------------------------------------------------------------------------
// Scratch
// ---------------------------------------------------------------------------
__device__ char   g_qt [B_*64*64*64];
__device__ char   g_kt [B_*64*64*64];
__device__ char   g_vt [(size_t)B_*64*256*128];
__device__ __half g_ao [B_*N_*C_];
__device__ __half g_xt [B_*N_*C_];
__device__ __half g_wohi[C_*C_];
__device__ __half g_wolo[C_*C_];
__device__ __half g_wv [C_*C_];
__device__ __half g_wq [D_*C_];
__device__ __half g_wk [D_*C_];

// ---------------------------------------------------------------------------
__global__ void wprep_all_kernel(const float* __restrict__ wo, const float* __restrict__ wv,
                                 const float* __restrict__ wq, const float* __restrict__ wk,
                                 __half* __restrict__ woh, __half* __restrict__ wol,
                                 __half* __restrict__ wvp, __half* __restrict__ wqp,
                                 __half* __restrict__ wkp)
{
    int which = blockIdx.y;
    int i = blockIdx.x * 256 + threadIdx.x;
    if (which == 0) {
        float f = wo[i];
        __half h = __float2half_rn(f);
        woh[i] = h;
        wol[i] = __float2half_rn(f - __half2float(h));
    } else if (which == 1) {
        wvp[i] = __float2half_rn(wv[i]);
    } else if (which == 2) {
        if (i < D_ * C_) wqp[i] = __float2half_rn(wq[i] * LOG2E);
    } else {
        if (i < D_ * C_) wkp[i] = __float2half_rn(wk[i]);
    }
}

// ---------------------------------------------------------------------------
__global__ __launch_bounds__(256)
void xt_pack_kernel(const float* __restrict__ x, __half* __restrict__ xt)
{
    __shared__ float ts[64][65];
    const int b = blockIdx.z, c0 = blockIdx.y * 64, n0 = blockIdx.x * 64;
    const int t = threadIdx.x;
    const int rr = t >> 4, c4 = t & 15;

#pragma unroll
    for (int it = 0; it < 4; it++) {
        int row = it * 16 + rr;
        float4 v = *(const float4*)&x[(size_t)(b * C_ + c0 + row) * N_ + n0 + c4 * 4];
        ts[row][c4 * 4 + 0] = v.x; ts[row][c4 * 4 + 1] = v.y;
        ts[row][c4 * 4 + 2] = v.z; ts[row][c4 * 4 + 3] = v.w;
    }
    __syncthreads();
#pragma unroll
    for (int it = 0; it < 4; it++) {
        int n = it * 16 + rr;
        unsigned short hs[4];
#pragma unroll
        for (int e = 0; e < 4; e++)
            hs[e] = __half_as_ushort(__float2half_rn(ts[c4 * 4 + e][n]));
        *(uint2*)&xt[(size_t)(b * N_ + n0 + n) * C_ + c0 + c4 * 4] = *(uint2*)hs;
    }
}

// ---------------------------------------------------------------------------
// Q+K projection GEMM (fp16) -> 64B-row swizzled g_qt, g_kt
// ---------------------------------------------------------------------------
#define QK_XT 0
#define QK_WB 73728
#define QK_SMEM 110592

__global__ __launch_bounds__(256, 1)
void qk_mma_kernel(const __half* __restrict__ xt,
                   const __half* __restrict__ wqp, const __half* __restrict__ wkp,
                   const float* __restrict__ bq, const float* __restrict__ bk,
                   char* __restrict__ qt, char* __restrict__ kt)
{
    extern __shared__ char sm[];
    const uint32_t sb = smem_u32(sm);
    const int t = threadIdx.x;
    const int wid = t >> 5, lane = t & 31;
    const int g = lane >> 2, tg = lane & 3;
    const int oA = aoffA(lane), oB = aoffB(lane);
    const int wm = wid >> 1, wn = wid & 1;
    const int b = blockIdx.y, n0 = blockIdx.x * 128;

#pragma unroll
    for (int it = 0; it < 16; it++) {
        int idx = t + it * 256;
        int r = idx >> 5, cc = idx & 31;
        uint32_t off = (cc >> 3) * 18432 + r * RS + (cc & 7) * 16;
        cpasync16(sb + QK_XT + off, xt + (size_t)(b * N_ + n0 + r) * C_ + cc * 8);
    }
#pragma unroll
    for (int it = 0; it < 8; it++) {
        int idx = t + it * 256;
        int o = idx >> 5, cc = idx & 31;
        uint32_t off = (cc >> 3) * 9216 + o * RS + (cc & 7) * 16;
        const __half* sh = (o < 32) ? (wqp + (size_t)o * C_) : (wkp + (size_t)(o - 32) * C_);
        cpasync16(sb + QK_WB + off, sh + cc * 8);
    }
    CP_COMMIT();
    CP_WAIT(0);
    __syncthreads();

    float oac[2][4][4];
#pragma unroll
    for (int i = 0; i < 2; i++)
#pragma unroll
        for (int j = 0; j < 4; j++)
#pragma unroll
            for (int c = 0; c < 4; c++) oac[i][j][c] = 0.f;

#pragma unroll
    for (int kc = 0; kc < 4; kc++) {
#pragma unroll
        for (int ks = 0; ks < 4; ks++) {
            uint32_t ah[2][4];
#pragma unroll
            for (int mf = 0; mf < 2; mf++)
                ldsm4(ah[mf], sb + QK_XT + kc * 18432 + (wm * 32 + mf * 16) * RS + ks * 32 + oA);
#pragma unroll
            for (int j = 0; j < 2; j++) {
                uint32_t bh[4];
                ldsm4(bh, sb + QK_WB + kc * 9216 + (wn * 32 + j * 16) * RS + ks * 32 + oB);
#pragma unroll
                for (int h = 0; h < 2; h++)
#pragma unroll
                    for (int mf = 0; mf < 2; mf++)
                        mma_fp(oac[mf][j * 2 + h], ah[mf], &bh[2 * h]);
            }
        }
    }

#pragma unroll
    for (int mf = 0; mf < 2; mf++) {
#pragma unroll
        for (int half = 0; half < 2; half++) {
            const int rA = wm * 32 + mf * 16 + half * 8 + g;
            const int n = n0 + rA;
            const int tile = n >> 6, rr = n & 63;
#pragma unroll
            for (int hh = 0; hh < 4; hh++) {
                int o = wn * 32 + hh * 8 + 2 * tg;
                bool isq = (o < 32);
                int oo = isq ? o : (o - 32);
                float bb0 = isq ? bq[oo] * LOG2E : bk[oo];
                float bb1 = isq ? bq[oo + 1] * LOG2E : bk[oo + 1];
                float d0 = oac[mf][hh][half * 2 + 0] + bb0;
                float d1 = oac[mf][hh][half * 2 + 1] + bb1;
                char* dst = (isq ? qt : kt) + ((size_t)(b * 64 + tile) * 64) * 64;
                *(uint32_t*)(dst + swz64(rr, oo >> 3) + ((oo * 2) & 15)) = pack_h2(d0, d1);
            }
        }
    }
}

// ---------------------------------------------------------------------------
// V projection GEMM (fp16) -> swizzled bf16 g_vt
// ---------------------------------------------------------------------------
#define VP_W 0
#define VP_X 18432
#define VP_BUF 36864
#define VP_SMEM 73728

__global__ __launch_bounds__(512, 1)
void v_mma_kernel(const __half* __restrict__ xt, const __half* __restrict__ wvp,
                  const float* __restrict__ bv, char* __restrict__ vt)
{
    extern __shared__ char sm[];
    const uint32_t sb = smem_u32(sm);
    const int t = threadIdx.x;
    const int wid = t >> 5, lane = t & 31;
    const int g = lane >> 2, tg = lane & 3;
    const int oA = aoffA(lane), oB = aoffB(lane);
    const int wm = wid >> 2, wn = wid & 3;
    const int b = blockIdx.z, o0 = blockIdx.y * 128, m0 = blockIdx.x * 128;

    float oac[2][4][4];
#pragma unroll
    for (int i = 0; i < 2; i++)
#pragma unroll
        for (int j = 0; j < 4; j++)
#pragma unroll
            for (int c = 0; c < 4; c++) oac[i][j][c] = 0.f;

    auto load_stage = [&](int kt_, int buf) {
        const uint32_t base = sb + buf * VP_BUF;
#pragma unroll
        for (int it = 0; it < 4; it++) {
            int idx = t + it * 512;
            int arr = idx >> 10, rr = (idx >> 3) & 127, cc = idx & 7;
            uint32_t dst = base + arr * 18432 + rr * RS + cc * 16;
            const __half* src = arr ? (xt + (size_t)(b * N_ + m0 + rr) * C_ + kt_ + cc * 8)
                                    : (wvp + (size_t)(o0 + rr) * C_ + kt_ + cc * 8);
            cpasync16(dst, src);
        }
        CP_COMMIT();
    };

    load_stage(0, 0);
    for (int s = 0; s < 4; s++) {
        if (s + 1 < 4) { load_stage((s + 1) * 64, (s + 1) & 1); CP_WAIT(1); }
        else CP_WAIT(0);
        __syncthreads();
        const uint32_t base = sb + (s & 1) * VP_BUF;
        const uint32_t Wp = base + VP_W + (wm * 32) * RS + oA;
        const uint32_t Xp = base + VP_X + (wn * 32) * RS + oB;
#pragma unroll
        for (int ks = 0; ks < 4; ks++) {
            uint32_t aw[2][4];
#pragma unroll
            for (int mf = 0; mf < 2; mf++)
                ldsm4(aw[mf], Wp + mf * 16 * RS + ks * 32);
#pragma unroll
            for (int j = 0; j < 2; j++) {
                uint32_t bh[4];
                ldsm4(bh, Xp + j * 16 * RS + ks * 32);
#pragma unroll
                for (int h = 0; h < 2; h++)
#pragma unroll
                    for (int mf = 0; mf < 2; mf++)
                        mma_fp(oac[mf][j * 2 + h], aw[mf], &bh[2 * h]);
            }
        }
        __syncthreads();
    }

#pragma unroll
    for (int mf = 0; mf < 2; mf++) {
#pragma unroll
        for (int half = 0; half < 2; half++) {
            const int rA = o0 + wm * 32 + mf * 16 + half * 8 + g;
            const float bvA = bv[rA];
            const int swx = (rA & 7) << 4;
#pragma unroll
            for (int nf = 0; nf < 4; nf++) {
                const int m = m0 + wn * 32 + nf * 8 + 2 * tg;
                const int tile = m >> 6, j = m & 63;
                char* dst = vt + ((size_t)(b * 64 + tile) * 256 + rA) * 128;
                *(uint32_t*)(dst + ((j * 2) ^ swx)) =
                    pack_bf16x2(oac[mf][nf][half * 2 + 0] + bvA, oac[mf][nf][half * 2 + 1] + bvA);
            }
        }
    }
}

// ---------------------------------------------------------------------------
// Flash attention, register-resident P.
// CTA = 128 queries, 256 threads = 8 warps; warp w owns rows 16w..16w+15,
// ALL 64 keys. S fp16 (16 MMA/warp), softmax in registers, PV bf16
// (128 MMA/warp). K double-buffered, V triple-buffered; one sync per iter.
// ---------------------------------------------------------------------------
#define OFF_LSUM 64
#define OFF_Q2   1024
#define OFF_K0   9216
#define OFF_K1   13312
#define OFF_V0   17408
#define ATTN_SMEM 115712

__global__ __launch_bounds__(256, 1)
void attn_mma_kernel(const char* __restrict__ qt,
                     const char* __restrict__ kt,
                     const char* __restrict__ vt,
                     __half* __restrict__ ao)
{
    extern __shared__ char sm[];
    const uint32_t sb = smem_u32(sm);
    const int t = threadIdx.x;
    const int wid = t >> 5, lane = t & 31;
    const int g = lane >> 2, tg = lane & 3;
    const int b = blockIdx.y, m0 = blockIdx.x * 128;

    // 64B-row frag pieces (Q/K)
    const int arow = lane & 15, achk = lane >> 4;
    const int brow = (lane & 7) + ((lane >> 4) << 3), bchk = (lane >> 3) & 1;
    // 128B-row V pieces
    const int vrow = (lane & 7) + ((lane >> 4) << 3), vcol = (lane & 8) * 2, vx = (lane & 7) << 4;

    const char* qt_b = qt + ((size_t)(b * 64 + (m0 >> 6))) * 4096;   // 2 tiles = 8KB contiguous
    const char* kt_b = kt + (size_t)b * 64 * 4096;
    const char* vt_b = vt + (size_t)b * 64 * 32768;

    float* lsum_s = (float*)(sm + OFF_LSUM);
    if (t == 0) {
        MBARRIER_INIT(sb + 0, 1);  MBARRIER_INIT(sb + 8, 1);
        MBARRIER_INIT(sb + 16, 1); MBARRIER_INIT(sb + 24, 1); MBARRIER_INIT(sb + 32, 1);
    }
    if (t < 128) lsum_s[t] = 0.f;

    // Q: 8KB contiguous (2 x 16B chunks per thread)
#pragma unroll
    for (int i = 0; i < 2; i++) {
        int idx = t + i * 256;
        cpasync16(sb + OFF_Q2 + idx * 16, qt_b + idx * 16);
    }
    CP_COMMIT();
    __syncthreads();   // barrier init + lsum visible

    if (t == 0) {
        MBARRIER_EXPECT_TX(sb + 0, 4096);  bulkcp(sb + OFF_K0, kt_b, 4096, sb + 0);
        MBARRIER_EXPECT_TX(sb + 8, 4096);  bulkcp(sb + OFF_K1, kt_b + 4096, 4096, sb + 8);
        MBARRIER_EXPECT_TX(sb + 16, 32768); bulkcp(sb + OFF_V0, vt_b, 32768, sb + 16);
        MBARRIER_EXPECT_TX(sb + 24, 32768); bulkcp(sb + OFF_V0 + 32768, vt_b + 32768, 32768, sb + 24);
        MBARRIER_EXPECT_TX(sb + 32, 32768); bulkcp(sb + OFF_V0 + 65536, vt_b + 65536, 32768, sb + 32);
    }
    CP_WAIT(0);        // own Q copies done...
    __syncthreads();   // ...and ALL threads' Q copies visible (was missing -> NaN)

    // Q fragments resident: warp rows 16*wid..16*wid+15
    uint32_t qf[2][4];
#pragma unroll
    for (int kc = 0; kc < 2; kc++) {
        int r = 16 * wid + arow;                   // 0..127
        uint32_t off = (uint32_t)(r >> 6) * 4096 + swz64(r & 63, kc * 2 + achk);
        ldsm4(qf[kc], sb + OFF_Q2 + off);
    }

    float oacc[32][4];
#pragma unroll
    for (int j = 0; j < 32; j++)
#pragma unroll
        for (int c = 0; c < 4; c++) oacc[j][c] = 0.f;
    float lpart[2] = {0.f, 0.f};

    for (int i = 0; i < 64; i++) {
        // ---- S_i : warp rows x all 64 keys (fp16) ----
        MBARRIER_WAIT_PARITY(sb + (i & 1) * 8, (i >> 1) & 1);
        float sacc[8][4];
#pragma unroll
        for (int nf = 0; nf < 8; nf++)
#pragma unroll
            for (int c = 0; c < 4; c++) sacc[nf][c] = 0.f;
        const uint32_t Kb = sb + ((i & 1) ? OFF_K1 : OFF_K0);
#pragma unroll
        for (int kc = 0; kc < 2; kc++) {
#pragma unroll
            for (int j = 0; j < 4; j++) {
                uint32_t bK[4];
                ldsm4(bK, Kb + swz64(j * 16 + brow, kc * 2 + bchk));
                mma_fp(sacc[2 * j],     qf[kc], &bK[0]);
                mma_fp(sacc[2 * j + 1], qf[kc], &bK[2]);
            }
        }

        // ---- softmax in registers -> P fragments (bf16 pairs) ----
        uint32_t pf[8][2];
#pragma unroll
        for (int nf = 0; nf < 8; nf++) {
            float p0 = exp2f(sacc[nf][0]);
            float p1 = exp2f(sacc[nf][1]);
            float p2 = exp2f(sacc[nf][2]);
            float p3 = exp2f(sacc[nf][3]);
            uint32_t hA = pack_bf16x2(p0, p1);
            uint32_t hB = pack_bf16x2(p2, p3);
            lpart[0] += __uint_as_float(hA << 16) + __uint_as_float(hA & 0xffff0000u);
            lpart[1] += __uint_as_float(hB << 16) + __uint_as_float(hB & 0xffff0000u);
            pf[nf][0] = hA;          // rows g    cols nf*8+2tg,+1
            pf[nf][1] = hB;          // rows g+8
        }

        // ---- PV_i : A = P frags (identity mapping), B = V tile ----
        const int vs = i % 3;
        MBARRIER_WAIT_PARITY(sb + 16 + vs * 8, (i / 3) & 1);
        const uint32_t Vb = sb + OFF_V0 + vs * 32768;
#pragma unroll
        for (int kk = 0; kk < 4; kk++) {
            uint32_t A[4] = {pf[2 * kk][0], pf[2 * kk][1], pf[2 * kk + 1][0], pf[2 * kk + 1][1]};
#pragma unroll
            for (int cj = 0; cj < 16; cj++) {
                uint32_t bV[4];
                ldsm4(bV, Vb + (cj * 16 + vrow) * 128 + ((kk * 32 + vcol) ^ vx));
                mma_bf(oacc[2 * cj],     A, &bV[0]);
                mma_bf(oacc[2 * cj + 1], A, &bV[2]);
            }
        }

        __syncthreads();   // all warps done with K slot (i&1) and V slot (i%3)
        if (t == 0) {
            if (i + 2 < 64) {
                MBARRIER_EXPECT_TX(sb + (i & 1) * 8, 4096);
                bulkcp(sb + ((i & 1) ? OFF_K1 : OFF_K0), kt_b + (size_t)(i + 2) * 4096, 4096, sb + (i & 1) * 8);
            }
            if (i + 3 < 64) {
                MBARRIER_EXPECT_TX(sb + 16 + vs * 8, 32768);
                bulkcp(sb + OFF_V0 + vs * 32768, vt_b + (size_t)(i + 3) * 32768, 32768, sb + 16 + vs * 8);
            }
        }
    }

    // ---- lsum reduction ----
    atomicAdd(&lsum_s[16 * wid + g],     lpart[0]);
    atomicAdd(&lsum_s[16 * wid + 8 + g], lpart[1]);
    __syncthreads();

    // ---- epilogue: O/lsum -> fp16 AO ----
    {
        const int rA = 16 * wid + g;
        const int rB = rA + 8;
        const float invA = 1.f / lsum_s[rA];
        const float invB = 1.f / lsum_s[rB];
        __half* hA = ao + (size_t)(b * N_ + m0 + rA) * C_;
        __half* hB = ao + (size_t)(b * N_ + m0 + rB) * C_;
#pragma unroll
        for (int cn = 0; cn < 32; cn++) {
            const int cb = cn * 8 + 2 * tg;
            *(uint32_t*)(hA + cb) = pack_h2(oacc[cn][0] * invA, oacc[cn][1] * invA);
            *(uint32_t*)(hB + cb) = pack_h2(oacc[cn][2] * invB, oacc[cn][3] * invB);
        }
    }
}

// ---------------------------------------------------------------------------
// Output projection: out = wo*AO + bo + x  (wo 2-term fp16, AO fp16)
// ---------------------------------------------------------------------------
#define OP_WH 0
#define OP_WL 18432
#define OP_A  36864
#define OP_BUF 55296
#define OPROJ_SMEM 110592

__global__ __launch_bounds__(512, 1)
void oproj_mma_kernel(const __half* __restrict__ ao,
                      const __half* __restrict__ whi,
                      const __half* __restrict__ wlo,
                      const float* __restrict__ bo,
                      const float* __restrict__ x,
                      float* __restrict__ out)
{
    extern __shared__ char sm[];
    const uint32_t sb = smem_u32(sm);
    const int t = threadIdx.x;
    const int wid = t >> 5, lane = t & 31;
    const int g = lane >> 2, tg = lane & 3;
    const int oA = aoffA(lane), oB = aoffB(lane);
    const int wm = wid >> 2, wn = wid & 3;
    const int b = blockIdx.z, o0 = blockIdx.y * 128, m0 = blockIdx.x * 128;

    float oac[2][4][4];
#pragma unroll
    for (int i = 0; i < 2; i++)
#pragma unroll
        for (int j = 0; j < 4; j++)
#pragma unroll
            for (int c = 0; c < 4; c++) oac[i][j][c] = 0.f;

    auto load_stage = [&](int kt_, int buf) {
        const uint32_t base = sb + buf * OP_BUF;
#pragma unroll
        for (int it = 0; it < 6; it++) {
            int idx = t + it * 512;
            int arr = idx >> 10, rr = (idx >> 3) & 127, cc = idx & 7;
            uint32_t dst = base + arr * 18432 + rr * RS + cc * 16;
            const __half* src;
            if (arr == 0)      src = whi + (size_t)(o0 + rr) * C_ + kt_ + cc * 8;
            else if (arr == 1) src = wlo + (size_t)(o0 + rr) * C_ + kt_ + cc * 8;
            else               src = ao + (size_t)(b * N_ + m0 + rr) * C_ + kt_ + cc * 8;
            cpasync16(dst, src);
        }
        CP_COMMIT();
    };

    load_stage(0, 0);
    for (int s = 0; s < 4; s++) {
        if (s + 1 < 4) { load_stage((s + 1) * 64, (s + 1) & 1); CP_WAIT(1); }
        else CP_WAIT(0);
        __syncthreads();
        const uint32_t base = sb + (s & 1) * OP_BUF;
        const uint32_t Wh = base + OP_WH + (wm * 32) * RS + oA;
        const uint32_t Wl = base + OP_WL + (wm * 32) * RS + oA;
        const uint32_t Ap = base + OP_A  + (wn * 32) * RS + oB;
#pragma unroll
        for (int ks = 0; ks < 4; ks++) {
            uint32_t awh[2][4], awl[2][4];
#pragma unroll
            for (int mf = 0; mf < 2; mf++) {
                ldsm4(awh[mf], Wh + mf * 16 * RS + ks * 32);
                ldsm4(awl[mf], Wl + mf * 16 * RS + ks * 32);
            }
#pragma unroll
            for (int j = 0; j < 2; j++) {
                uint32_t bh[4];
                ldsm4(bh, Ap + j * 16 * RS + ks * 32);
#pragma unroll
                for (int h = 0; h < 2; h++) {
                    const int nf = 2 * j + h;
#pragma unroll
                    for (int mf = 0; mf < 2; mf++) {
                        mma_fp(oac[mf][nf], awh[mf], &bh[2 * h]);
                        mma_fp(oac[mf][nf], awl[mf], &bh[2 * h]);
                    }
                }
            }
        }
        __syncthreads();
    }

#pragma unroll
    for (int mf = 0; mf < 2; mf++) {
        const int rA = o0 + wm * 32 + mf * 16 + g;
        const int rB = rA + 8;
        const float bvA = bo[rA], bvB = bo[rB];
#pragma unroll
        for (int nf = 0; nf < 4; nf++) {
            const int m = m0 + wn * 32 + nf * 8 + 2 * tg;
            size_t iA = (size_t)(b * C_ + rA) * N_ + m;
            size_t iB = (size_t)(b * C_ + rB) * N_ + m;
            float2 xA = *(const float2*)&x[iA];
            float2 xB = *(const float2*)&x[iB];
            *(float2*)&out[iA] = make_float2(oac[mf][nf][0] + bvA + xA.x, oac[mf][nf][1] + bvA + xA.y);
            *(float2*)&out[iB] = make_float2(oac[mf][nf][2] + bvB + xB.x, oac[mf][nf][3] + bvB + xB.y);
        }
    }
}

// ---------------------------------------------------------------------------
extern "C" void kernel_launch(void* const* d_in, const int* in_sizes, int n_in,
                              void* d_out, int out_size)
{
    const float* x  = (const float*)d_in[0];
    const float* wq = (const float*)d_in[1];
    const float* bq = (const float*)d_in[2];
    const float* wk = (const float*)d_in[3];
    const float* bk = (const float*)d_in[4];
    const float* wv = (const float*)d_in[5];
    const float* bv = (const float*)d_in[6];
    const float* wo = (const float*)d_in[7];
    const float* bo = (const float*)d_in[8];
    float* out = (float*)d_out;

    char *gqt, *gkt, *gvt;
    __half *gao, *gxt, *gwoh, *gwol, *gwv, *gwq, *gwk;
    cudaGetSymbolAddress((void**)&gqt,  g_qt);
    cudaGetSymbolAddress((void**)&gkt,  g_kt);
    cudaGetSymbolAddress((void**)&gvt,  g_vt);
    cudaGetSymbolAddress((void**)&gao,  g_ao);
    cudaGetSymbolAddress((void**)&gxt,  g_xt);
    cudaGetSymbolAddress((void**)&gwoh, g_wohi);
    cudaGetSymbolAddress((void**)&gwol, g_wolo);
    cudaGetSymbolAddress((void**)&gwv,  g_wv);
    cudaGetSymbolAddress((void**)&gwq,  g_wq);
    cudaGetSymbolAddress((void**)&gwk,  g_wk);

    cudaFuncSetAttribute(attn_mma_kernel, cudaFuncAttributeMaxDynamicSharedMemorySize, ATTN_SMEM);
    cudaFuncSetAttribute(oproj_mma_kernel, cudaFuncAttributeMaxDynamicSharedMemorySize, OPROJ_SMEM);
    cudaFuncSetAttribute(v_mma_kernel, cudaFuncAttributeMaxDynamicSharedMemorySize, VP_SMEM);
    cudaFuncSetAttribute(qk_mma_kernel, cudaFuncAttributeMaxDynamicSharedMemorySize, QK_SMEM);

    wprep_all_kernel<<<dim3(C_ * C_ / 256, 4), 256>>>(wo, wv, wq, wk,
        gwoh, gwol, gwv, gwq, gwk);
    xt_pack_kernel<<<dim3(N_ / 64, C_ / 64, B_), 256>>>(x, gxt);
    qk_mma_kernel<<<dim3(N_ / 128, B_), 256, QK_SMEM>>>(
        gxt, gwq, gwk, bq, bk, gqt, gkt);
    v_mma_kernel<<<dim3(N_ / 128, C_ / 128, B_), 512, VP_SMEM>>>(
        gxt, gwv, bv, gvt);
    attn_mma_kernel<<<dim3(N_ / 128, B_), 256, ATTN_SMEM>>>(gqt, gkt, gvt, gao);
    oproj_mma_kernel<<<dim3(N_ / 128, C_ / 128, B_), 512, OPROJ_SMEM>>>(
        gao, gwoh, gwol, bo, x, out);
}